// round 2
// baseline (speedup 1.0000x reference)
#include <cuda_runtime.h>
#include <math.h>

#define MROWS 8192      // 1024 * 8 rows
#define CDIM  1024
#define KPAD  112       // padded token/attention dim (100 -> 112)
#define TROWS 144       // padded token rows
#define NZ    513       // kept spectrum columns

// ---------------- scratch (device globals; no allocation allowed) ----------
__device__ float g_phase[MROWS*CDIM];
__device__ float g_amp  [MROWS*CDIM];
__device__ float g_T1   [TROWS*CDIM];
__device__ float g_T2   [TROWS*CDIM];
__device__ float g_A1   [MROWS*KPAD];
__device__ float g_A2r  [MROWS*KPAD];
__device__ float g_S1   [MROWS*KPAD];
__device__ float g_S2   [MROWS*KPAD];
__device__ float g_vT1  [CDIM*KPAD];
__device__ float g_vT2  [CDIM*KPAD];
__device__ float g_df1  [MROWS*CDIM];
__device__ float g_df2  [MROWS*CDIM];
__device__ float g_dp   [MROWS*NZ];
__device__ float g_da   [MROWS*NZ];
__device__ float g_zr   [MROWS*NZ];
__device__ float g_zi   [MROWS*NZ];

// ---------------- token prep: T[layer] -> padded buffers --------------------
__global__ void prep_tokens(const float* __restrict__ lt1,
                            const float* __restrict__ lt2,
                            const int* __restrict__ layer_p)
{
    int i = blockIdx.x * 256 + threadIdx.x;
    if (i >= TROWS * CDIM) return;
    int row = i >> 10;
    int layer = layer_p[0];
    float v1 = 0.f, v2 = 0.f;
    if (row < 100) {
        v1 = lt1[layer * 100 * CDIM + i];
        v2 = lt2[layer * 100 * CDIM + i];
    }
    g_T1[i] = v1;
    g_T2[i] = v2;
}

// ---------------- forward FFT2 + amp/phase ---------------------------------
// one block per n slice (8 x 1024 real), 512 threads
__global__ void __launch_bounds__(512) fft_fwd(const float* __restrict__ feats)
{
    extern __shared__ float sm[];
    float* sre = sm;               // 8192
    float* sim = sm + 8192;        // 8192
    float* twr = sm + 16384;       // 512
    float* twi = twr + 512;        // 512
    int tid = threadIdx.x;
    int n = blockIdx.x;
    const float* x = feats + (size_t)(n + 1) * 8192;

    { // twiddle table: exp(-2*pi*i*t/1024), t in [0,512)
        float s_, c_;
        sincospif(-(float)tid * (1.0f / 512.0f), &s_, &c_);
        twr[tid] = c_;
        twi[tid] = s_;
    }
    // load with bit-reversed c
    for (int i = tid; i < 8192; i += 512) {
        int b = i >> 10, c = i & 1023;
        int rc = __brev((unsigned)c) >> 22;
        sre[(b << 10) + rc] = x[i];
        sim[(b << 10) + rc] = 0.f;
    }
    __syncthreads();
    // 10 radix-2 DIT stages, per-row (8 rows x 512 butterflies)
    for (int s = 1; s <= 10; s++) {
        int half = 1 << (s - 1);
        for (int t = tid; t < 4096; t += 512) {
            int b = t >> 9;
            int j = t & 511;
            int pos = j & (half - 1);
            int base = (j >> (s - 1)) << s;
            int i1 = (b << 10) + base + pos;
            int i2 = i1 + half;
            int ti = pos << (10 - s);
            float wr = twr[ti], wi = twi[ti];
            float ur = sre[i1], ui = sim[i1];
            float xr = sre[i2], xi = sim[i2];
            float vr = xr * wr - xi * wi;
            float vi = xr * wi + xi * wr;
            sre[i1] = ur + vr; sim[i1] = ui + vi;
            sre[i2] = ur - vr; sim[i2] = ui - vi;
        }
        __syncthreads();
    }
    // 8-point DFT along b, then amp / phase with denormal replacement
    const float W8R[8] = {1.f, 0.70710678f, 0.f, -0.70710678f, -1.f, -0.70710678f, 0.f, 0.70710678f};
    const float W8I[8] = {0.f, -0.70710678f, -1.f, -0.70710678f, 0.f, 0.70710678f, 1.f, 0.70710678f};
    for (int c = tid; c < 1024; c += 512) {
        float ar[8], ai[8];
        #pragma unroll
        for (int b = 0; b < 8; b++) { ar[b] = sre[(b << 10) + c]; ai[b] = sim[(b << 10) + c]; }
        #pragma unroll
        for (int kb = 0; kb < 8; kb++) {
            float orr = 0.f, oii = 0.f;
            #pragma unroll
            for (int b = 0; b < 8; b++) {
                int t8 = (kb * b) & 7;
                orr += ar[b] * W8R[t8] - ai[b] * W8I[t8];
                oii += ar[b] * W8I[t8] + ai[b] * W8R[t8];
            }
            float p = orr * orr + oii * oii;
            if (p < 1e-5f) p = 1e-5f;
            float amp = sqrtf(p);
            float rr = orr;
            if (rr < 1e-5f && rr > -1e-5f) rr = 1e-5f;
            float ph = atan2f(oii, rr);
            int off = (((n << 3) + kb) << 10) + c;
            g_amp[off] = amp;
            g_phase[off] = ph;
        }
    }
}

// ---------------- batched NT SGEMM -----------------------------------------
// C[M,N] = (A (+A2)) * B^T (+bias).  A: M x K row-major, B: N x K row-major.
// Tile 128x128x8, 256 threads, 8x8 per-thread. blockIdx.z selects problem 0/1.
struct GemmArgs {
    const float *A0, *A20, *B0, *bias0; float* C0;
    const float *A1, *A21, *B1, *bias1; float* C1;
};

template<bool ADDA2, int BIASMODE>  // 0: none, 1: bias[col], 2: bias[row]
__global__ void __launch_bounds__(256, 2) sgemm_nt(GemmArgs ga, int M, int N, int K)
{
    const float* A    = blockIdx.z ? ga.A1    : ga.A0;
    const float* A2   = blockIdx.z ? ga.A21   : ga.A20;
    const float* B    = blockIdx.z ? ga.B1    : ga.B0;
    const float* bias = blockIdx.z ? ga.bias1 : ga.bias0;
    float* C          = blockIdx.z ? ga.C1    : ga.C0;

    __shared__ float As[8][132];
    __shared__ float Bs[8][132];
    int tid = threadIdx.x;
    int tx = tid & 15, ty = tid >> 4;
    int row0 = blockIdx.y * 128, col0 = blockIdx.x * 128;
    int lr = tid >> 1, lk = (tid & 1) * 4;
    const float* Ap  = A + (size_t)(row0 + lr) * K + lk;
    const float* A2p = ADDA2 ? (A2 + (size_t)(row0 + lr) * K + lk) : nullptr;
    const float* Bp  = B + (size_t)(col0 + lr) * K + lk;

    float acc[8][8];
    #pragma unroll
    for (int i = 0; i < 8; i++)
        #pragma unroll
        for (int j = 0; j < 8; j++) acc[i][j] = 0.f;

    for (int k0 = 0; k0 < K; k0 += 8) {
        float4 av = *(const float4*)(Ap + k0);
        if (ADDA2) {
            float4 a2 = *(const float4*)(A2p + k0);
            av.x += a2.x; av.y += a2.y; av.z += a2.z; av.w += a2.w;
        }
        float4 bv = *(const float4*)(Bp + k0);
        As[lk + 0][lr] = av.x; As[lk + 1][lr] = av.y; As[lk + 2][lr] = av.z; As[lk + 3][lr] = av.w;
        Bs[lk + 0][lr] = bv.x; Bs[lk + 1][lr] = bv.y; Bs[lk + 2][lr] = bv.z; Bs[lk + 3][lr] = bv.w;
        __syncthreads();
        #pragma unroll
        for (int kk = 0; kk < 8; kk++) {
            float ar[8], br[8];
            *(float4*)&ar[0] = *(const float4*)&As[kk][ty * 8];
            *(float4*)&ar[4] = *(const float4*)&As[kk][ty * 8 + 4];
            *(float4*)&br[0] = *(const float4*)&Bs[kk][tx * 8];
            *(float4*)&br[4] = *(const float4*)&Bs[kk][tx * 8 + 4];
            #pragma unroll
            for (int i = 0; i < 8; i++)
                #pragma unroll
                for (int j = 0; j < 8; j++)
                    acc[i][j] = fmaf(ar[i], br[j], acc[i][j]);
        }
        __syncthreads();
    }
    #pragma unroll
    for (int i = 0; i < 8; i++) {
        int r = row0 + ty * 8 + i;
        #pragma unroll
        for (int j = 0; j < 8; j++) {
            int c = col0 + tx * 8 + j;
            if (c < N) {
                float vv = acc[i][j];
                if (BIASMODE == 1) vv += bias[c];
                if (BIASMODE == 2) vv += bias[r];
                C[(size_t)r * N + c] = vv;
            }
        }
    }
}

// ---------------- softmax (+optional instance norm) ------------------------
// one warp per (n,b) row of 100; writes shifted (m=1..99) + zero pad to 112
template<bool INORM>
__global__ void __launch_bounds__(256) softmax_k(const float* __restrict__ Ain,
                                                 float* __restrict__ Sout)
{
    int gw = (blockIdx.x * 256 + threadIdx.x) >> 5;
    int lane = threadIdx.x & 31;
    if (gw >= MROWS) return;
    const float* a = Ain + (size_t)gw * KPAD;
    float v[4]; bool val[4];
    #pragma unroll
    for (int q = 0; q < 4; q++) {
        int idx = lane + 32 * q;
        val[q] = idx < 100;
        v[q] = val[q] ? a[idx] : 0.f;
    }
    if (INORM) {
        float s = v[0] + v[1] + v[2] + v[3];
        #pragma unroll
        for (int o = 16; o > 0; o >>= 1) s += __shfl_xor_sync(0xffffffffu, s, o);
        float mu = s * 0.01f;
        float s2 = 0.f;
        #pragma unroll
        for (int q = 0; q < 4; q++) if (val[q]) { float d = v[q] - mu; s2 += d * d; }
        #pragma unroll
        for (int o = 16; o > 0; o >>= 1) s2 += __shfl_xor_sync(0xffffffffu, s2, o);
        float inv = rsqrtf(s2 * 0.01f + 1e-5f);
        #pragma unroll
        for (int q = 0; q < 4; q++) v[q] = (v[q] - mu) * inv;
    }
    float m = -1e30f;
    #pragma unroll
    for (int q = 0; q < 4; q++) if (val[q]) m = fmaxf(m, v[q] * 0.03125f);
    #pragma unroll
    for (int o = 16; o > 0; o >>= 1) m = fmaxf(m, __shfl_xor_sync(0xffffffffu, m, o));
    float e[4]; float se = 0.f;
    #pragma unroll
    for (int q = 0; q < 4; q++) {
        e[q] = val[q] ? expf(v[q] * 0.03125f - m) : 0.f;
        se += e[q];
    }
    #pragma unroll
    for (int o = 16; o > 0; o >>= 1) se += __shfl_xor_sync(0xffffffffu, se, o);
    float rinv = 1.f / se;
    float* o = Sout + (size_t)gw * KPAD;
    #pragma unroll
    for (int q = 0; q < 4; q++) {
        int idx = lane + 32 * q;
        if (idx >= 1 && idx < 100) o[idx - 1] = e[q] * rinv;
    }
    if (lane < KPAD - 99) o[99 + lane] = 0.f;
}

// ---------------- z = (cos(dp)*da, sin(dp)*da)  (1/sqrt(2048) folded later)
__global__ void zbuild_k()
{
    int i = blockIdx.x * 256 + threadIdx.x;
    if (i >= MROWS * NZ) return;
    float ph = g_dp[i], am = g_da[i];
    float s, c;
    sincosf(ph, &s, &c);
    g_zr[i] = c * am;
    g_zi[i] = s * am;
}

// ---------------- inverse: ifft_b(8) -> Hermitian irfft(1024) -> out -------
__global__ void __launch_bounds__(512) fft_inv(const float* __restrict__ feats,
                                               const float* __restrict__ scale_p,
                                               float* __restrict__ out)
{
    extern __shared__ float sm[];
    float* sre = sm;               // 8192
    float* sim = sm + 8192;        // 8192
    float* twr = sm + 16384;       // 512
    float* twi = twr + 512;        // 512
    float* zr  = twi + 512;        // 8*513
    float* zi  = zr + 8 * 513;     // 8*513
    int tid = threadIdx.x;
    int n = blockIdx.x;

    { // inverse twiddles: exp(+2*pi*i*t/1024)
        float s_, c_;
        sincospif((float)tid * (1.0f / 512.0f), &s_, &c_);
        twr[tid] = c_;
        twi[tid] = s_;
    }
    for (int i = tid; i < 8 * 513; i += 512) {
        zr[i] = g_zr[(size_t)n * (8 * 513) + i];
        zi[i] = g_zi[(size_t)n * (8 * 513) + i];
    }
    __syncthreads();
    // 8-point inverse DFT along b (in place on z columns)
    const float W8R[8] = {1.f, 0.70710678f, 0.f, -0.70710678f, -1.f, -0.70710678f, 0.f, 0.70710678f};
    const float W8I[8] = {0.f, -0.70710678f, -1.f, -0.70710678f, 0.f, 0.70710678f, 1.f, 0.70710678f};
    for (int c = tid; c < 513; c += 512) {
        float ar[8], ai[8], obr[8], obi[8];
        #pragma unroll
        for (int kb = 0; kb < 8; kb++) { ar[kb] = zr[kb * 513 + c]; ai[kb] = zi[kb * 513 + c]; }
        #pragma unroll
        for (int b = 0; b < 8; b++) {
            float orr = 0.f, oii = 0.f;
            #pragma unroll
            for (int kb = 0; kb < 8; kb++) {
                int t8 = (kb * b) & 7;
                float wr = W8R[t8], wi = -W8I[t8];   // conjugate = inverse
                orr += ar[kb] * wr - ai[kb] * wi;
                oii += ar[kb] * wi + ai[kb] * wr;
            }
            obr[b] = orr; obi[b] = oii;
        }
        #pragma unroll
        for (int b = 0; b < 8; b++) { zr[b * 513 + c] = obr[b]; zi[b * 513 + c] = obi[b]; }
    }
    __syncthreads();
    // Hermitian extension (bit-reversed fill)
    for (int i = tid; i < 8192; i += 512) {
        int b = i >> 10, k = i & 1023;
        int rc = __brev((unsigned)k) >> 22;
        float vr, vi;
        if (k <= 512) { vr = zr[b * 513 + k];          vi =  zi[b * 513 + k]; }
        else          { vr = zr[b * 513 + (1024 - k)]; vi = -zi[b * 513 + (1024 - k)]; }
        sre[(b << 10) + rc] = vr;
        sim[(b << 10) + rc] = vi;
    }
    __syncthreads();
    // inverse 1024-point FFT (DIT, + twiddles)
    for (int s = 1; s <= 10; s++) {
        int half = 1 << (s - 1);
        for (int t = tid; t < 4096; t += 512) {
            int b = t >> 9;
            int j = t & 511;
            int pos = j & (half - 1);
            int base = (j >> (s - 1)) << s;
            int i1 = (b << 10) + base + pos;
            int i2 = i1 + half;
            int ti = pos << (10 - s);
            float wr = twr[ti], wi = twi[ti];
            float ur = sre[i1], ui = sim[i1];
            float xr = sre[i2], xi = sim[i2];
            float vr = xr * wr - xi * wi;
            float vi = xr * wi + xi * wr;
            sre[i1] = ur + vr; sim[i1] = ui + vi;
            sre[i2] = ur - vr; sim[i2] = ui - vi;
        }
        __syncthreads();
    }
    // delta = Re(.) * 1/4096  (= ortho 1/sqrt(8192) * z-scale 1/sqrt(2048))
    float sc = scale_p[0];
    for (int i = tid; i < 8192; i += 512) {
        int b = i >> 10, c = i & 1023;
        float d = sre[(b << 10) + c] * (1.0f / 4096.0f);
        size_t off = ((size_t)(n + 1) * 8 + b) * 1024 + c;
        out[off] = feats[off] + d * sc;
    }
}

__global__ void cls_copy(const float* __restrict__ feats, float* __restrict__ out)
{
    int i = blockIdx.x * 256 + threadIdx.x;
    if (i < 8192) out[i] = feats[i];
}

// ---------------- host ------------------------------------------------------
static void* symaddr(const void* s)
{
    void* p = nullptr;
    cudaGetSymbolAddress(&p, s);
    return p;
}

extern "C" void kernel_launch(void* const* d_in, const int* in_sizes, int n_in,
                              void* d_out, int out_size)
{
    (void)in_sizes; (void)n_in; (void)out_size;
    const float* feats  = (const float*)d_in[0];
    const float* lt1    = (const float*)d_in[1];
    const float* lt2    = (const float*)d_in[2];
    const float* w_t2f  = (const float*)d_in[3];
    const float* b_t2f  = (const float*)d_in[4];
    const float* w_df   = (const float*)d_in[5];
    const float* b_df   = (const float*)d_in[6];
    const float* w_t2f2 = (const float*)d_in[7];
    const float* b_t2f2 = (const float*)d_in[8];
    const float* w_df2  = (const float*)d_in[9];
    const float* b_df2  = (const float*)d_in[10];
    const float* scale  = (const float*)d_in[11];
    const int*   layer  = (const int*)d_in[12];
    float* out = (float*)d_out;

    float* phase = (float*)symaddr(g_phase);
    float* amp   = (float*)symaddr(g_amp);
    float* T1    = (float*)symaddr(g_T1);
    float* T2    = (float*)symaddr(g_T2);
    float* A1    = (float*)symaddr(g_A1);
    float* A2r   = (float*)symaddr(g_A2r);
    float* S1    = (float*)symaddr(g_S1);
    float* S2    = (float*)symaddr(g_S2);
    float* vT1   = (float*)symaddr(g_vT1);
    float* vT2   = (float*)symaddr(g_vT2);
    float* df1   = (float*)symaddr(g_df1);
    float* df2   = (float*)symaddr(g_df2);
    float* dp    = (float*)symaddr(g_dp);
    float* da    = (float*)symaddr(g_da);

    const int FWD_SMEM = (8192 * 2 + 1024) * 4;                 // 69632
    const int INV_SMEM = (8192 * 2 + 1024 + 2 * 8 * 513) * 4;   // 102464
    cudaFuncSetAttribute(fft_fwd, cudaFuncAttributeMaxDynamicSharedMemorySize, FWD_SMEM);
    cudaFuncSetAttribute(fft_inv, cudaFuncAttributeMaxDynamicSharedMemorySize, INV_SMEM);

    // 1) padded tokens for the selected layer
    prep_tokens<<<(TROWS * CDIM) / 256, 256>>>(lt1, lt2, layer);

    // 2) FFT2 + amp/phase
    fft_fwd<<<1024, 512, FWD_SMEM>>>(feats);

    // 3) attn = X @ T^T   (both branches batched)
    GemmArgs attn = { phase, nullptr, T1, nullptr, A1,
                      amp,   nullptr, T2, nullptr, A2r };
    sgemm_nt<false, 0><<<dim3(1, 64, 2), 256>>>(attn, MROWS, KPAD, CDIM);

    // 4) softmax (amp branch with instance norm), shifted + zero padded
    softmax_k<false><<<1024, 256>>>(A1, S1);
    softmax_k<true ><<<1024, 256>>>(A2r, S2);

    // 5) vT[c][j] = sum_k T[1+j][k] * W[c][k] + b[c]   (row bias)
    GemmArgs vt = { w_t2f,  nullptr, T1 + CDIM, b_t2f,  vT1,
                    w_t2f2, nullptr, T2 + CDIM, b_t2f2, vT2 };
    sgemm_nt<false, 2><<<dim3(1, 8, 2), 256>>>(vt, CDIM, KPAD, CDIM);

    // 6) df = S @ vT^T
    GemmArgs dfa = { S1, nullptr, vT1, nullptr, df1,
                     S2, nullptr, vT2, nullptr, df2 };
    sgemm_nt<false, 0><<<dim3(8, 64, 2), 256>>>(dfa, MROWS, CDIM, KPAD);

    // 7) d = (df + X) @ Wdf^T + b  — only the 513 needed columns
    GemmArgs big = { df1, phase, w_df,  b_df,  dp,
                     df2, amp,   w_df2, b_df2, da };
    sgemm_nt<true, 1><<<dim3(5, 64, 2), 256>>>(big, MROWS, NZ, CDIM);

    // 8) z = (cos*amp, sin*amp)
    zbuild_k<<<(MROWS * NZ + 255) / 256, 256>>>();

    // 9) irfft2 + residual add
    fft_inv<<<1024, 512, INV_SMEM>>>(feats, scale, out);

    // 10) cls row passthrough
    cls_copy<<<32, 256>>>(feats, out);
}

// round 6
// speedup vs baseline: 2.0781x; 2.0781x over previous
#include <cuda_runtime.h>
#include <cuda_bf16.h>
#include <math.h>
#include <stdint.h>

#if defined(__CUDA_ARCH__) && (defined(__CUDA_ARCH_SPECIFIC__) || defined(__CUDA_ARCH_FAMILY_SPECIFIC__))
#define HAS_TCGEN05 1
#else
#define HAS_TCGEN05 0
#endif

#define MROWS 8192      // 1024 * 8 rows
#define CDIM  1024
#define KP    128       // padded token/attention dim
#define NZ    513       // kept spectrum columns

// ---------------- scratch (device globals; no allocation allowed) ----------
__device__ float g_phase[MROWS*CDIM];
__device__ float g_amp  [MROWS*CDIM];
__device__ __nv_bfloat16 g_phb[MROWS*CDIM];
__device__ __nv_bfloat16 g_amb[MROWS*CDIM];
__device__ __nv_bfloat16 g_T1b[144*CDIM];
__device__ __nv_bfloat16 g_T2b[144*CDIM];
__device__ float g_A1[MROWS*KP];
__device__ float g_A2[MROWS*KP];
__device__ __nv_bfloat16 g_S1[MROWS*KP];
__device__ __nv_bfloat16 g_S2[MROWS*KP];
__device__ __nv_bfloat16 g_vT1[CDIM*KP];
__device__ __nv_bfloat16 g_vT2[CDIM*KP];
__device__ __nv_bfloat16 g_P1[MROWS*CDIM];
__device__ __nv_bfloat16 g_P2[MROWS*CDIM];
__device__ __nv_bfloat16 g_W1[CDIM*CDIM]; // w_t2f
__device__ __nv_bfloat16 g_W2[CDIM*CDIM]; // w_t2f2
__device__ __nv_bfloat16 g_W3[CDIM*CDIM]; // w_df
__device__ __nv_bfloat16 g_W4[CDIM*CDIM]; // w_df2
__device__ float g_dp[MROWS*NZ];
__device__ float g_da[MROWS*NZ];
__device__ float g_zr[MROWS*NZ];
__device__ float g_zi[MROWS*NZ];

// ---------------- PTX helpers ----------------------------------------------
__device__ __forceinline__ uint32_t smem_u32(const void* p) {
    uint32_t a;
    asm("{ .reg .u64 t; cvta.to.shared.u64 t, %1; cvt.u32.u64 %0, t; }" : "=r"(a) : "l"(p));
    return a;
}
__device__ __forceinline__ bool elect1() {
    uint32_t p;
    asm volatile("{ .reg .pred p; elect.sync _|p, 0xFFFFFFFF; selp.b32 %0, 1, 0, p; }" : "=r"(p));
    return p != 0;
}
__device__ __forceinline__ uint64_t make_desc(uint32_t addr) {
    const uint64_t base = (uint64_t(2) << 61) | (uint64_t(1) << 46) |
                          (uint64_t(64) << 32) | (uint64_t(1) << 16);
    return base | ((addr >> 4) & 0x3FFF);
}
__device__ __forceinline__ void mbar_wait(uint32_t mbar, uint32_t parity) {
    asm volatile(
        "{\n\t.reg .pred P;\n\t"
        "WL%=:\n\t"
        "mbarrier.try_wait.parity.acquire.cta.shared::cta.b64 P, [%0], %1, 0x989680;\n\t"
        "@P bra.uni WD%=;\n\t"
        "bra.uni WL%=;\n\t"
        "WD%=:\n\t}"
        :: "r"(mbar), "r"(parity) : "memory");
}

#if HAS_TCGEN05
__device__ __forceinline__ void mma_ss_f16(uint32_t d, uint64_t ad, uint64_t bd,
                                           uint32_t idesc, bool acc) {
    uint32_t en = acc ? 1u : 0u;
    asm volatile(
        "{\n\t.reg .pred p;\n\tsetp.ne.u32 p, %4, 0;\n\t"
        "tcgen05.mma.cta_group::1.kind::f16 [%0], %1, %2, %3, {%5, %5, %5, %5}, p;\n\t}"
        :: "r"(d), "l"(ad), "l"(bd), "r"(idesc), "r"(en), "r"(0u) : "memory");
}
#define LDTM_X32(r, a) \
    asm volatile( \
        "tcgen05.ld.sync.aligned.32x32b.x32.b32 " \
        "{%0, %1, %2, %3, %4, %5, %6, %7, " \
        " %8, %9, %10, %11, %12, %13, %14, %15, " \
        " %16, %17, %18, %19, %20, %21, %22, %23, " \
        " %24, %25, %26, %27, %28, %29, %30, %31}, [%32];" \
        : "=r"((r)[0]),  "=r"((r)[1]),  "=r"((r)[2]),  "=r"((r)[3]), \
          "=r"((r)[4]),  "=r"((r)[5]),  "=r"((r)[6]),  "=r"((r)[7]), \
          "=r"((r)[8]),  "=r"((r)[9]),  "=r"((r)[10]), "=r"((r)[11]), \
          "=r"((r)[12]), "=r"((r)[13]), "=r"((r)[14]), "=r"((r)[15]), \
          "=r"((r)[16]), "=r"((r)[17]), "=r"((r)[18]), "=r"((r)[19]), \
          "=r"((r)[20]), "=r"((r)[21]), "=r"((r)[22]), "=r"((r)[23]), \
          "=r"((r)[24]), "=r"((r)[25]), "=r"((r)[26]), "=r"((r)[27]), \
          "=r"((r)[28]), "=r"((r)[29]), "=r"((r)[30]), "=r"((r)[31]) \
        : "r"(a))
#endif

// idesc: fp32 accum, bf16 A/B, M=128, N=128
#define IDESC_128 0x08200490u

// ---------------- token prep: T[layer] -> bf16 padded buffers --------------
__global__ void prep_tokens(const float* __restrict__ lt1,
                            const float* __restrict__ lt2,
                            const int* __restrict__ layer_p)
{
    int i = blockIdx.x * 256 + threadIdx.x;
    if (i >= 144 * CDIM) return;
    int row = i >> 10;
    int layer = layer_p[0];
    float v1 = 0.f, v2 = 0.f;
    if (row < 100) {
        v1 = lt1[layer * 100 * CDIM + i];
        v2 = lt2[layer * 100 * CDIM + i];
    }
    g_T1b[i] = __float2bfloat16(v1);
    g_T2b[i] = __float2bfloat16(v2);
}

// ---------------- weight conversion fp32 -> bf16 ---------------------------
__global__ void conv_w(const float* __restrict__ a, const float* __restrict__ b,
                       const float* __restrict__ c, const float* __restrict__ d)
{
    int i = blockIdx.x * 256 + threadIdx.x;
    if (i >= CDIM * CDIM) return;
    g_W1[i] = __float2bfloat16(a[i]);
    g_W2[i] = __float2bfloat16(b[i]);
    g_W3[i] = __float2bfloat16(c[i]);
    g_W4[i] = __float2bfloat16(d[i]);
}

// ---------------- forward FFT2 + amp/phase ---------------------------------
__global__ void __launch_bounds__(512) fft_fwd(const float* __restrict__ feats)
{
    extern __shared__ float sm[];
    float* sre = sm;
    float* sim = sm + 8192;
    float* twr = sm + 16384;
    float* twi = twr + 512;
    int tid = threadIdx.x;
    int n = blockIdx.x;
    const float* x = feats + (size_t)(n + 1) * 8192;

    {
        float s_, c_;
        sincospif(-(float)tid * (1.0f / 512.0f), &s_, &c_);
        twr[tid] = c_;
        twi[tid] = s_;
    }
    for (int i = tid; i < 8192; i += 512) {
        int b = i >> 10, c = i & 1023;
        int rc = __brev((unsigned)c) >> 22;
        sre[(b << 10) + rc] = x[i];
        sim[(b << 10) + rc] = 0.f;
    }
    __syncthreads();
    for (int s = 1; s <= 10; s++) {
        int half = 1 << (s - 1);
        for (int t = tid; t < 4096; t += 512) {
            int b = t >> 9;
            int j = t & 511;
            int pos = j & (half - 1);
            int base = (j >> (s - 1)) << s;
            int i1 = (b << 10) + base + pos;
            int i2 = i1 + half;
            int ti = pos << (10 - s);
            float wr = twr[ti], wi = twi[ti];
            float ur = sre[i1], ui = sim[i1];
            float xr = sre[i2], xi = sim[i2];
            float vr = xr * wr - xi * wi;
            float vi = xr * wi + xi * wr;
            sre[i1] = ur + vr; sim[i1] = ui + vi;
            sre[i2] = ur - vr; sim[i2] = ui - vi;
        }
        __syncthreads();
    }
    const float W8R[8] = {1.f, 0.70710678f, 0.f, -0.70710678f, -1.f, -0.70710678f, 0.f, 0.70710678f};
    const float W8I[8] = {0.f, -0.70710678f, -1.f, -0.70710678f, 0.f, 0.70710678f, 1.f, 0.70710678f};
    for (int c = tid; c < 1024; c += 512) {
        float ar[8], ai[8];
        #pragma unroll
        for (int b = 0; b < 8; b++) { ar[b] = sre[(b << 10) + c]; ai[b] = sim[(b << 10) + c]; }
        #pragma unroll
        for (int kb = 0; kb < 8; kb++) {
            float orr = 0.f, oii = 0.f;
            #pragma unroll
            for (int b = 0; b < 8; b++) {
                int t8 = (kb * b) & 7;
                orr += ar[b] * W8R[t8] - ai[b] * W8I[t8];
                oii += ar[b] * W8I[t8] + ai[b] * W8R[t8];
            }
            float p = orr * orr + oii * oii;
            if (p < 1e-5f) p = 1e-5f;
            float amp = sqrtf(p);
            float rr = orr;
            if (rr < 1e-5f && rr > -1e-5f) rr = 1e-5f;
            float ph = atan2f(oii, rr);
            int off = (((n << 3) + kb) << 10) + c;
            g_amp[off] = amp;
            g_phase[off] = ph;
            g_amb[off] = __float2bfloat16(amp);
            g_phb[off] = __float2bfloat16(ph);
        }
    }
}

// ---------------- tcgen05 bf16 GEMM ----------------------------------------
// C[M,N] = A * B^T, A: M x K (lda), B: N x K (ldb), bf16 in, fp32 accum.
// 128x128 tile / CTA, K chunks of 64, double-buffered smem, TMEM accumulator.
// blockIdx.z selects branch. EPI: 0 = f32 store, 1 = bf16 store,
// 2 = (+X fp32) -> bf16 store. BIAS: 0 none, 1 per-col fp32, 2 per-row fp32.
struct GB {
    const __nv_bfloat16 *A0, *A1b;
    const __nv_bfloat16 *B0, *B1b;
    const float *bias0, *bias1;
    const float *X0, *X1;
    void *C0, *C1;
};

template<int EPI, int BIAS>
__global__ void __launch_bounds__(128, 3) gemm_tc(GB g, int lda, int ldb, int ldc,
                                                  int ldx, int nk, int nguard)
{
    extern __shared__ char sm_[];
    int tid = threadIdx.x;
    int z = blockIdx.z;
    const __nv_bfloat16* A = z ? g.A1b : g.A0;
    const __nv_bfloat16* B = z ? g.B1b : g.B0;
    const float* bias = z ? g.bias1 : g.bias0;
    const float* X = z ? g.X1 : g.X0;
    char* C = (char*)(z ? g.C1 : g.C0);
    int row0 = blockIdx.y << 7, col0 = blockIdx.x << 7;

#if HAS_TCGEN05
    uint32_t sb = smem_u32(sm_);
    uint32_t ta = (sb + 1023u) & ~1023u;       // 1024-aligned tile base
    char* tp = sm_ + (ta - sb);
    uint32_t ctrl = ta + 65536;                // tmem ptr + mbarriers live above tiles
    int wid = tid >> 5, lane = tid & 31;

    if (wid == 0) {
        asm volatile("tcgen05.alloc.cta_group::1.sync.aligned.shared::cta.b32 [%0], %1;"
                     :: "r"(ctrl), "r"(128u) : "memory");
        asm volatile("tcgen05.relinquish_alloc_permit.cta_group::1.sync.aligned;");
    }
    if (tid == 0) {
        asm volatile("mbarrier.init.shared.b64 [%0], 1;" :: "r"(ctrl + 8) : "memory");
        asm volatile("mbarrier.init.shared.b64 [%0], 1;" :: "r"(ctrl + 16) : "memory");
    }
    __syncthreads();
    uint32_t tmem;
    asm volatile("ld.shared.b32 %0, [%1];" : "=r"(tmem) : "r"(ctrl));

    const __nv_bfloat16* Ab = A + (size_t)row0 * lda;
    const __nv_bfloat16* Bb = B + (size_t)col0 * ldb;
    const int abase[2] = {0, 16384};
    const int bbase[2] = {32768, 49152};
    int ph[2] = {0, 0};

    for (int c = 0; c < nk; c++) {
        int b = c & 1;
        if (c >= 2) { mbar_wait(ctrl + 8 + b * 8, (uint32_t)ph[b]); ph[b] ^= 1; }
        int k0 = c << 6;
        #pragma unroll
        for (int it = 0; it < 8; it++) {
            int u = tid + (it << 7);
            int row = u >> 3, seg = u & 7;
            uint4 va = *(const uint4*)(Ab + (size_t)row * lda + k0 + (seg << 3));
            uint4 vb = *(const uint4*)(Bb + (size_t)row * ldb + k0 + (seg << 3));
            uint32_t bo = (row << 7) + (seg << 4);
            uint32_t so = bo ^ ((bo >> 3) & 0x70);
            *(uint4*)(tp + abase[b] + so) = va;
            *(uint4*)(tp + bbase[b] + so) = vb;
        }
        asm volatile("fence.proxy.async.shared::cta;" ::: "memory");
        __syncthreads();
        if (wid == 0 && elect1()) {
            uint64_t ad = make_desc(ta + abase[b]);
            uint64_t bd = make_desc(ta + bbase[b]);
            #pragma unroll
            for (int kk = 0; kk < 4; kk++)
                mma_ss_f16(tmem, ad + kk * 2, bd + kk * 2, IDESC_128, (c | kk) != 0);
            asm volatile(
                "tcgen05.commit.cta_group::1.mbarrier::arrive::one.shared::cluster.b64 [%0];"
                :: "r"(ctrl + 8 + b * 8) : "memory");
        }
    }
    mbar_wait(ctrl + 8, (uint32_t)ph[0]);
    mbar_wait(ctrl + 16, (uint32_t)ph[1]);
    asm volatile("tcgen05.fence::after_thread_sync;" ::: "memory");

    // epilogue: TMEM -> smem transpose -> coalesced global stores
    float* smf = (float*)tp;
    int rr_ = (wid << 5) + lane;
    float biasr = (BIAS == 2) ? bias[row0 + rr_] : 0.f;
    for (int cb = 0; cb < 4; cb++) {
        uint32_t r_[32];
        LDTM_X32(r_, tmem + (cb << 5));
        asm volatile("tcgen05.wait::ld.sync.aligned;" ::: "memory");
        __syncthreads();
        #pragma unroll
        for (int j = 0; j < 32; j++) smf[rr_ * 33 + j] = __uint_as_float(r_[j]) + biasr;
        __syncthreads();
        #pragma unroll
        for (int i = 0; i < 32; i++) {
            int idx = tid + (i << 7);
            int orow = idx >> 5, ocol = idx & 31;
            int cc = col0 + (cb << 5) + ocol;
            if (cc < nguard) {
                float v = smf[orow * 33 + ocol];
                if (BIAS == 1) v += bias[cc];
                size_t off = (size_t)(row0 + orow) * ldc + cc;
                if (EPI == 0) ((float*)C)[off] = v;
                else if (EPI == 1) ((__nv_bfloat16*)C)[off] = __float2bfloat16(v);
                else {
                    v += X[(size_t)(row0 + orow) * ldx + cc];
                    ((__nv_bfloat16*)C)[off] = __float2bfloat16(v);
                }
            }
        }
    }
    __syncthreads();
    if (wid == 0) {
        asm volatile("tcgen05.dealloc.cta_group::1.sync.aligned.b32 %0, %1;"
                     :: "r"(tmem), "r"(128u));
    }
#else
    // Scalar fallback — correct on any target; only runs if the arch-specific
    // cubin is unavailable.
    (void)sm_;
    int row = row0 + tid;
    int K = nk << 6;
    for (int cc = 0; cc < 128; cc++) {
        int c = col0 + cc;
        if (c >= nguard) continue;
        float acc = 0.f;
        for (int k = 0; k < K; k++)
            acc += __bfloat162float(A[(size_t)row * lda + k]) *
                   __bfloat162float(B[(size_t)c * ldb + k]);
        if (BIAS == 1) acc += bias[c];
        if (BIAS == 2) acc += bias[row];
        size_t off = (size_t)row * ldc + c;
        if (EPI == 0) ((float*)C)[off] = acc;
        else if (EPI == 1) ((__nv_bfloat16*)C)[off] = __float2bfloat16(acc);
        else {
            acc += X[(size_t)row * ldx + c];
            ((__nv_bfloat16*)C)[off] = __float2bfloat16(acc);
        }
    }
#endif
}

// ---------------- softmax (+optional instance norm), bf16 out --------------
template<bool INORM>
__global__ void __launch_bounds__(256) softmax_k(const float* __restrict__ Ain,
                                                 __nv_bfloat16* __restrict__ Sout)
{
    int gw = (blockIdx.x * 256 + threadIdx.x) >> 5;
    int lane = threadIdx.x & 31;
    if (gw >= MROWS) return;
    const float* a = Ain + (size_t)gw * KP;
    float v[4]; bool val[4];
    #pragma unroll
    for (int q = 0; q < 4; q++) {
        int idx = lane + 32 * q;
        val[q] = idx < 100;
        v[q] = val[q] ? a[idx] : 0.f;
    }
    if (INORM) {
        float s = v[0] + v[1] + v[2] + v[3];
        #pragma unroll
        for (int o = 16; o > 0; o >>= 1) s += __shfl_xor_sync(0xffffffffu, s, o);
        float mu = s * 0.01f;
        float s2 = 0.f;
        #pragma unroll
        for (int q = 0; q < 4; q++) if (val[q]) { float d = v[q] - mu; s2 += d * d; }
        #pragma unroll
        for (int o = 16; o > 0; o >>= 1) s2 += __shfl_xor_sync(0xffffffffu, s2, o);
        float inv = rsqrtf(s2 * 0.01f + 1e-5f);
        #pragma unroll
        for (int q = 0; q < 4; q++) v[q] = (v[q] - mu) * inv;
    }
    float m = -1e30f;
    #pragma unroll
    for (int q = 0; q < 4; q++) if (val[q]) m = fmaxf(m, v[q] * 0.03125f);
    #pragma unroll
    for (int o = 16; o > 0; o >>= 1) m = fmaxf(m, __shfl_xor_sync(0xffffffffu, m, o));
    float e[4]; float se = 0.f;
    #pragma unroll
    for (int q = 0; q < 4; q++) {
        e[q] = val[q] ? expf(v[q] * 0.03125f - m) : 0.f;
        se += e[q];
    }
    #pragma unroll
    for (int o = 16; o > 0; o >>= 1) se += __shfl_xor_sync(0xffffffffu, se, o);
    float rinv = 1.f / se;
    __nv_bfloat16* o = Sout + (size_t)gw * KP;
    #pragma unroll
    for (int q = 0; q < 4; q++) {
        int idx = lane + 32 * q;
        if (idx >= 1 && idx < 100) o[idx - 1] = __float2bfloat16(e[q] * rinv);
        else if (idx >= 100) o[idx - 1] = __float2bfloat16(0.f);
        else o[127] = __float2bfloat16(0.f);   // idx == 0
    }
}

// ---------------- z = (cos(dp)*da, sin(dp)*da) ------------------------------
__global__ void zbuild_k()
{
    int i = blockIdx.x * 256 + threadIdx.x;
    if (i >= MROWS * NZ) return;
    float ph = g_dp[i], am = g_da[i];
    float s, c;
    sincosf(ph, &s, &c);
    g_zr[i] = c * am;
    g_zi[i] = s * am;
}

// ---------------- inverse: ifft_b(8) -> Hermitian irfft(1024) -> out -------
__global__ void __launch_bounds__(512) fft_inv(const float* __restrict__ feats,
                                               const float* __restrict__ scale_p,
                                               float* __restrict__ out)
{
    extern __shared__ float sm[];
    float* sre = sm;
    float* sim = sm + 8192;
    float* twr = sm + 16384;
    float* twi = twr + 512;
    float* zr  = twi + 512;
    float* zi  = zr + 8 * 513;
    int tid = threadIdx.x;
    int n = blockIdx.x;

    {
        float s_, c_;
        sincospif((float)tid * (1.0f / 512.0f), &s_, &c_);
        twr[tid] = c_;
        twi[tid] = s_;
    }
    for (int i = tid; i < 8 * 513; i += 512) {
        zr[i] = g_zr[(size_t)n * (8 * 513) + i];
        zi[i] = g_zi[(size_t)n * (8 * 513) + i];
    }
    __syncthreads();
    const float W8R[8] = {1.f, 0.70710678f, 0.f, -0.70710678f, -1.f, -0.70710678f, 0.f, 0.70710678f};
    const float W8I[8] = {0.f, -0.70710678f, -1.f, -0.70710678f, 0.f, 0.70710678f, 1.f, 0.70710678f};
    for (int c = tid; c < 513; c += 512) {
        float ar[8], ai[8], obr[8], obi[8];
        #pragma unroll
        for (int kb = 0; kb < 8; kb++) { ar[kb] = zr[kb * 513 + c]; ai[kb] = zi[kb * 513 + c]; }
        #pragma unroll
        for (int b = 0; b < 8; b++) {
            float orr = 0.f, oii = 0.f;
            #pragma unroll
            for (int kb = 0; kb < 8; kb++) {
                int t8 = (kb * b) & 7;
                float wr = W8R[t8], wi = -W8I[t8];
                orr += ar[kb] * wr - ai[kb] * wi;
                oii += ar[kb] * wi + ai[kb] * wr;
            }
            obr[b] = orr; obi[b] = oii;
        }
        #pragma unroll
        for (int b = 0; b < 8; b++) { zr[b * 513 + c] = obr[b]; zi[b * 513 + c] = obi[b]; }
    }
    __syncthreads();
    for (int i = tid; i < 8192; i += 512) {
        int b = i >> 10, k = i & 1023;
        int rc = __brev((unsigned)k) >> 22;
        float vr, vi;
        if (k <= 512) { vr = zr[b * 513 + k];          vi =  zi[b * 513 + k]; }
        else          { vr = zr[b * 513 + (1024 - k)]; vi = -zi[b * 513 + (1024 - k)]; }
        sre[(b << 10) + rc] = vr;
        sim[(b << 10) + rc] = vi;
    }
    __syncthreads();
    for (int s = 1; s <= 10; s++) {
        int half = 1 << (s - 1);
        for (int t = tid; t < 4096; t += 512) {
            int b = t >> 9;
            int j = t & 511;
            int pos = j & (half - 1);
            int base = (j >> (s - 1)) << s;
            int i1 = (b << 10) + base + pos;
            int i2 = i1 + half;
            int ti = pos << (10 - s);
            float wr = twr[ti], wi = twi[ti];
            float ur = sre[i1], ui = sim[i1];
            float xr = sre[i2], xi = sim[i2];
            float vr = xr * wr - xi * wi;
            float vi = xr * wi + xi * wr;
            sre[i1] = ur + vr; sim[i1] = ui + vi;
            sre[i2] = ur - vr; sim[i2] = ui - vi;
        }
        __syncthreads();
    }
    float sc = scale_p[0];
    for (int i = tid; i < 8192; i += 512) {
        int b = i >> 10, c = i & 1023;
        float d = sre[(b << 10) + c] * (1.0f / 4096.0f);
        size_t off = ((size_t)(n + 1) * 8 + b) * 1024 + c;
        out[off] = feats[off] + d * sc;
    }
}

__global__ void cls_copy(const float* __restrict__ feats, float* __restrict__ out)
{
    int i = blockIdx.x * 256 + threadIdx.x;
    if (i < 8192) out[i] = feats[i];
}

// ---------------- host ------------------------------------------------------
static void* symaddr(const void* s)
{
    void* p = nullptr;
    cudaGetSymbolAddress(&p, s);
    return p;
}

extern "C" void kernel_launch(void* const* d_in, const int* in_sizes, int n_in,
                              void* d_out, int out_size)
{
    (void)in_sizes; (void)n_in; (void)out_size;
    const float* feats  = (const float*)d_in[0];
    const float* lt1    = (const float*)d_in[1];
    const float* lt2    = (const float*)d_in[2];
    const float* w_t2f  = (const float*)d_in[3];
    const float* b_t2f  = (const float*)d_in[4];
    const float* w_df   = (const float*)d_in[5];
    const float* b_df   = (const float*)d_in[6];
    const float* w_t2f2 = (const float*)d_in[7];
    const float* b_t2f2 = (const float*)d_in[8];
    const float* w_df2  = (const float*)d_in[9];
    const float* b_df2  = (const float*)d_in[10];
    const float* scale  = (const float*)d_in[11];
    const int*   layer  = (const int*)d_in[12];
    float* out = (float*)d_out;

    __nv_bfloat16* phb = (__nv_bfloat16*)symaddr(g_phb);
    __nv_bfloat16* amb = (__nv_bfloat16*)symaddr(g_amb);
    float* phase = (float*)symaddr(g_phase);
    float* amp   = (float*)symaddr(g_amp);
    __nv_bfloat16* T1b = (__nv_bfloat16*)symaddr(g_T1b);
    __nv_bfloat16* T2b = (__nv_bfloat16*)symaddr(g_T2b);
    float* A1 = (float*)symaddr(g_A1);
    float* A2 = (float*)symaddr(g_A2);
    __nv_bfloat16* S1  = (__nv_bfloat16*)symaddr(g_S1);
    __nv_bfloat16* S2  = (__nv_bfloat16*)symaddr(g_S2);
    __nv_bfloat16* vT1 = (__nv_bfloat16*)symaddr(g_vT1);
    __nv_bfloat16* vT2 = (__nv_bfloat16*)symaddr(g_vT2);
    __nv_bfloat16* P1  = (__nv_bfloat16*)symaddr(g_P1);
    __nv_bfloat16* P2  = (__nv_bfloat16*)symaddr(g_P2);
    __nv_bfloat16* W1  = (__nv_bfloat16*)symaddr(g_W1);
    __nv_bfloat16* W2  = (__nv_bfloat16*)symaddr(g_W2);
    __nv_bfloat16* W3  = (__nv_bfloat16*)symaddr(g_W3);
    __nv_bfloat16* W4  = (__nv_bfloat16*)symaddr(g_W4);
    float* dp = (float*)symaddr(g_dp);
    float* da = (float*)symaddr(g_da);

    const int FWD_SMEM  = (8192 * 2 + 1024) * 4;
    const int INV_SMEM  = (8192 * 2 + 1024 + 2 * 8 * 513) * 4;
    const int GEMM_SMEM = 66624;   // align slack + 64KB tiles + ctrl words
    cudaFuncSetAttribute(fft_fwd, cudaFuncAttributeMaxDynamicSharedMemorySize, FWD_SMEM);
    cudaFuncSetAttribute(fft_inv, cudaFuncAttributeMaxDynamicSharedMemorySize, INV_SMEM);
    cudaFuncSetAttribute(gemm_tc<0,0>, cudaFuncAttributeMaxDynamicSharedMemorySize, GEMM_SMEM);
    cudaFuncSetAttribute(gemm_tc<1,2>, cudaFuncAttributeMaxDynamicSharedMemorySize, GEMM_SMEM);
    cudaFuncSetAttribute(gemm_tc<2,0>, cudaFuncAttributeMaxDynamicSharedMemorySize, GEMM_SMEM);
    cudaFuncSetAttribute(gemm_tc<0,1>, cudaFuncAttributeMaxDynamicSharedMemorySize, GEMM_SMEM);

    // 1) tokens (bf16, padded) + weight conversion
    prep_tokens<<<(144 * CDIM + 255) / 256, 256>>>(lt1, lt2, layer);
    conv_w<<<(CDIM * CDIM + 255) / 256, 256>>>(w_t2f, w_t2f2, w_df, w_df2);

    // 2) FFT2 + amp/phase (fp32 + bf16)
    fft_fwd<<<1024, 512, FWD_SMEM>>>(feats);

    // 3) attn = X @ T^T  -> fp32 [8192 x 128]
    {
        GB g = { phb, amb, T1b, T2b, nullptr, nullptr, nullptr, nullptr, A1, A2 };
        gemm_tc<0,0><<<dim3(1, 64, 2), 128, GEMM_SMEM>>>(g, CDIM, CDIM, KP, 0, 16, KP);
    }

    // 4) softmax -> bf16 S, shifted + zero padded to 128
    softmax_k<false><<<1024, 256>>>(A1, S1);
    softmax_k<true ><<<1024, 256>>>(A2, S2);

    // 5) vT[c][j] = sum_k W[c][k]*T[1+j][k] + b[c]  -> bf16 [1024 x 128]
    {
        GB g = { W1, W2, T1b + CDIM, T2b + CDIM, b_t2f, b_t2f2, nullptr, nullptr, vT1, vT2 };
        gemm_tc<1,2><<<dim3(1, 8, 2), 128, GEMM_SMEM>>>(g, CDIM, CDIM, KP, 0, 16, KP);
    }

    // 6) P = S @ vT^T + X  -> bf16 [8192 x 1024]
    {
        GB g = { S1, S2, vT1, vT2, nullptr, nullptr, phase, amp, P1, P2 };
        gemm_tc<2,0><<<dim3(8, 64, 2), 128, GEMM_SMEM>>>(g, KP, KP, CDIM, CDIM, 2, CDIM);
    }

    // 7) d = P @ Wdf^T + b  -> fp32 [8192 x 513]
    {
        GB g = { P1, P2, W3, W4, b_df, b_df2, nullptr, nullptr, dp, da };
        gemm_tc<0,1><<<dim3(5, 64, 2), 128, GEMM_SMEM>>>(g, CDIM, CDIM, NZ, 0, 16, NZ);
    }

    // 8) z = (cos*amp, sin*amp)
    zbuild_k<<<(MROWS * NZ + 255) / 256, 256>>>();

    // 9) irfft2 + residual add
    fft_inv<<<1024, 512, INV_SMEM>>>(feats, scale, out);

    // 10) cls row passthrough
    cls_copy<<<32, 256>>>(feats, out);
}

// round 7
// speedup vs baseline: 4.3559x; 2.0961x over previous
#include <cuda_runtime.h>
#include <cuda_bf16.h>
#include <math.h>
#include <stdint.h>

#if defined(__CUDA_ARCH__) && (defined(__CUDA_ARCH_SPECIFIC__) || defined(__CUDA_ARCH_FAMILY_SPECIFIC__))
#define HAS_TCGEN05 1
#else
#define HAS_TCGEN05 0
#endif

#define MROWS 8192      // 1024 * 8 rows
#define CDIM  1024
#define KP    128       // padded token/attention dim
#define NZ    513       // kept spectrum columns

// smem bank swizzle for FFT arrays
#define SW(i) ((i) ^ (((i) >> 5) & 31))

// ---------------- scratch (device globals; no allocation allowed) ----------
__device__ __nv_bfloat16 g_phb[MROWS*CDIM];
__device__ __nv_bfloat16 g_amb[MROWS*CDIM];
__device__ __nv_bfloat16 g_T1b[144*CDIM];
__device__ __nv_bfloat16 g_T2b[144*CDIM];
__device__ float g_A1[MROWS*KP];
__device__ float g_A2[MROWS*KP];
__device__ __nv_bfloat16 g_S1[MROWS*KP];
__device__ __nv_bfloat16 g_S2[MROWS*KP];
__device__ __nv_bfloat16 g_vT1[CDIM*KP];
__device__ __nv_bfloat16 g_vT2[CDIM*KP];
__device__ __nv_bfloat16 g_P1[MROWS*CDIM];
__device__ __nv_bfloat16 g_P2[MROWS*CDIM];
__device__ __nv_bfloat16 g_W1[CDIM*CDIM]; // w_t2f
__device__ __nv_bfloat16 g_W2[CDIM*CDIM]; // w_t2f2
__device__ __nv_bfloat16 g_W3[CDIM*CDIM]; // w_df
__device__ __nv_bfloat16 g_W4[CDIM*CDIM]; // w_df2
__device__ __nv_bfloat16 g_dpb[MROWS*NZ];
__device__ __nv_bfloat16 g_dab[MROWS*NZ];

// ---------------- PTX helpers ----------------------------------------------
__device__ __forceinline__ uint32_t smem_u32(const void* p) {
    uint32_t a;
    asm("{ .reg .u64 t; cvta.to.shared.u64 t, %1; cvt.u32.u64 %0, t; }" : "=r"(a) : "l"(p));
    return a;
}
__device__ __forceinline__ bool elect1() {
    uint32_t p;
    asm volatile("{ .reg .pred p; elect.sync _|p, 0xFFFFFFFF; selp.b32 %0, 1, 0, p; }" : "=r"(p));
    return p != 0;
}
__device__ __forceinline__ uint64_t make_desc(uint32_t addr) {
    const uint64_t base = (uint64_t(2) << 61) | (uint64_t(1) << 46) |
                          (uint64_t(64) << 32) | (uint64_t(1) << 16);
    return base | ((addr >> 4) & 0x3FFF);
}
__device__ __forceinline__ void mbar_wait(uint32_t mbar, uint32_t parity) {
    asm volatile(
        "{\n\t.reg .pred P;\n\t"
        "WL%=:\n\t"
        "mbarrier.try_wait.parity.acquire.cta.shared::cta.b64 P, [%0], %1, 0x989680;\n\t"
        "@P bra.uni WD%=;\n\t"
        "bra.uni WL%=;\n\t"
        "WD%=:\n\t}"
        :: "r"(mbar), "r"(parity) : "memory");
}

#if HAS_TCGEN05
__device__ __forceinline__ void mma_ss_f16(uint32_t d, uint64_t ad, uint64_t bd,
                                           uint32_t idesc, bool acc) {
    uint32_t en = acc ? 1u : 0u;
    asm volatile(
        "{\n\t.reg .pred p;\n\tsetp.ne.u32 p, %4, 0;\n\t"
        "tcgen05.mma.cta_group::1.kind::f16 [%0], %1, %2, %3, {%5, %5, %5, %5}, p;\n\t}"
        :: "r"(d), "l"(ad), "l"(bd), "r"(idesc), "r"(en), "r"(0u) : "memory");
}
#define LDTM_X32(r, a) \
    asm volatile( \
        "tcgen05.ld.sync.aligned.32x32b.x32.b32 " \
        "{%0, %1, %2, %3, %4, %5, %6, %7, " \
        " %8, %9, %10, %11, %12, %13, %14, %15, " \
        " %16, %17, %18, %19, %20, %21, %22, %23, " \
        " %24, %25, %26, %27, %28, %29, %30, %31}, [%32];" \
        : "=r"((r)[0]),  "=r"((r)[1]),  "=r"((r)[2]),  "=r"((r)[3]), \
          "=r"((r)[4]),  "=r"((r)[5]),  "=r"((r)[6]),  "=r"((r)[7]), \
          "=r"((r)[8]),  "=r"((r)[9]),  "=r"((r)[10]), "=r"((r)[11]), \
          "=r"((r)[12]), "=r"((r)[13]), "=r"((r)[14]), "=r"((r)[15]), \
          "=r"((r)[16]), "=r"((r)[17]), "=r"((r)[18]), "=r"((r)[19]), \
          "=r"((r)[20]), "=r"((r)[21]), "=r"((r)[22]), "=r"((r)[23]), \
          "=r"((r)[24]), "=r"((r)[25]), "=r"((r)[26]), "=r"((r)[27]), \
          "=r"((r)[28]), "=r"((r)[29]), "=r"((r)[30]), "=r"((r)[31]) \
        : "r"(a))
#endif

// idesc: fp32 accum, bf16 A/B, M=128, N=128
#define IDESC_128 0x08200490u

// base-4 digit reverse of 10-bit index
__device__ __forceinline__ int rc4(int c) {
    return ((c & 3) << 8) | (((c >> 2) & 3) << 6) | (((c >> 4) & 3) << 4) |
           (((c >> 6) & 3) << 2) | ((c >> 8) & 3);
}

// ---------------- token prep: T[layer] -> bf16 padded buffers --------------
__global__ void prep_tokens(const float* __restrict__ lt1,
                            const float* __restrict__ lt2,
                            const int* __restrict__ layer_p)
{
    int i = blockIdx.x * 256 + threadIdx.x;
    if (i >= 144 * CDIM) return;
    int row = i >> 10;
    int layer = layer_p[0];
    float v1 = 0.f, v2 = 0.f;
    if (row < 100) {
        v1 = lt1[layer * 100 * CDIM + i];
        v2 = lt2[layer * 100 * CDIM + i];
    }
    g_T1b[i] = __float2bfloat16(v1);
    g_T2b[i] = __float2bfloat16(v2);
}

// ---------------- weight conversion fp32 -> bf16 ---------------------------
__global__ void conv_w(const float* __restrict__ a, const float* __restrict__ b,
                       const float* __restrict__ c, const float* __restrict__ d)
{
    int i = blockIdx.x * 256 + threadIdx.x;
    if (i >= CDIM * CDIM) return;
    g_W1[i] = __float2bfloat16(a[i]);
    g_W2[i] = __float2bfloat16(b[i]);
    g_W3[i] = __float2bfloat16(c[i]);
    g_W4[i] = __float2bfloat16(d[i]);
}

// ---------------- radix-4 butterfly stages (in-place, swizzled smem) --------
// dir = -1 forward, +1 inverse; table tw holds exp(dir*2*pi*i*t/1024)
__device__ __forceinline__ void fft_stages_r4(float* sre, float* sim,
                                              const float* twr, const float* twi,
                                              int tid, int dir)
{
    #pragma unroll
    for (int s = 1; s <= 5; s++) {
        int Q = 1 << (2 * (s - 1));
        int sh = 10 - 2 * s;
        for (int t = tid; t < 2048; t += 512) {
            int b = t >> 8, j = t & 255;
            int pos = j & (Q - 1);
            int i0 = (b << 10) + ((j >> (2 * (s - 1))) << (2 * s)) + pos;
            int e = pos << sh;
            float w1r = twr[e], w1i = twi[e];
            float w2r = w1r * w1r - w1i * w1i, w2i = 2.f * w1r * w1i;
            float w3r = w2r * w1r - w2i * w1i, w3i = w2r * w1i + w2i * w1r;
            int p0 = SW(i0), p1 = SW(i0 + Q), p2 = SW(i0 + 2 * Q), p3 = SW(i0 + 3 * Q);
            float a0r = sre[p0], a0i = sim[p0];
            float b1r = sre[p1], b1i = sim[p1];
            float b2r = sre[p2], b2i = sim[p2];
            float b3r = sre[p3], b3i = sim[p3];
            float x1r = b1r * w1r - b1i * w1i, x1i = b1r * w1i + b1i * w1r;
            float x2r = b2r * w2r - b2i * w2i, x2i = b2r * w2i + b2i * w2r;
            float x3r = b3r * w3r - b3i * w3i, x3i = b3r * w3i + b3i * w3r;
            float t0r = a0r + x2r, t0i = a0i + x2i;
            float t1r = a0r - x2r, t1i = a0i - x2i;
            float t2r = x1r + x3r, t2i = x1i + x3i;
            float t3r = x1r - x3r, t3i = x1i - x3i;
            sre[p0] = t0r + t2r; sim[p0] = t0i + t2i;
            sre[p2] = t0r - t2r; sim[p2] = t0i - t2i;
            if (dir < 0) {   // forward: y1 = t1 - j*t3, y3 = t1 + j*t3
                sre[p1] = t1r + t3i; sim[p1] = t1i - t3r;
                sre[p3] = t1r - t3i; sim[p3] = t1i + t3r;
            } else {         // inverse: y1 = t1 + j*t3, y3 = t1 - j*t3
                sre[p1] = t1r - t3i; sim[p1] = t1i + t3r;
                sre[p3] = t1r + t3i; sim[p3] = t1i - t3r;
            }
        }
        __syncthreads();
    }
}

// ---------------- forward FFT2 + amp/phase (bf16 out) ----------------------
__global__ void __launch_bounds__(512) fft_fwd(const float* __restrict__ feats)
{
    extern __shared__ float sm[];
    float* sre = sm;               // 8192
    float* sim = sm + 8192;        // 8192
    float* twr = sm + 16384;       // 1024
    float* twi = twr + 1024;       // 1024
    int tid = threadIdx.x;
    int n = blockIdx.x;
    const float* x = feats + (size_t)(n + 1) * 8192;

    for (int t = tid; t < 1024; t += 512) {
        float s_, c_;
        sincospif(-(float)t * (1.0f / 512.0f), &s_, &c_);
        twr[t] = c_; twi[t] = s_;
    }
    // load with base-4 digit-reversed c (swizzled)
    for (int i = tid; i < 8192; i += 512) {
        int b = i >> 10, c = i & 1023;
        int p = SW((b << 10) + rc4(c));
        sre[p] = x[i];
        sim[p] = 0.f;
    }
    __syncthreads();
    fft_stages_r4(sre, sim, twr, twi, tid, -1);

    const float W8R[8] = {1.f, 0.70710678f, 0.f, -0.70710678f, -1.f, -0.70710678f, 0.f, 0.70710678f};
    const float W8I[8] = {0.f, -0.70710678f, -1.f, -0.70710678f, 0.f, 0.70710678f, 1.f, 0.70710678f};
    for (int c = tid; c < 1024; c += 512) {
        float ar[8], ai[8];
        #pragma unroll
        for (int b = 0; b < 8; b++) {
            int p = SW((b << 10) + c);
            ar[b] = sre[p]; ai[b] = sim[p];
        }
        #pragma unroll
        for (int kb = 0; kb < 8; kb++) {
            float orr = 0.f, oii = 0.f;
            #pragma unroll
            for (int b = 0; b < 8; b++) {
                int t8 = (kb * b) & 7;
                orr += ar[b] * W8R[t8] - ai[b] * W8I[t8];
                oii += ar[b] * W8I[t8] + ai[b] * W8R[t8];
            }
            float p2 = orr * orr + oii * oii;
            if (p2 < 1e-5f) p2 = 1e-5f;
            float amp = sqrtf(p2);
            float rr = orr;
            if (rr < 1e-5f && rr > -1e-5f) rr = 1e-5f;
            float ph = atan2f(oii, rr);
            int off = (((n << 3) + kb) << 10) + c;
            g_amb[off] = __float2bfloat16(amp);
            g_phb[off] = __float2bfloat16(ph);
        }
    }
}

// ---------------- tcgen05 bf16 GEMM (256 threads) ---------------------------
// C[M,N] = A * B^T. EPI: 0 = f32 store, 1 = bf16 store, 2 = (+X bf16) -> bf16.
// BIAS: 0 none, 1 per-col fp32, 2 per-row fp32.
struct GB {
    const __nv_bfloat16 *A0, *A1b;
    const __nv_bfloat16 *B0, *B1b;
    const float *bias0, *bias1;
    const __nv_bfloat16 *X0, *X1;
    void *C0, *C1;
};

template<int EPI, int BIAS>
__global__ void __launch_bounds__(256, 2) gemm_tc(GB g, int lda, int ldb, int ldc,
                                                  int ldx, int nk, int nguard)
{
    extern __shared__ char sm_[];
    int tid = threadIdx.x;
    int z = blockIdx.z;
    const __nv_bfloat16* A = z ? g.A1b : g.A0;
    const __nv_bfloat16* B = z ? g.B1b : g.B0;
    const float* bias = z ? g.bias1 : g.bias0;
    const __nv_bfloat16* X = z ? g.X1 : g.X0;
    char* C = (char*)(z ? g.C1 : g.C0);
    int row0 = blockIdx.y << 7, col0 = blockIdx.x << 7;

#if HAS_TCGEN05
    uint32_t sb = smem_u32(sm_);
    uint32_t ta = (sb + 1023u) & ~1023u;       // 1024-aligned tile base
    char* tp = sm_ + (ta - sb);
    uint32_t ctrl = ta + 65536;                // tmem ptr + mbarriers above tiles
    int wid = tid >> 5, lane = tid & 31;

    if (wid == 0) {
        asm volatile("tcgen05.alloc.cta_group::1.sync.aligned.shared::cta.b32 [%0], %1;"
                     :: "r"(ctrl), "r"(128u) : "memory");
        asm volatile("tcgen05.relinquish_alloc_permit.cta_group::1.sync.aligned;");
    }
    if (tid == 0) {
        asm volatile("mbarrier.init.shared.b64 [%0], 1;" :: "r"(ctrl + 8) : "memory");
        asm volatile("mbarrier.init.shared.b64 [%0], 1;" :: "r"(ctrl + 16) : "memory");
    }
    __syncthreads();
    uint32_t tmem;
    asm volatile("ld.shared.b32 %0, [%1];" : "=r"(tmem) : "r"(ctrl));

    const __nv_bfloat16* Ab = A + (size_t)row0 * lda;
    const __nv_bfloat16* Bb = B + (size_t)col0 * ldb;
    const int abase[2] = {0, 16384};
    const int bbase[2] = {32768, 49152};
    int ph[2] = {0, 0};

    for (int c = 0; c < nk; c++) {
        int b = c & 1;
        if (c >= 2) { mbar_wait(ctrl + 8 + b * 8, (uint32_t)ph[b]); ph[b] ^= 1; }
        int k0 = c << 6;
        #pragma unroll
        for (int it = 0; it < 4; it++) {
            int u = tid + (it << 8);
            int row = u >> 3, seg = u & 7;
            uint4 va = *(const uint4*)(Ab + (size_t)row * lda + k0 + (seg << 3));
            uint4 vb = *(const uint4*)(Bb + (size_t)row * ldb + k0 + (seg << 3));
            uint32_t bo = (row << 7) + (seg << 4);
            uint32_t so = bo ^ ((bo >> 3) & 0x70);
            *(uint4*)(tp + abase[b] + so) = va;
            *(uint4*)(tp + bbase[b] + so) = vb;
        }
        asm volatile("fence.proxy.async.shared::cta;" ::: "memory");
        __syncthreads();
        if (wid == 0 && elect1()) {
            uint64_t ad = make_desc(ta + abase[b]);
            uint64_t bd = make_desc(ta + bbase[b]);
            #pragma unroll
            for (int kk = 0; kk < 4; kk++)
                mma_ss_f16(tmem, ad + kk * 2, bd + kk * 2, IDESC_128, (c | kk) != 0);
            asm volatile(
                "tcgen05.commit.cta_group::1.mbarrier::arrive::one.shared::cluster.b64 [%0];"
                :: "r"(ctrl + 8 + b * 8) : "memory");
        }
    }
    mbar_wait(ctrl + 8, (uint32_t)ph[0]);
    mbar_wait(ctrl + 16, (uint32_t)ph[1]);
    asm volatile("tcgen05.fence::after_thread_sync;" ::: "memory");
    __syncthreads();

    // epilogue: two 128-thread half-groups, each handles 64 columns
    int sub = wid & 3, half = wid >> 2;
    int rsub = (sub << 5) + lane;              // row within tile, 0..127
    float* smf = (float*)tp + half * 4224;     // 128 x 33 staging per half
    float biasr = (BIAS == 2) ? bias[row0 + rsub] : 0.f;
    int barid = 1 + half;
    #pragma unroll
    for (int q = 0; q < 2; q++) {
        int cb = (half << 1) + q;              // 32-col block index 0..3
        uint32_t r_[32];
        LDTM_X32(r_, tmem + (cb << 5));
        asm volatile("tcgen05.wait::ld.sync.aligned;" ::: "memory");
        asm volatile("bar.sync %0, 128;" :: "r"(barid) : "memory");
        #pragma unroll
        for (int j = 0; j < 32; j++) smf[rsub * 33 + j] = __uint_as_float(r_[j]) + biasr;
        asm volatile("bar.sync %0, 128;" :: "r"(barid) : "memory");
        #pragma unroll
        for (int i = 0; i < 32; i++) {
            int idx = rsub + (i << 7);
            int orow = idx >> 5, ocol = idx & 31;
            int cc = col0 + (cb << 5) + ocol;
            if (cc < nguard) {
                float v = smf[orow * 33 + ocol];
                if (BIAS == 1) v += bias[cc];
                size_t off = (size_t)(row0 + orow) * ldc + cc;
                if (EPI == 0) ((float*)C)[off] = v;
                else if (EPI == 1) ((__nv_bfloat16*)C)[off] = __float2bfloat16(v);
                else {
                    v += __bfloat162float(X[(size_t)(row0 + orow) * ldx + cc]);
                    ((__nv_bfloat16*)C)[off] = __float2bfloat16(v);
                }
            }
        }
    }
    __syncthreads();
    if (wid == 0) {
        asm volatile("tcgen05.dealloc.cta_group::1.sync.aligned.b32 %0, %1;"
                     :: "r"(tmem), "r"(128u));
    }
#else
    // Scalar fallback — only runs if the arch-specific cubin is unavailable.
    (void)sm_;
    if (tid < 128) {
        int row = row0 + tid;
        int K = nk << 6;
        for (int cc = 0; cc < 128; cc++) {
            int c = col0 + cc;
            if (c >= nguard) continue;
            float acc = 0.f;
            for (int k = 0; k < K; k++)
                acc += __bfloat162float(A[(size_t)row * lda + k]) *
                       __bfloat162float(B[(size_t)c * ldb + k]);
            if (BIAS == 1) acc += bias[c];
            if (BIAS == 2) acc += bias[row];
            size_t off = (size_t)row * ldc + c;
            if (EPI == 0) ((float*)C)[off] = acc;
            else if (EPI == 1) ((__nv_bfloat16*)C)[off] = __float2bfloat16(acc);
            else {
                acc += __bfloat162float(X[(size_t)row * ldx + c]);
                ((__nv_bfloat16*)C)[off] = __float2bfloat16(acc);
            }
        }
    }
#endif
}

// ---------------- softmax (both branches in one launch), bf16 out ----------
__global__ void __launch_bounds__(256) softmax_k(const float* __restrict__ A1,
                                                 const float* __restrict__ A2,
                                                 __nv_bfloat16* __restrict__ S1,
                                                 __nv_bfloat16* __restrict__ S2)
{
    int gw = (blockIdx.x * 256 + threadIdx.x) >> 5;
    int lane = threadIdx.x & 31;
    if (gw >= MROWS) return;
    bool inorm = (blockIdx.y != 0);
    const float* a = (inorm ? A2 : A1) + (size_t)gw * KP;
    __nv_bfloat16* o = (inorm ? S2 : S1) + (size_t)gw * KP;
    float v[4]; bool val[4];
    #pragma unroll
    for (int q = 0; q < 4; q++) {
        int idx = lane + 32 * q;
        val[q] = idx < 100;
        v[q] = val[q] ? a[idx] : 0.f;
    }
    if (inorm) {
        float s = v[0] + v[1] + v[2] + v[3];
        #pragma unroll
        for (int off = 16; off > 0; off >>= 1) s += __shfl_xor_sync(0xffffffffu, s, off);
        float mu = s * 0.01f;
        float s2 = 0.f;
        #pragma unroll
        for (int q = 0; q < 4; q++) if (val[q]) { float d = v[q] - mu; s2 += d * d; }
        #pragma unroll
        for (int off = 16; off > 0; off >>= 1) s2 += __shfl_xor_sync(0xffffffffu, s2, off);
        float inv = rsqrtf(s2 * 0.01f + 1e-5f);
        #pragma unroll
        for (int q = 0; q < 4; q++) v[q] = (v[q] - mu) * inv;
    }
    float m = -1e30f;
    #pragma unroll
    for (int q = 0; q < 4; q++) if (val[q]) m = fmaxf(m, v[q] * 0.03125f);
    #pragma unroll
    for (int off = 16; off > 0; off >>= 1) m = fmaxf(m, __shfl_xor_sync(0xffffffffu, m, off));
    float e[4]; float se = 0.f;
    #pragma unroll
    for (int q = 0; q < 4; q++) {
        e[q] = val[q] ? expf(v[q] * 0.03125f - m) : 0.f;
        se += e[q];
    }
    #pragma unroll
    for (int off = 16; off > 0; off >>= 1) se += __shfl_xor_sync(0xffffffffu, se, off);
    float rinv = 1.f / se;
    #pragma unroll
    for (int q = 0; q < 4; q++) {
        int idx = lane + 32 * q;
        if (idx >= 1 && idx < 100) o[idx - 1] = __float2bfloat16(e[q] * rinv);
        else if (idx >= 100) o[idx - 1] = __float2bfloat16(0.f);
        else o[127] = __float2bfloat16(0.f);   // idx == 0
    }
}

// ---------------- inverse: z-build + ifft_b(8) + Hermitian irfft -> out ----
__global__ void __launch_bounds__(512) fft_inv(const float* __restrict__ feats,
                                               const float* __restrict__ scale_p,
                                               float* __restrict__ out)
{
    extern __shared__ float sm[];
    float* sre = sm;               // 8192
    float* sim = sm + 8192;        // 8192
    float* twr = sm + 16384;       // 1024
    float* twi = twr + 1024;       // 1024
    int tid = threadIdx.x;
    int n = blockIdx.x;

    for (int t = tid; t < 1024; t += 512) {
        float s_, c_;
        sincospif((float)t * (1.0f / 512.0f), &s_, &c_);
        twr[t] = c_; twi[t] = s_;
    }
    __syncthreads();

    const float W8R[8] = {1.f, 0.70710678f, 0.f, -0.70710678f, -1.f, -0.70710678f, 0.f, 0.70710678f};
    const float W8I[8] = {0.f, -0.70710678f, -1.f, -0.70710678f, 0.f, 0.70710678f, 1.f, 0.70710678f};

    // fused: z = (cos(dp)*da, sin(dp)*da); inverse 8-pt DFT along b;
    // Hermitian extension with base-4 digit-reversed scatter (swizzled)
    for (int c = tid; c < 513; c += 512) {
        float zr_[8], zi_[8];
        #pragma unroll
        for (int b = 0; b < 8; b++) {
            size_t off = (size_t)((n << 3) + b) * NZ + c;
            float phv = __bfloat162float(g_dpb[off]);
            float amv = __bfloat162float(g_dab[off]);
            float s_, c_;
            sincosf(phv, &s_, &c_);
            zr_[b] = c_ * amv;
            zi_[b] = s_ * amv;
        }
        int rcp = rc4(c);
        int rcm = rc4((1024 - c) & 1023);
        bool mir = (c != 0) && (c != 512);
        #pragma unroll
        for (int b = 0; b < 8; b++) {
            float orr = 0.f, oii = 0.f;
            #pragma unroll
            for (int kb = 0; kb < 8; kb++) {
                int t8 = (kb * b) & 7;
                float wr = W8R[t8], wi = -W8I[t8];   // conjugate = inverse
                orr += zr_[kb] * wr - zi_[kb] * wi;
                oii += zr_[kb] * wi + zi_[kb] * wr;
            }
            int p1 = SW((b << 10) + rcp);
            sre[p1] = orr; sim[p1] = oii;
            if (mir) {
                int p2 = SW((b << 10) + rcm);
                sre[p2] = orr; sim[p2] = -oii;
            }
        }
    }
    __syncthreads();
    fft_stages_r4(sre, sim, twr, twi, tid, +1);

    float sc = scale_p[0];
    for (int i = tid; i < 8192; i += 512) {
        int b = i >> 10, c = i & 1023;
        float d = sre[SW((b << 10) + c)] * (1.0f / 4096.0f);
        size_t off = ((size_t)(n + 1) * 8 + b) * 1024 + c;
        out[off] = feats[off] + d * sc;
    }
}

__global__ void cls_copy(const float* __restrict__ feats, float* __restrict__ out)
{
    int i = blockIdx.x * 256 + threadIdx.x;
    if (i < 8192) out[i] = feats[i];
}

// ---------------- host ------------------------------------------------------
static void* symaddr(const void* s)
{
    void* p = nullptr;
    cudaGetSymbolAddress(&p, s);
    return p;
}

extern "C" void kernel_launch(void* const* d_in, const int* in_sizes, int n_in,
                              void* d_out, int out_size)
{
    (void)in_sizes; (void)n_in; (void)out_size;
    const float* feats  = (const float*)d_in[0];
    const float* lt1    = (const float*)d_in[1];
    const float* lt2    = (const float*)d_in[2];
    const float* w_t2f  = (const float*)d_in[3];
    const float* b_t2f  = (const float*)d_in[4];
    const float* w_df   = (const float*)d_in[5];
    const float* b_df   = (const float*)d_in[6];
    const float* w_t2f2 = (const float*)d_in[7];
    const float* b_t2f2 = (const float*)d_in[8];
    const float* w_df2  = (const float*)d_in[9];
    const float* b_df2  = (const float*)d_in[10];
    const float* scale  = (const float*)d_in[11];
    const int*   layer  = (const int*)d_in[12];
    float* out = (float*)d_out;

    __nv_bfloat16* phb = (__nv_bfloat16*)symaddr(g_phb);
    __nv_bfloat16* amb = (__nv_bfloat16*)symaddr(g_amb);
    __nv_bfloat16* T1b = (__nv_bfloat16*)symaddr(g_T1b);
    __nv_bfloat16* T2b = (__nv_bfloat16*)symaddr(g_T2b);
    float* A1 = (float*)symaddr(g_A1);
    float* A2 = (float*)symaddr(g_A2);
    __nv_bfloat16* S1  = (__nv_bfloat16*)symaddr(g_S1);
    __nv_bfloat16* S2  = (__nv_bfloat16*)symaddr(g_S2);
    __nv_bfloat16* vT1 = (__nv_bfloat16*)symaddr(g_vT1);
    __nv_bfloat16* vT2 = (__nv_bfloat16*)symaddr(g_vT2);
    __nv_bfloat16* P1  = (__nv_bfloat16*)symaddr(g_P1);
    __nv_bfloat16* P2  = (__nv_bfloat16*)symaddr(g_P2);
    __nv_bfloat16* W1  = (__nv_bfloat16*)symaddr(g_W1);
    __nv_bfloat16* W2  = (__nv_bfloat16*)symaddr(g_W2);
    __nv_bfloat16* W3  = (__nv_bfloat16*)symaddr(g_W3);
    __nv_bfloat16* W4  = (__nv_bfloat16*)symaddr(g_W4);
    __nv_bfloat16* dpb = (__nv_bfloat16*)symaddr(g_dpb);
    __nv_bfloat16* dab = (__nv_bfloat16*)symaddr(g_dab);

    const int FFT_SMEM  = (8192 * 2 + 2048) * 4;   // 73728
    const int GEMM_SMEM = 66624;
    cudaFuncSetAttribute(fft_fwd, cudaFuncAttributeMaxDynamicSharedMemorySize, FFT_SMEM);
    cudaFuncSetAttribute(fft_inv, cudaFuncAttributeMaxDynamicSharedMemorySize, FFT_SMEM);
    cudaFuncSetAttribute(gemm_tc<0,0>, cudaFuncAttributeMaxDynamicSharedMemorySize, GEMM_SMEM);
    cudaFuncSetAttribute(gemm_tc<1,2>, cudaFuncAttributeMaxDynamicSharedMemorySize, GEMM_SMEM);
    cudaFuncSetAttribute(gemm_tc<2,0>, cudaFuncAttributeMaxDynamicSharedMemorySize, GEMM_SMEM);
    cudaFuncSetAttribute(gemm_tc<1,1>, cudaFuncAttributeMaxDynamicSharedMemorySize, GEMM_SMEM);

    // 1) tokens (bf16, padded) + weight conversion
    prep_tokens<<<(144 * CDIM + 255) / 256, 256>>>(lt1, lt2, layer);
    conv_w<<<(CDIM * CDIM + 255) / 256, 256>>>(w_t2f, w_t2f2, w_df, w_df2);

    // 2) FFT2 + amp/phase (bf16)
    fft_fwd<<<1024, 512, FFT_SMEM>>>(feats);

    // 3) attn = X @ T^T  -> fp32 [8192 x 128]
    {
        GB g = { phb, amb, T1b, T2b, nullptr, nullptr, nullptr, nullptr, A1, A2 };
        gemm_tc<0,0><<<dim3(1, 64, 2), 256, GEMM_SMEM>>>(g, CDIM, CDIM, KP, 0, 16, KP);
    }

    // 4) softmax (both branches) -> bf16 S, shifted + zero padded to 128
    softmax_k<<<dim3(1024, 2), 256>>>(A1, A2, S1, S2);

    // 5) vT[c][j] = sum_k W[c][k]*T[1+j][k] + b[c]  -> bf16 [1024 x 128]
    {
        GB g = { W1, W2, T1b + CDIM, T2b + CDIM, b_t2f, b_t2f2, nullptr, nullptr, vT1, vT2 };
        gemm_tc<1,2><<<dim3(1, 8, 2), 256, GEMM_SMEM>>>(g, CDIM, CDIM, KP, 0, 16, KP);
    }

    // 6) P = S @ vT^T + X  -> bf16 [8192 x 1024]
    {
        GB g = { S1, S2, vT1, vT2, nullptr, nullptr, phb, amb, P1, P2 };
        gemm_tc<2,0><<<dim3(8, 64, 2), 256, GEMM_SMEM>>>(g, KP, KP, CDIM, CDIM, 2, CDIM);
    }

    // 7) d = P @ Wdf^T + b  -> bf16 [8192 x 513]
    {
        GB g = { P1, P2, W3, W4, b_df, b_df2, nullptr, nullptr, dpb, dab };
        gemm_tc<1,1><<<dim3(5, 64, 2), 256, GEMM_SMEM>>>(g, CDIM, CDIM, NZ, 0, 16, NZ);
    }

    // 8) z-build + irfft2 + residual add (fused)
    fft_inv<<<1024, 512, FFT_SMEM>>>(feats, scale, out);

    // 9) cls row passthrough
    cls_copy<<<32, 256>>>(feats, out);
}

// round 8
// speedup vs baseline: 4.5216x; 1.0380x over previous
#include <cuda_runtime.h>
#include <cuda_bf16.h>
#include <math.h>
#include <stdint.h>

#if defined(__CUDA_ARCH__) && (defined(__CUDA_ARCH_SPECIFIC__) || defined(__CUDA_ARCH_FAMILY_SPECIFIC__))
#define HAS_TCGEN05 1
#else
#define HAS_TCGEN05 0
#endif

#define MROWS 8192      // 1024 * 8 rows
#define CDIM  1024
#define KP    128       // padded token/attention dim
#define NZ    513       // kept spectrum columns

// smem bank swizzle for FFT arrays
#define SW(i) ((i) ^ (((i) >> 5) & 31))

// ---------------- scratch (device globals; no allocation allowed) ----------
__device__ __nv_bfloat16 g_phb[MROWS*CDIM];
__device__ __nv_bfloat16 g_amb[MROWS*CDIM];
__device__ __nv_bfloat16 g_T1b[144*CDIM];
__device__ __nv_bfloat16 g_T2b[144*CDIM];
__device__ __nv_bfloat16 g_S1[MROWS*KP];
__device__ __nv_bfloat16 g_S2[MROWS*KP];
__device__ __nv_bfloat16 g_vT1[CDIM*KP];
__device__ __nv_bfloat16 g_vT2[CDIM*KP];
__device__ __nv_bfloat16 g_P1[MROWS*CDIM];
__device__ __nv_bfloat16 g_P2[MROWS*CDIM];
__device__ __nv_bfloat16 g_W1[CDIM*CDIM]; // w_t2f
__device__ __nv_bfloat16 g_W2[CDIM*CDIM]; // w_t2f2
__device__ __nv_bfloat16 g_W3[CDIM*CDIM]; // w_df
__device__ __nv_bfloat16 g_W4[CDIM*CDIM]; // w_df2
__device__ __nv_bfloat16 g_dpb[MROWS*NZ];
__device__ __nv_bfloat16 g_dab[MROWS*NZ];

// ---------------- PTX helpers ----------------------------------------------
__device__ __forceinline__ uint32_t smem_u32(const void* p) {
    uint32_t a;
    asm("{ .reg .u64 t; cvta.to.shared.u64 t, %1; cvt.u32.u64 %0, t; }" : "=r"(a) : "l"(p));
    return a;
}
__device__ __forceinline__ bool elect1() {
    uint32_t p;
    asm volatile("{ .reg .pred p; elect.sync _|p, 0xFFFFFFFF; selp.b32 %0, 1, 0, p; }" : "=r"(p));
    return p != 0;
}
__device__ __forceinline__ uint64_t make_desc(uint32_t addr) {
    const uint64_t base = (uint64_t(2) << 61) | (uint64_t(1) << 46) |
                          (uint64_t(64) << 32) | (uint64_t(1) << 16);
    return base | ((addr >> 4) & 0x3FFF);
}
__device__ __forceinline__ void mbar_wait(uint32_t mbar, uint32_t parity) {
    asm volatile(
        "{\n\t.reg .pred P;\n\t"
        "WL%=:\n\t"
        "mbarrier.try_wait.parity.acquire.cta.shared::cta.b64 P, [%0], %1, 0x989680;\n\t"
        "@P bra.uni WD%=;\n\t"
        "bra.uni WL%=;\n\t"
        "WD%=:\n\t}"
        :: "r"(mbar), "r"(parity) : "memory");
}

#if HAS_TCGEN05
__device__ __forceinline__ void mma_ss_f16(uint32_t d, uint64_t ad, uint64_t bd,
                                           uint32_t idesc, bool acc) {
    uint32_t en = acc ? 1u : 0u;
    asm volatile(
        "{\n\t.reg .pred p;\n\tsetp.ne.u32 p, %4, 0;\n\t"
        "tcgen05.mma.cta_group::1.kind::f16 [%0], %1, %2, %3, {%5, %5, %5, %5}, p;\n\t}"
        :: "r"(d), "l"(ad), "l"(bd), "r"(idesc), "r"(en), "r"(0u) : "memory");
}
#define LDTM_X32(r, a) \
    asm volatile( \
        "tcgen05.ld.sync.aligned.32x32b.x32.b32 " \
        "{%0, %1, %2, %3, %4, %5, %6, %7, " \
        " %8, %9, %10, %11, %12, %13, %14, %15, " \
        " %16, %17, %18, %19, %20, %21, %22, %23, " \
        " %24, %25, %26, %27, %28, %29, %30, %31}, [%32];" \
        : "=r"((r)[0]),  "=r"((r)[1]),  "=r"((r)[2]),  "=r"((r)[3]), \
          "=r"((r)[4]),  "=r"((r)[5]),  "=r"((r)[6]),  "=r"((r)[7]), \
          "=r"((r)[8]),  "=r"((r)[9]),  "=r"((r)[10]), "=r"((r)[11]), \
          "=r"((r)[12]), "=r"((r)[13]), "=r"((r)[14]), "=r"((r)[15]), \
          "=r"((r)[16]), "=r"((r)[17]), "=r"((r)[18]), "=r"((r)[19]), \
          "=r"((r)[20]), "=r"((r)[21]), "=r"((r)[22]), "=r"((r)[23]), \
          "=r"((r)[24]), "=r"((r)[25]), "=r"((r)[26]), "=r"((r)[27]), \
          "=r"((r)[28]), "=r"((r)[29]), "=r"((r)[30]), "=r"((r)[31]) \
        : "r"(a))
#endif

// idesc: fp32 accum, bf16 A/B, M=128, N=128
#define IDESC_128 0x08200490u

// base-4 digit reverse of 10-bit index
__device__ __forceinline__ int rc4(int c) {
    return ((c & 3) << 8) | (((c >> 2) & 3) << 6) | (((c >> 4) & 3) << 4) |
           (((c >> 6) & 3) << 2) | ((c >> 8) & 3);
}

// fast atan2 (~2e-5 rad abs err) — delta-path only, error suppressed x1e-3
__device__ __forceinline__ float fast_atan2(float y, float x) {
    float ax = fabsf(x), ay = fabsf(y);
    float mx = fmaxf(ax, ay), mn = fminf(ax, ay);
    float a = __fdividef(mn, mx);
    float s = a * a;
    float r = a * (0.99997726f + s * (-0.33262347f + s * (0.19354346f +
              s * (-0.11643287f + s * (0.05265332f - s * 0.01172120f)))));
    if (ay > ax) r = 1.57079637f - r;
    if (x < 0.f) r = 3.14159274f - r;
    return copysignf(r, y);
}

// ---------------- token prep: T[layer] -> bf16 padded buffers --------------
__global__ void prep_tokens(const float* __restrict__ lt1,
                            const float* __restrict__ lt2,
                            const int* __restrict__ layer_p)
{
    int i = blockIdx.x * 256 + threadIdx.x;
    if (i >= 144 * CDIM) return;
    int row = i >> 10;
    int layer = layer_p[0];
    float v1 = 0.f, v2 = 0.f;
    if (row < 100) {
        v1 = lt1[layer * 100 * CDIM + i];
        v2 = lt2[layer * 100 * CDIM + i];
    }
    g_T1b[i] = __float2bfloat16(v1);
    g_T2b[i] = __float2bfloat16(v2);
}

// ---------------- weight conversion fp32 -> bf16 ---------------------------
__global__ void conv_w(const float* __restrict__ a, const float* __restrict__ b,
                       const float* __restrict__ c, const float* __restrict__ d)
{
    int i = blockIdx.x * 256 + threadIdx.x;
    if (i >= CDIM * CDIM) return;
    g_W1[i] = __float2bfloat16(a[i]);
    g_W2[i] = __float2bfloat16(b[i]);
    g_W3[i] = __float2bfloat16(c[i]);
    g_W4[i] = __float2bfloat16(d[i]);
}

// ---------------- radix-4 butterfly stages (in-place, swizzled smem) --------
__device__ __forceinline__ void fft_stages_r4(float* sre, float* sim,
                                              const float* twr, const float* twi,
                                              int tid, int dir)
{
    #pragma unroll
    for (int s = 1; s <= 5; s++) {
        int Q = 1 << (2 * (s - 1));
        int sh = 10 - 2 * s;
        for (int t = tid; t < 2048; t += 512) {
            int b = t >> 8, j = t & 255;
            int pos = j & (Q - 1);
            int i0 = (b << 10) + ((j >> (2 * (s - 1))) << (2 * s)) + pos;
            int e = pos << sh;
            float w1r = twr[e], w1i = twi[e];
            float w2r = w1r * w1r - w1i * w1i, w2i = 2.f * w1r * w1i;
            float w3r = w2r * w1r - w2i * w1i, w3i = w2r * w1i + w2i * w1r;
            int p0 = SW(i0), p1 = SW(i0 + Q), p2 = SW(i0 + 2 * Q), p3 = SW(i0 + 3 * Q);
            float a0r = sre[p0], a0i = sim[p0];
            float b1r = sre[p1], b1i = sim[p1];
            float b2r = sre[p2], b2i = sim[p2];
            float b3r = sre[p3], b3i = sim[p3];
            float x1r = b1r * w1r - b1i * w1i, x1i = b1r * w1i + b1i * w1r;
            float x2r = b2r * w2r - b2i * w2i, x2i = b2r * w2i + b2i * w2r;
            float x3r = b3r * w3r - b3i * w3i, x3i = b3r * w3i + b3i * w3r;
            float t0r = a0r + x2r, t0i = a0i + x2i;
            float t1r = a0r - x2r, t1i = a0i - x2i;
            float t2r = x1r + x3r, t2i = x1i + x3i;
            float t3r = x1r - x3r, t3i = x1i - x3i;
            sre[p0] = t0r + t2r; sim[p0] = t0i + t2i;
            sre[p2] = t0r - t2r; sim[p2] = t0i - t2i;
            if (dir < 0) {
                sre[p1] = t1r + t3i; sim[p1] = t1i - t3r;
                sre[p3] = t1r - t3i; sim[p3] = t1i + t3r;
            } else {
                sre[p1] = t1r - t3i; sim[p1] = t1i + t3r;
                sre[p3] = t1r + t3i; sim[p3] = t1i - t3r;
            }
        }
        __syncthreads();
    }
}

// ---------------- forward FFT2 + amp/phase (bf16 out) ----------------------
__global__ void __launch_bounds__(512) fft_fwd(const float* __restrict__ feats)
{
    extern __shared__ float sm[];
    float* sre = sm;               // 8192
    float* sim = sm + 8192;        // 8192
    float* twr = sm + 16384;       // 1024
    float* twi = twr + 1024;       // 1024
    int tid = threadIdx.x;
    int n = blockIdx.x;
    const float* x = feats + (size_t)(n + 1) * 8192;

    for (int t = tid; t < 1024; t += 512) {
        float s_, c_;
        __sincosf((float)t * -6.1359233e-3f, &s_, &c_);   // -2*pi/1024
        twr[t] = c_; twi[t] = s_;
    }
    for (int i = tid; i < 8192; i += 512) {
        int b = i >> 10, c = i & 1023;
        int p = SW((b << 10) + rc4(c));
        sre[p] = x[i];
        sim[p] = 0.f;
    }
    __syncthreads();
    fft_stages_r4(sre, sim, twr, twi, tid, -1);

    const float W8R[8] = {1.f, 0.70710678f, 0.f, -0.70710678f, -1.f, -0.70710678f, 0.f, 0.70710678f};
    const float W8I[8] = {0.f, -0.70710678f, -1.f, -0.70710678f, 0.f, 0.70710678f, 1.f, 0.70710678f};
    for (int c = tid; c < 1024; c += 512) {
        float ar[8], ai[8];
        #pragma unroll
        for (int b = 0; b < 8; b++) {
            int p = SW((b << 10) + c);
            ar[b] = sre[p]; ai[b] = sim[p];
        }
        #pragma unroll
        for (int kb = 0; kb < 8; kb++) {
            float orr = 0.f, oii = 0.f;
            #pragma unroll
            for (int b = 0; b < 8; b++) {
                int t8 = (kb * b) & 7;
                orr += ar[b] * W8R[t8] - ai[b] * W8I[t8];
                oii += ar[b] * W8I[t8] + ai[b] * W8R[t8];
            }
            float p2 = orr * orr + oii * oii;
            if (p2 < 1e-5f) p2 = 1e-5f;
            float amp = sqrtf(p2);
            float rr = orr;
            if (rr < 1e-5f && rr > -1e-5f) rr = 1e-5f;
            float ph = fast_atan2(oii, rr);
            int off = (((n << 3) + kb) << 10) + c;
            g_amb[off] = __float2bfloat16(amp);
            g_phb[off] = __float2bfloat16(ph);
        }
    }
}

// ---------------- tcgen05 bf16 GEMM (256 threads) ---------------------------
// C[M,N] = A * B^T. EPI: 0 = f32 store, 1 = bf16 store, 2 = (+X bf16) -> bf16,
// 3 = fused row softmax (attn path; tile = full padded row).
// BIAS: 0 none, 1 per-col fp32, 2 per-row fp32.
struct GB {
    const __nv_bfloat16 *A0, *A1b;
    const __nv_bfloat16 *B0, *B1b;
    const float *bias0, *bias1;
    const __nv_bfloat16 *X0, *X1;
    void *C0, *C1;
};

#define CTRL_OFF 66560   // above 64KB tiles / 66KB softmax staging

template<int EPI, int BIAS>
__global__ void __launch_bounds__(256, 2) gemm_tc(GB g, int lda, int ldb, int ldc,
                                                  int ldx, int nk, int nguard)
{
    extern __shared__ char sm_[];
    int tid = threadIdx.x;
    int z = blockIdx.z;
    const __nv_bfloat16* A = z ? g.A1b : g.A0;
    const __nv_bfloat16* B = z ? g.B1b : g.B0;
    const float* bias = z ? g.bias1 : g.bias0;
    const __nv_bfloat16* X = z ? g.X1 : g.X0;
    char* C = (char*)(z ? g.C1 : g.C0);
    int row0 = blockIdx.y << 7, col0 = blockIdx.x << 7;

#if HAS_TCGEN05
    uint32_t sb = smem_u32(sm_);
    uint32_t ta = (sb + 1023u) & ~1023u;       // 1024-aligned tile base
    char* tp = sm_ + (ta - sb);
    uint32_t ctrl = ta + CTRL_OFF;
    int wid = tid >> 5, lane = tid & 31;

    if (wid == 0) {
        asm volatile("tcgen05.alloc.cta_group::1.sync.aligned.shared::cta.b32 [%0], %1;"
                     :: "r"(ctrl), "r"(128u) : "memory");
        asm volatile("tcgen05.relinquish_alloc_permit.cta_group::1.sync.aligned;");
    }
    if (tid == 0) {
        asm volatile("mbarrier.init.shared.b64 [%0], 1;" :: "r"(ctrl + 8) : "memory");
        asm volatile("mbarrier.init.shared.b64 [%0], 1;" :: "r"(ctrl + 16) : "memory");
    }
    __syncthreads();
    uint32_t tmem;
    asm volatile("ld.shared.b32 %0, [%1];" : "=r"(tmem) : "r"(ctrl));

    const __nv_bfloat16* Ab = A + (size_t)row0 * lda;
    const __nv_bfloat16* Bb = B + (size_t)col0 * ldb;
    const int abase[2] = {0, 16384};
    const int bbase[2] = {32768, 49152};
    int ph[2] = {0, 0};

    for (int c = 0; c < nk; c++) {
        int b = c & 1;
        if (c >= 2) { mbar_wait(ctrl + 8 + b * 8, (uint32_t)ph[b]); ph[b] ^= 1; }
        int k0 = c << 6;
        #pragma unroll
        for (int it = 0; it < 4; it++) {
            int u = tid + (it << 8);
            int row = u >> 3, seg = u & 7;
            uint4 va = *(const uint4*)(Ab + (size_t)row * lda + k0 + (seg << 3));
            uint4 vb = *(const uint4*)(Bb + (size_t)row * ldb + k0 + (seg << 3));
            uint32_t bo = (row << 7) + (seg << 4);
            uint32_t so = bo ^ ((bo >> 3) & 0x70);
            *(uint4*)(tp + abase[b] + so) = va;
            *(uint4*)(tp + bbase[b] + so) = vb;
        }
        asm volatile("fence.proxy.async.shared::cta;" ::: "memory");
        __syncthreads();
        if (wid == 0 && elect1()) {
            uint64_t ad = make_desc(ta + abase[b]);
            uint64_t bd = make_desc(ta + bbase[b]);
            #pragma unroll
            for (int kk = 0; kk < 4; kk++)
                mma_ss_f16(tmem, ad + kk * 2, bd + kk * 2, IDESC_128, (c | kk) != 0);
            asm volatile(
                "tcgen05.commit.cta_group::1.mbarrier::arrive::one.shared::cluster.b64 [%0];"
                :: "r"(ctrl + 8 + b * 8) : "memory");
        }
    }
    mbar_wait(ctrl + 8, (uint32_t)ph[0]);
    mbar_wait(ctrl + 16, (uint32_t)ph[1]);
    asm volatile("tcgen05.fence::after_thread_sync;" ::: "memory");
    __syncthreads();

    int sub = wid & 3, half = wid >> 2;
    int rsub = (sub << 5) + lane;              // row within tile, 0..127

    if (EPI == 3) {
        // ---- fused softmax epilogue: stage full 128x128 tile (stride 129)
        float* smf = (float*)tp;
        #pragma unroll
        for (int q = 0; q < 2; q++) {
            int cb = (half << 1) + q;
            uint32_t r_[32];
            LDTM_X32(r_, tmem + (cb << 5));
            asm volatile("tcgen05.wait::ld.sync.aligned;" ::: "memory");
            #pragma unroll
            for (int j = 0; j < 32; j++)
                smf[rsub * 129 + (cb << 5) + j] = __uint_as_float(r_[j]);
        }
        __syncthreads();
        bool inorm = (z != 0);
        __nv_bfloat16* Srow = (__nv_bfloat16*)C;
        for (int r = wid; r < 128; r += 8) {
            const float* a = smf + r * 129;
            float v[4]; bool val[4];
            #pragma unroll
            for (int q = 0; q < 4; q++) {
                int idx = lane + 32 * q;
                val[q] = idx < 100;
                v[q] = val[q] ? a[idx] : 0.f;
            }
            if (inorm) {
                float s = v[0] + v[1] + v[2] + v[3];
                #pragma unroll
                for (int off = 16; off > 0; off >>= 1) s += __shfl_xor_sync(0xffffffffu, s, off);
                float mu = s * 0.01f;
                float s2 = 0.f;
                #pragma unroll
                for (int q = 0; q < 4; q++) if (val[q]) { float d = v[q] - mu; s2 += d * d; }
                #pragma unroll
                for (int off = 16; off > 0; off >>= 1) s2 += __shfl_xor_sync(0xffffffffu, s2, off);
                float inv = rsqrtf(s2 * 0.01f + 1e-5f);
                #pragma unroll
                for (int q = 0; q < 4; q++) v[q] = (v[q] - mu) * inv;
            }
            float m = -1e30f;
            #pragma unroll
            for (int q = 0; q < 4; q++) if (val[q]) m = fmaxf(m, v[q] * 0.03125f);
            #pragma unroll
            for (int off = 16; off > 0; off >>= 1) m = fmaxf(m, __shfl_xor_sync(0xffffffffu, m, off));
            float e[4]; float se = 0.f;
            #pragma unroll
            for (int q = 0; q < 4; q++) {
                e[q] = val[q] ? __expf(v[q] * 0.03125f - m) : 0.f;
                se += e[q];
            }
            #pragma unroll
            for (int off = 16; off > 0; off >>= 1) se += __shfl_xor_sync(0xffffffffu, se, off);
            float rinv = __fdividef(1.f, se);
            __nv_bfloat16* o = Srow + (size_t)(row0 + r) * KP;
            #pragma unroll
            for (int q = 0; q < 4; q++) {
                int idx = lane + 32 * q;
                if (idx >= 1 && idx < 100) o[idx - 1] = __float2bfloat16(e[q] * rinv);
                else if (idx >= 100) o[idx - 1] = __float2bfloat16(0.f);
                else o[127] = __float2bfloat16(0.f);
            }
        }
    } else {
        // ---- standard epilogue: two 128-thread half-groups, 64 cols each
        float* smf = (float*)tp + half * 4224;     // 128 x 33 staging per half
        float biasr = (BIAS == 2) ? bias[row0 + rsub] : 0.f;
        int barid = 1 + half;
        #pragma unroll
        for (int q = 0; q < 2; q++) {
            int cb = (half << 1) + q;
            uint32_t r_[32];
            LDTM_X32(r_, tmem + (cb << 5));
            asm volatile("tcgen05.wait::ld.sync.aligned;" ::: "memory");
            asm volatile("bar.sync %0, 128;" :: "r"(barid) : "memory");
            #pragma unroll
            for (int j = 0; j < 32; j++) smf[rsub * 33 + j] = __uint_as_float(r_[j]) + biasr;
            asm volatile("bar.sync %0, 128;" :: "r"(barid) : "memory");
            #pragma unroll
            for (int i = 0; i < 32; i++) {
                int idx = rsub + (i << 7);
                int orow = idx >> 5, ocol = idx & 31;
                int cc = col0 + (cb << 5) + ocol;
                if (cc < nguard) {
                    float v = smf[orow * 33 + ocol];
                    if (BIAS == 1) v += bias[cc];
                    size_t off = (size_t)(row0 + orow) * ldc + cc;
                    if (EPI == 0) ((float*)C)[off] = v;
                    else if (EPI == 1) ((__nv_bfloat16*)C)[off] = __float2bfloat16(v);
                    else {
                        v += __bfloat162float(X[(size_t)(row0 + orow) * ldx + cc]);
                        ((__nv_bfloat16*)C)[off] = __float2bfloat16(v);
                    }
                }
            }
        }
    }
    __syncthreads();
    if (wid == 0) {
        asm volatile("tcgen05.dealloc.cta_group::1.sync.aligned.b32 %0, %1;"
                     :: "r"(tmem), "r"(128u));
    }
#else
    // Scalar fallback — only runs if the arch-specific cubin is unavailable.
    (void)sm_;
    if (tid < 128) {
        int row = row0 + tid;
        int K = nk << 6;
        float acc_row[128];
        for (int cc = 0; cc < 128; cc++) {
            int c = col0 + cc;
            float acc = 0.f;
            if (c < nguard || EPI == 3) {
                for (int k = 0; k < K; k++)
                    acc += __bfloat162float(A[(size_t)row * lda + k]) *
                           __bfloat162float(B[(size_t)c * ldb + k]);
            }
            acc_row[cc] = acc;
            if (EPI != 3 && c < nguard) {
                if (BIAS == 1) acc += bias[c];
                if (BIAS == 2) acc += bias[row];
                size_t off = (size_t)row * ldc + c;
                if (EPI == 0) ((float*)C)[off] = acc;
                else if (EPI == 1) ((__nv_bfloat16*)C)[off] = __float2bfloat16(acc);
                else {
                    acc += __bfloat162float(X[(size_t)row * ldx + c]);
                    ((__nv_bfloat16*)C)[off] = __float2bfloat16(acc);
                }
            }
        }
        if (EPI == 3) {
            bool inorm = (z != 0);
            if (inorm) {
                float s = 0.f;
                for (int i = 0; i < 100; i++) s += acc_row[i];
                float mu = s * 0.01f, s2 = 0.f;
                for (int i = 0; i < 100; i++) { float d = acc_row[i] - mu; s2 += d * d; }
                float inv = rsqrtf(s2 * 0.01f + 1e-5f);
                for (int i = 0; i < 100; i++) acc_row[i] = (acc_row[i] - mu) * inv;
            }
            float m = -1e30f;
            for (int i = 0; i < 100; i++) m = fmaxf(m, acc_row[i] * 0.03125f);
            float se = 0.f;
            for (int i = 0; i < 100; i++) { acc_row[i] = expf(acc_row[i] * 0.03125f - m); se += acc_row[i]; }
            float rinv = 1.f / se;
            __nv_bfloat16* o = (__nv_bfloat16*)C + (size_t)row * KP;
            for (int i = 1; i < 100; i++) o[i - 1] = __float2bfloat16(acc_row[i] * rinv);
            for (int i = 99; i < 128; i++) o[i] = __float2bfloat16(0.f);
        }
    }
#endif
}

// ---------------- inverse: z-build + ifft_b(8) + Hermitian irfft -> out ----
__global__ void __launch_bounds__(512) fft_inv(const float* __restrict__ feats,
                                               const float* __restrict__ scale_p,
                                               float* __restrict__ out)
{
    extern __shared__ float sm[];
    float* sre = sm;               // 8192
    float* sim = sm + 8192;        // 8192
    float* twr = sm + 16384;       // 1024
    float* twi = twr + 1024;       // 1024
    int tid = threadIdx.x;
    int n = blockIdx.x;

    for (int t = tid; t < 1024; t += 512) {
        float s_, c_;
        __sincosf((float)t * 6.1359233e-3f, &s_, &c_);    // +2*pi/1024
        twr[t] = c_; twi[t] = s_;
    }
    __syncthreads();

    const float W8R[8] = {1.f, 0.70710678f, 0.f, -0.70710678f, -1.f, -0.70710678f, 0.f, 0.70710678f};
    const float W8I[8] = {0.f, -0.70710678f, -1.f, -0.70710678f, 0.f, 0.70710678f, 1.f, 0.70710678f};

    for (int c = tid; c < 513; c += 512) {
        float zr_[8], zi_[8];
        #pragma unroll
        for (int b = 0; b < 8; b++) {
            size_t off = (size_t)((n << 3) + b) * NZ + c;
            float phv = __bfloat162float(g_dpb[off]);
            float amv = __bfloat162float(g_dab[off]);
            float s_, c_;
            __sincosf(phv, &s_, &c_);
            zr_[b] = c_ * amv;
            zi_[b] = s_ * amv;
        }
        int rcp = rc4(c);
        int rcm = rc4((1024 - c) & 1023);
        bool mir = (c != 0) && (c != 512);
        #pragma unroll
        for (int b = 0; b < 8; b++) {
            float orr = 0.f, oii = 0.f;
            #pragma unroll
            for (int kb = 0; kb < 8; kb++) {
                int t8 = (kb * b) & 7;
                float wr = W8R[t8], wi = -W8I[t8];
                orr += zr_[kb] * wr - zi_[kb] * wi;
                oii += zr_[kb] * wi + zi_[kb] * wr;
            }
            int p1 = SW((b << 10) + rcp);
            sre[p1] = orr; sim[p1] = oii;
            if (mir) {
                int p2 = SW((b << 10) + rcm);
                sre[p2] = orr; sim[p2] = -oii;
            }
        }
    }
    __syncthreads();
    fft_stages_r4(sre, sim, twr, twi, tid, +1);

    float sc = scale_p[0];
    for (int i = tid; i < 8192; i += 512) {
        int b = i >> 10, c = i & 1023;
        float d = sre[SW((b << 10) + c)] * (1.0f / 4096.0f);
        size_t off = ((size_t)(n + 1) * 8 + b) * 1024 + c;
        out[off] = feats[off] + d * sc;
    }
}

__global__ void cls_copy(const float* __restrict__ feats, float* __restrict__ out)
{
    int i = blockIdx.x * 256 + threadIdx.x;
    if (i < 8192) out[i] = feats[i];
}

// ---------------- host ------------------------------------------------------
static void* symaddr(const void* s)
{
    void* p = nullptr;
    cudaGetSymbolAddress(&p, s);
    return p;
}

extern "C" void kernel_launch(void* const* d_in, const int* in_sizes, int n_in,
                              void* d_out, int out_size)
{
    (void)in_sizes; (void)n_in; (void)out_size;
    const float* feats  = (const float*)d_in[0];
    const float* lt1    = (const float*)d_in[1];
    const float* lt2    = (const float*)d_in[2];
    const float* w_t2f  = (const float*)d_in[3];
    const float* b_t2f  = (const float*)d_in[4];
    const float* w_df   = (const float*)d_in[5];
    const float* b_df   = (const float*)d_in[6];
    const float* w_t2f2 = (const float*)d_in[7];
    const float* b_t2f2 = (const float*)d_in[8];
    const float* w_df2  = (const float*)d_in[9];
    const float* b_df2  = (const float*)d_in[10];
    const float* scale  = (const float*)d_in[11];
    const int*   layer  = (const int*)d_in[12];
    float* out = (float*)d_out;

    __nv_bfloat16* phb = (__nv_bfloat16*)symaddr(g_phb);
    __nv_bfloat16* amb = (__nv_bfloat16*)symaddr(g_amb);
    __nv_bfloat16* T1b = (__nv_bfloat16*)symaddr(g_T1b);
    __nv_bfloat16* T2b = (__nv_bfloat16*)symaddr(g_T2b);
    __nv_bfloat16* S1  = (__nv_bfloat16*)symaddr(g_S1);
    __nv_bfloat16* S2  = (__nv_bfloat16*)symaddr(g_S2);
    __nv_bfloat16* vT1 = (__nv_bfloat16*)symaddr(g_vT1);
    __nv_bfloat16* vT2 = (__nv_bfloat16*)symaddr(g_vT2);
    __nv_bfloat16* P1  = (__nv_bfloat16*)symaddr(g_P1);
    __nv_bfloat16* P2  = (__nv_bfloat16*)symaddr(g_P2);
    __nv_bfloat16* W1  = (__nv_bfloat16*)symaddr(g_W1);
    __nv_bfloat16* W2  = (__nv_bfloat16*)symaddr(g_W2);
    __nv_bfloat16* W3  = (__nv_bfloat16*)symaddr(g_W3);
    __nv_bfloat16* W4  = (__nv_bfloat16*)symaddr(g_W4);
    __nv_bfloat16* dpb = (__nv_bfloat16*)symaddr(g_dpb);
    __nv_bfloat16* dab = (__nv_bfloat16*)symaddr(g_dab);

    const int FFT_SMEM  = (8192 * 2 + 2048) * 4;   // 73728
    const int GEMM_SMEM = 1024 + CTRL_OFF + 64;    // 67648
    cudaFuncSetAttribute(fft_fwd, cudaFuncAttributeMaxDynamicSharedMemorySize, FFT_SMEM);
    cudaFuncSetAttribute(fft_inv, cudaFuncAttributeMaxDynamicSharedMemorySize, FFT_SMEM);
    cudaFuncSetAttribute(gemm_tc<3,0>, cudaFuncAttributeMaxDynamicSharedMemorySize, GEMM_SMEM);
    cudaFuncSetAttribute(gemm_tc<1,2>, cudaFuncAttributeMaxDynamicSharedMemorySize, GEMM_SMEM);
    cudaFuncSetAttribute(gemm_tc<2,0>, cudaFuncAttributeMaxDynamicSharedMemorySize, GEMM_SMEM);
    cudaFuncSetAttribute(gemm_tc<1,1>, cudaFuncAttributeMaxDynamicSharedMemorySize, GEMM_SMEM);

    // 1) tokens (bf16, padded) + weight conversion
    prep_tokens<<<(144 * CDIM + 255) / 256, 256>>>(lt1, lt2, layer);
    conv_w<<<(CDIM * CDIM + 255) / 256, 256>>>(w_t2f, w_t2f2, w_df, w_df2);

    // 2) FFT2 + amp/phase (bf16)
    fft_fwd<<<1024, 512, FFT_SMEM>>>(feats);

    // 3) attn = X @ T^T with fused softmax -> bf16 S [8192 x 128]
    {
        GB g = { phb, amb, T1b, T2b, nullptr, nullptr, nullptr, nullptr, S1, S2 };
        gemm_tc<3,0><<<dim3(1, 64, 2), 256, GEMM_SMEM>>>(g, CDIM, CDIM, KP, 0, 16, KP);
    }

    // 4) vT[c][j] = sum_k W[c][k]*T[1+j][k] + b[c]  -> bf16 [1024 x 128]
    {
        GB g = { W1, W2, T1b + CDIM, T2b + CDIM, b_t2f, b_t2f2, nullptr, nullptr, vT1, vT2 };
        gemm_tc<1,2><<<dim3(1, 8, 2), 256, GEMM_SMEM>>>(g, CDIM, CDIM, KP, 0, 16, KP);
    }

    // 5) P = S @ vT^T + X  -> bf16 [8192 x 1024]
    {
        GB g = { S1, S2, vT1, vT2, nullptr, nullptr, phb, amb, P1, P2 };
        gemm_tc<2,0><<<dim3(8, 64, 2), 256, GEMM_SMEM>>>(g, KP, KP, CDIM, CDIM, 2, CDIM);
    }

    // 6) d = P @ Wdf^T + b  -> bf16 [8192 x 513]
    {
        GB g = { P1, P2, W3, W4, b_df, b_df2, nullptr, nullptr, dpb, dab };
        gemm_tc<1,1><<<dim3(5, 64, 2), 256, GEMM_SMEM>>>(g, CDIM, CDIM, NZ, 0, 16, NZ);
    }

    // 7) z-build + irfft2 + residual add (fused)
    fft_inv<<<1024, 512, FFT_SMEM>>>(feats, scale, out);

    // 8) cls row passthrough
    cls_copy<<<32, 256>>>(feats, out);
}

// round 10
// speedup vs baseline: 4.5697x; 1.0106x over previous
#include <cuda_runtime.h>
#include <cuda_bf16.h>
#include <math.h>
#include <stdint.h>

#if defined(__CUDA_ARCH__) && (defined(__CUDA_ARCH_SPECIFIC__) || defined(__CUDA_ARCH_FAMILY_SPECIFIC__))
#define HAS_TCGEN05 1
#else
#define HAS_TCGEN05 0
#endif

#define MROWS 8192      // 1024 * 8 rows
#define CDIM  1024
#define KP    128       // padded token/attention dim
#define NZ    513       // kept spectrum columns

// smem bank swizzle for FFT arrays
#define SW(i) ((i) ^ (((i) >> 5) & 31))

// ---------------- scratch (device globals; no allocation allowed) ----------
__device__ __nv_bfloat16 g_phb[MROWS*CDIM];
__device__ __nv_bfloat16 g_amb[MROWS*CDIM];
__device__ __nv_bfloat16 g_T1b[144*CDIM];
__device__ __nv_bfloat16 g_T2b[144*CDIM];
__device__ __nv_bfloat16 g_S1[MROWS*KP];
__device__ __nv_bfloat16 g_S2[MROWS*KP];
__device__ __nv_bfloat16 g_vT1[CDIM*KP];
__device__ __nv_bfloat16 g_vT2[CDIM*KP];
__device__ __nv_bfloat16 g_P1[MROWS*CDIM];
__device__ __nv_bfloat16 g_P2[MROWS*CDIM];
__device__ __nv_bfloat16 g_W1[CDIM*CDIM]; // w_t2f
__device__ __nv_bfloat16 g_W2[CDIM*CDIM]; // w_t2f2
__device__ __nv_bfloat16 g_W3[CDIM*CDIM]; // w_df
__device__ __nv_bfloat16 g_W4[CDIM*CDIM]; // w_df2
__device__ __nv_bfloat16 g_dpb[MROWS*NZ];
__device__ __nv_bfloat16 g_dab[MROWS*NZ];

// ---------------- PTX helpers ----------------------------------------------
__device__ __forceinline__ uint32_t smem_u32(const void* p) {
    uint32_t a;
    asm("{ .reg .u64 t; cvta.to.shared.u64 t, %1; cvt.u32.u64 %0, t; }" : "=r"(a) : "l"(p));
    return a;
}
__device__ __forceinline__ bool elect1() {
    uint32_t p;
    asm volatile("{ .reg .pred p; elect.sync _|p, 0xFFFFFFFF; selp.b32 %0, 1, 0, p; }" : "=r"(p));
    return p != 0;
}
__device__ __forceinline__ uint64_t make_desc(uint32_t addr) {
    const uint64_t base = (uint64_t(2) << 61) | (uint64_t(1) << 46) |
                          (uint64_t(64) << 32) | (uint64_t(1) << 16);
    return base | ((addr >> 4) & 0x3FFF);
}
__device__ __forceinline__ void mbar_wait(uint32_t mbar, uint32_t parity) {
    asm volatile(
        "{\n\t.reg .pred P;\n\t"
        "WL%=:\n\t"
        "mbarrier.try_wait.parity.acquire.cta.shared::cta.b64 P, [%0], %1, 0x989680;\n\t"
        "@P bra.uni WD%=;\n\t"
        "bra.uni WL%=;\n\t"
        "WD%=:\n\t}"
        :: "r"(mbar), "r"(parity) : "memory");
}

#if HAS_TCGEN05
__device__ __forceinline__ void mma_ss_f16(uint32_t d, uint64_t ad, uint64_t bd,
                                           uint32_t idesc, bool acc) {
    uint32_t en = acc ? 1u : 0u;
    asm volatile(
        "{\n\t.reg .pred p;\n\tsetp.ne.u32 p, %4, 0;\n\t"
        "tcgen05.mma.cta_group::1.kind::f16 [%0], %1, %2, %3, {%5, %5, %5, %5}, p;\n\t}"
        :: "r"(d), "l"(ad), "l"(bd), "r"(idesc), "r"(en), "r"(0u) : "memory");
}
#define LDTM_X32(r, a) \
    asm volatile( \
        "tcgen05.ld.sync.aligned.32x32b.x32.b32 " \
        "{%0, %1, %2, %3, %4, %5, %6, %7, " \
        " %8, %9, %10, %11, %12, %13, %14, %15, " \
        " %16, %17, %18, %19, %20, %21, %22, %23, " \
        " %24, %25, %26, %27, %28, %29, %30, %31}, [%32];" \
        : "=r"((r)[0]),  "=r"((r)[1]),  "=r"((r)[2]),  "=r"((r)[3]), \
          "=r"((r)[4]),  "=r"((r)[5]),  "=r"((r)[6]),  "=r"((r)[7]), \
          "=r"((r)[8]),  "=r"((r)[9]),  "=r"((r)[10]), "=r"((r)[11]), \
          "=r"((r)[12]), "=r"((r)[13]), "=r"((r)[14]), "=r"((r)[15]), \
          "=r"((r)[16]), "=r"((r)[17]), "=r"((r)[18]), "=r"((r)[19]), \
          "=r"((r)[20]), "=r"((r)[21]), "=r"((r)[22]), "=r"((r)[23]), \
          "=r"((r)[24]), "=r"((r)[25]), "=r"((r)[26]), "=r"((r)[27]), \
          "=r"((r)[28]), "=r"((r)[29]), "=r"((r)[30]), "=r"((r)[31]) \
        : "r"(a))
#endif

// idesc: fp32 accum, bf16 A/B, M=128, N=128
#define IDESC_128 0x08200490u
#define CTRL_OFF 66560   // above 64KB tiles / 66KB softmax staging

// base-4 digit reverse of 10-bit index
__device__ __forceinline__ int rc4(int c) {
    return ((c & 3) << 8) | (((c >> 2) & 3) << 6) | (((c >> 4) & 3) << 4) |
           (((c >> 6) & 3) << 2) | ((c >> 8) & 3);
}

// fast atan2 (~2e-5 rad abs err) — delta-path only, error suppressed x1e-3
__device__ __forceinline__ float fast_atan2(float y, float x) {
    float ax = fabsf(x), ay = fabsf(y);
    float mx = fmaxf(ax, ay), mn = fminf(ax, ay);
    float a = __fdividef(mn, mx);
    float s = a * a;
    float r = a * (0.99997726f + s * (-0.33262347f + s * (0.19354346f +
              s * (-0.11643287f + s * (0.05265332f - s * 0.01172120f)))));
    if (ay > ax) r = 1.57079637f - r;
    if (x < 0.f) r = 3.14159274f - r;
    return copysignf(r, y);
}

// ---------------- prep: tokens -> bf16 padded + weights -> bf16 (one launch)
__global__ void prep_all(const float* __restrict__ lt1,
                         const float* __restrict__ lt2,
                         const int* __restrict__ layer_p,
                         const float* __restrict__ wa, const float* __restrict__ wb,
                         const float* __restrict__ wc, const float* __restrict__ wd)
{
    int blk = blockIdx.x;
    if (blk < 4096) {                       // weight conversion: 1M elements
        int i = blk * 256 + threadIdx.x;
        g_W1[i] = __float2bfloat16(wa[i]);
        g_W2[i] = __float2bfloat16(wb[i]);
        g_W3[i] = __float2bfloat16(wc[i]);
        g_W4[i] = __float2bfloat16(wd[i]);
    } else {                                // token prep: 144K elements
        int i = (blk - 4096) * 256 + threadIdx.x;
        if (i >= 144 * CDIM) return;
        int row = i >> 10;
        int layer = layer_p[0];
        float v1 = 0.f, v2 = 0.f;
        if (row < 100) {
            v1 = lt1[layer * 100 * CDIM + i];
            v2 = lt2[layer * 100 * CDIM + i];
        }
        g_T1b[i] = __float2bfloat16(v1);
        g_T2b[i] = __float2bfloat16(v2);
    }
}

// ---------------- radix-4 butterfly stages (in-place, swizzled smem) --------
__device__ __forceinline__ void fft_stages_r4(float* sre, float* sim,
                                              const float* twr, const float* twi,
                                              int tid, int dir)
{
    #pragma unroll
    for (int s = 1; s <= 5; s++) {
        int Q = 1 << (2 * (s - 1));
        int sh = 10 - 2 * s;
        for (int t = tid; t < 2048; t += 512) {
            int b = t >> 8, j = t & 255;
            int pos = j & (Q - 1);
            int i0 = (b << 10) + ((j >> (2 * (s - 1))) << (2 * s)) + pos;
            int e = pos << sh;
            float w1r = twr[e], w1i = twi[e];
            float w2r = w1r * w1r - w1i * w1i, w2i = 2.f * w1r * w1i;
            float w3r = w2r * w1r - w2i * w1i, w3i = w2r * w1i + w2i * w1r;
            int p0 = SW(i0), p1 = SW(i0 + Q), p2 = SW(i0 + 2 * Q), p3 = SW(i0 + 3 * Q);
            float a0r = sre[p0], a0i = sim[p0];
            float b1r = sre[p1], b1i = sim[p1];
            float b2r = sre[p2], b2i = sim[p2];
            float b3r = sre[p3], b3i = sim[p3];
            float x1r = b1r * w1r - b1i * w1i, x1i = b1r * w1i + b1i * w1r;
            float x2r = b2r * w2r - b2i * w2i, x2i = b2r * w2i + b2i * w2r;
            float x3r = b3r * w3r - b3i * w3i, x3i = b3r * w3i + b3i * w3r;
            float t0r = a0r + x2r, t0i = a0i + x2i;
            float t1r = a0r - x2r, t1i = a0i - x2i;
            float t2r = x1r + x3r, t2i = x1i + x3i;
            float t3r = x1r - x3r, t3i = x1i - x3i;
            sre[p0] = t0r + t2r; sim[p0] = t0i + t2i;
            sre[p2] = t0r - t2r; sim[p2] = t0i - t2i;
            if (dir < 0) {
                sre[p1] = t1r + t3i; sim[p1] = t1i - t3r;
                sre[p3] = t1r - t3i; sim[p3] = t1i + t3r;
            } else {
                sre[p1] = t1r - t3i; sim[p1] = t1i + t3r;
                sre[p3] = t1r + t3i; sim[p3] = t1i - t3r;
            }
        }
        __syncthreads();
    }
}

// ---------------- forward FFT2 + amp/phase (bf16x2 stores) ------------------
__global__ void __launch_bounds__(512) fft_fwd(const float* __restrict__ feats)
{
    extern __shared__ float sm[];
    float* sre = sm;               // 8192
    float* sim = sm + 8192;        // 8192
    float* twr = sm + 16384;       // 1024
    float* twi = twr + 1024;       // 1024
    int tid = threadIdx.x;
    int n = blockIdx.x;
    const float* x = feats + (size_t)(n + 1) * 8192;

    for (int t = tid; t < 1024; t += 512) {
        float s_, c_;
        __sincosf((float)t * -6.1359233e-3f, &s_, &c_);   // -2*pi/1024
        twr[t] = c_; twi[t] = s_;
    }
    for (int i = tid; i < 8192; i += 512) {
        int b = i >> 10, c = i & 1023;
        int p = SW((b << 10) + rc4(c));
        sre[p] = x[i];
        sim[p] = 0.f;
    }
    __syncthreads();
    fft_stages_r4(sre, sim, twr, twi, tid, -1);

    const float W8R[8] = {1.f, 0.70710678f, 0.f, -0.70710678f, -1.f, -0.70710678f, 0.f, 0.70710678f};
    const float W8I[8] = {0.f, -0.70710678f, -1.f, -0.70710678f, 0.f, 0.70710678f, 1.f, 0.70710678f};
    int c0 = tid << 1;             // two consecutive columns per thread
    float ar0[8], ai0[8], ar1[8], ai1[8];
    #pragma unroll
    for (int b = 0; b < 8; b++) {
        int p0 = SW((b << 10) + c0), p1 = SW((b << 10) + c0 + 1);
        ar0[b] = sre[p0]; ai0[b] = sim[p0];
        ar1[b] = sre[p1]; ai1[b] = sim[p1];
    }
    #pragma unroll
    for (int kb = 0; kb < 8; kb++) {
        float o0r = 0.f, o0i = 0.f, o1r = 0.f, o1i = 0.f;
        #pragma unroll
        for (int b = 0; b < 8; b++) {
            int t8 = (kb * b) & 7;
            float wr = W8R[t8], wi = W8I[t8];
            o0r += ar0[b] * wr - ai0[b] * wi;
            o0i += ar0[b] * wi + ai0[b] * wr;
            o1r += ar1[b] * wr - ai1[b] * wi;
            o1i += ar1[b] * wi + ai1[b] * wr;
        }
        float p20 = o0r * o0r + o0i * o0i; if (p20 < 1e-5f) p20 = 1e-5f;
        float p21 = o1r * o1r + o1i * o1i; if (p21 < 1e-5f) p21 = 1e-5f;
        float am0 = sqrtf(p20), am1 = sqrtf(p21);
        float rr0 = o0r; if (rr0 < 1e-5f && rr0 > -1e-5f) rr0 = 1e-5f;
        float rr1 = o1r; if (rr1 < 1e-5f && rr1 > -1e-5f) rr1 = 1e-5f;
        float ph0 = fast_atan2(o0i, rr0);
        float ph1 = fast_atan2(o1i, rr1);
        int off = (((n << 3) + kb) << 10) + c0;
        *(__nv_bfloat162*)(&g_amb[off]) = __nv_bfloat162(__float2bfloat16(am0), __float2bfloat16(am1));
        *(__nv_bfloat162*)(&g_phb[off]) = __nv_bfloat162(__float2bfloat16(ph0), __float2bfloat16(ph1));
    }
}

// ---------------- tcgen05 bf16 GEMM building blocks -------------------------
struct GB {
    const __nv_bfloat16 *A0, *A1b;
    const __nv_bfloat16 *B0, *B1b;
    const float *bias0, *bias1;
    const __nv_bfloat16 *X0, *X1;
    void *C0, *C1;
};

#if HAS_TCGEN05
// Prologue: TMEM alloc + mbarrier init. Returns tmem base.
__device__ __forceinline__ uint32_t gemm_prologue(uint32_t ctrl, int tid, int wid)
{
    if (wid == 0) {
        asm volatile("tcgen05.alloc.cta_group::1.sync.aligned.shared::cta.b32 [%0], %1;"
                     :: "r"(ctrl), "r"(128u) : "memory");
        asm volatile("tcgen05.relinquish_alloc_permit.cta_group::1.sync.aligned;");
    }
    if (tid == 0) {
        asm volatile("mbarrier.init.shared.b64 [%0], 1;" :: "r"(ctrl + 8) : "memory");
        asm volatile("mbarrier.init.shared.b64 [%0], 1;" :: "r"(ctrl + 16) : "memory");
    }
    __syncthreads();
    uint32_t tmem;
    asm volatile("ld.shared.b32 %0, [%1];" : "=r"(tmem) : "r"(ctrl));
    return tmem;
}

// Mainloop with register-prefetch pipeline: chunk c+1 LDGs issue right after
// chunk c STS, absorbing DRAM latency across fence/sync/MMA/wait.
__device__ __forceinline__ void gemm_mainloop(const __nv_bfloat16* Ab, const __nv_bfloat16* Bb,
                                              int lda, int ldb, int nk,
                                              char* tp, uint32_t ta, uint32_t ctrl,
                                              uint32_t tmem, int tid, int wid)
{
    const int abase[2] = {0, 16384};
    const int bbase[2] = {32768, 49152};
    int ph[2] = {0, 0};

    const __nv_bfloat16* ap[4];
    const __nv_bfloat16* bp[4];
    uint32_t so[4];
    #pragma unroll
    for (int it = 0; it < 4; it++) {
        int u = tid + (it << 8);
        int r = u >> 3, s = u & 7;
        ap[it] = Ab + (size_t)r * lda + (s << 3);
        bp[it] = Bb + (size_t)r * ldb + (s << 3);
        uint32_t bo = (r << 7) + (s << 4);
        so[it] = bo ^ ((bo >> 3) & 0x70);
    }
    uint4 ra[4], rb[4];
    #pragma unroll
    for (int it = 0; it < 4; it++) { ra[it] = *(const uint4*)ap[it]; rb[it] = *(const uint4*)bp[it]; }

    for (int c = 0; c < nk; c++) {
        int b = c & 1;
        if (c >= 2) { mbar_wait(ctrl + 8 + b * 8, (uint32_t)ph[b]); ph[b] ^= 1; }
        #pragma unroll
        for (int it = 0; it < 4; it++) {
            *(uint4*)(tp + abase[b] + so[it]) = ra[it];
            *(uint4*)(tp + bbase[b] + so[it]) = rb[it];
        }
        if (c + 1 < nk) {
            int k1 = (c + 1) << 6;
            #pragma unroll
            for (int it = 0; it < 4; it++) {
                ra[it] = *(const uint4*)(ap[it] + k1);
                rb[it] = *(const uint4*)(bp[it] + k1);
            }
        }
        asm volatile("fence.proxy.async.shared::cta;" ::: "memory");
        __syncthreads();
        if (wid == 0 && elect1()) {
            uint64_t ad = make_desc(ta + abase[b]);
            uint64_t bd = make_desc(ta + bbase[b]);
            #pragma unroll
            for (int kk = 0; kk < 4; kk++)
                mma_ss_f16(tmem, ad + kk * 2, bd + kk * 2, IDESC_128, (c | kk) != 0);
            asm volatile(
                "tcgen05.commit.cta_group::1.mbarrier::arrive::one.shared::cluster.b64 [%0];"
                :: "r"(ctrl + 8 + b * 8) : "memory");
        }
    }
    mbar_wait(ctrl + 8, (uint32_t)ph[0]);
    mbar_wait(ctrl + 16, (uint32_t)ph[1]);
    asm volatile("tcgen05.fence::after_thread_sync;" ::: "memory");
    __syncthreads();
}
#endif

// ---------------- fused attn(+softmax) / vT GEMM launch ---------------------
// grid (1, 72, 2): y<64 -> attn rows (EPI softmax), y>=64 -> vT rows (bias row)
__global__ void __launch_bounds__(256, 2) gemm_attn_vt(GB g, const float* bias0,
                                                       const float* bias1)
{
    extern __shared__ char sm_[];
    int tid = threadIdx.x;
    int z = blockIdx.z;
    bool is_vt = (blockIdx.y >= 64);
    int row0 = (is_vt ? ((int)blockIdx.y - 64) : (int)blockIdx.y) << 7;
    const __nv_bfloat16* A = is_vt ? (z ? g.X1 : g.X0)            // W1/W2
                                   : (z ? g.A1b : g.A0);          // phb/amb
    const __nv_bfloat16* Bm = (z ? g.B1b : g.B0) + (is_vt ? CDIM : 0);  // tokens (+1 row)
    const float* bias = z ? bias1 : bias0;

#if HAS_TCGEN05
    uint32_t sb = smem_u32(sm_);
    uint32_t ta = (sb + 1023u) & ~1023u;
    char* tp = sm_ + (ta - sb);
    uint32_t ctrl = ta + CTRL_OFF;
    int wid = tid >> 5, lane = tid & 31;
    uint32_t tmem = gemm_prologue(ctrl, tid, wid);
    gemm_mainloop(A + (size_t)row0 * CDIM, Bm, CDIM, CDIM, 16, tp, ta, ctrl, tmem, tid, wid);

    int sub = wid & 3, half = wid >> 2;
    int rsub = (sub << 5) + lane;

    if (!is_vt) {
        // fused softmax epilogue: stage 128x128 tile (stride 129)
        float* smf = (float*)tp;
        #pragma unroll
        for (int q = 0; q < 2; q++) {
            int cb = (half << 1) + q;
            uint32_t r_[32];
            LDTM_X32(r_, tmem + (cb << 5));
            asm volatile("tcgen05.wait::ld.sync.aligned;" ::: "memory");
            #pragma unroll
            for (int j = 0; j < 32; j++)
                smf[rsub * 129 + (cb << 5) + j] = __uint_as_float(r_[j]);
        }
        __syncthreads();
        bool inorm = (z != 0);
        __nv_bfloat16* Srow = (__nv_bfloat16*)(z ? g.C1 : g.C0);
        for (int r = wid; r < 128; r += 8) {
            const float* a = smf + r * 129;
            float v[4]; bool val[4];
            #pragma unroll
            for (int q = 0; q < 4; q++) {
                int idx = lane + 32 * q;
                val[q] = idx < 100;
                v[q] = val[q] ? a[idx] : 0.f;
            }
            if (inorm) {
                float s = v[0] + v[1] + v[2] + v[3];
                #pragma unroll
                for (int off = 16; off > 0; off >>= 1) s += __shfl_xor_sync(0xffffffffu, s, off);
                float mu = s * 0.01f;
                float s2 = 0.f;
                #pragma unroll
                for (int q = 0; q < 4; q++) if (val[q]) { float d = v[q] - mu; s2 += d * d; }
                #pragma unroll
                for (int off = 16; off > 0; off >>= 1) s2 += __shfl_xor_sync(0xffffffffu, s2, off);
                float inv = rsqrtf(s2 * 0.01f + 1e-5f);
                #pragma unroll
                for (int q = 0; q < 4; q++) v[q] = (v[q] - mu) * inv;
            }
            float m = -1e30f;
            #pragma unroll
            for (int q = 0; q < 4; q++) if (val[q]) m = fmaxf(m, v[q] * 0.03125f);
            #pragma unroll
            for (int off = 16; off > 0; off >>= 1) m = fmaxf(m, __shfl_xor_sync(0xffffffffu, m, off));
            float e[4]; float se = 0.f;
            #pragma unroll
            for (int q = 0; q < 4; q++) {
                e[q] = val[q] ? __expf(v[q] * 0.03125f - m) : 0.f;
                se += e[q];
            }
            #pragma unroll
            for (int off = 16; off > 0; off >>= 1) se += __shfl_xor_sync(0xffffffffu, se, off);
            float rinv = __fdividef(1.f, se);
            __nv_bfloat16* o = Srow + (size_t)(row0 + r) * KP;
            #pragma unroll
            for (int q = 0; q < 4; q++) {
                int idx = lane + 32 * q;
                if (idx >= 1 && idx < 100) o[idx - 1] = __float2bfloat16(e[q] * rinv);
                else if (idx >= 100) o[idx - 1] = __float2bfloat16(0.f);
                else o[127] = __float2bfloat16(0.f);
            }
        }
    } else {
        // vT epilogue: bias per row, bf16 out (vT1/vT2 passed via bias slot of C)
        __nv_bfloat16* C = (__nv_bfloat16*)(z ? (void*)g.bias1 : (void*)g.bias0);
        float* smf = (float*)tp + half * 4224;
        float biasr = bias[row0 + rsub];
        int barid = 1 + half;
        #pragma unroll
        for (int q = 0; q < 2; q++) {
            int cb = (half << 1) + q;
            uint32_t r_[32];
            LDTM_X32(r_, tmem + (cb << 5));
            asm volatile("tcgen05.wait::ld.sync.aligned;" ::: "memory");
            asm volatile("bar.sync %0, 128;" :: "r"(barid) : "memory");
            #pragma unroll
            for (int j = 0; j < 32; j++) smf[rsub * 33 + j] = __uint_as_float(r_[j]) + biasr;
            asm volatile("bar.sync %0, 128;" :: "r"(barid) : "memory");
            #pragma unroll
            for (int i = 0; i < 32; i++) {
                int idx = rsub + (i << 7);
                int orow = idx >> 5, ocol = idx & 31;
                int cc = (cb << 5) + ocol;
                C[(size_t)(row0 + orow) * KP + cc] = __float2bfloat16(smf[orow * 33 + ocol]);
            }
        }
    }
    __syncthreads();
    if (wid == 0) {
        asm volatile("tcgen05.dealloc.cta_group::1.sync.aligned.b32 %0, %1;"
                     :: "r"(tmem), "r"(128u));
    }
#else
    (void)sm_;
    if (tid < 128) {
        int row = row0 + tid;
        float acc_row[128];
        for (int cc = 0; cc < 128; cc++) {
            float acc = 0.f;
            for (int k = 0; k < 1024; k++)
                acc += __bfloat162float(A[(size_t)row * CDIM + k]) *
                       __bfloat162float(Bm[(size_t)cc * CDIM + k]);
            acc_row[cc] = acc;
        }
        if (is_vt) {
            __nv_bfloat16* C = (__nv_bfloat16*)(z ? (void*)g.bias1 : (void*)g.bias0);
            for (int cc = 0; cc < 128; cc++)
                C[(size_t)row * KP + cc] = __float2bfloat16(acc_row[cc] + bias[row]);
        } else {
            bool inorm = (z != 0);
            if (inorm) {
                float s = 0.f;
                for (int i = 0; i < 100; i++) s += acc_row[i];
                float mu = s * 0.01f, s2 = 0.f;
                for (int i = 0; i < 100; i++) { float d = acc_row[i] - mu; s2 += d * d; }
                float inv = rsqrtf(s2 * 0.01f + 1e-5f);
                for (int i = 0; i < 100; i++) acc_row[i] = (acc_row[i] - mu) * inv;
            }
            float m = -1e30f;
            for (int i = 0; i < 100; i++) m = fmaxf(m, acc_row[i] * 0.03125f);
            float se = 0.f;
            for (int i = 0; i < 100; i++) { acc_row[i] = expf(acc_row[i] * 0.03125f - m); se += acc_row[i]; }
            float rinv = 1.f / se;
            __nv_bfloat16* o = (__nv_bfloat16*)(z ? g.C1 : g.C0) + (size_t)row * KP;
            for (int i = 1; i < 100; i++) o[i - 1] = __float2bfloat16(acc_row[i] * rinv);
            for (int i = 99; i < 128; i++) o[i] = __float2bfloat16(0.f);
        }
    }
#endif
}

// ---------------- generic GEMM: EPI 1 = bf16, 2 = (+X bf16)->bf16 -----------
// BIAS: 0 none, 1 per-col fp32
template<int EPI, int BIAS>
__global__ void __launch_bounds__(256, 2) gemm_tc(GB g, int lda, int ldb, int ldc,
                                                  int ldx, int nk, int nguard)
{
    extern __shared__ char sm_[];
    int tid = threadIdx.x;
    int z = blockIdx.z;
    const __nv_bfloat16* A = z ? g.A1b : g.A0;
    const __nv_bfloat16* B = z ? g.B1b : g.B0;
    const float* bias = z ? g.bias1 : g.bias0;
    const __nv_bfloat16* X = z ? g.X1 : g.X0;
    char* C = (char*)(z ? g.C1 : g.C0);
    int row0 = blockIdx.y << 7, col0 = blockIdx.x << 7;

#if HAS_TCGEN05
    uint32_t sb = smem_u32(sm_);
    uint32_t ta = (sb + 1023u) & ~1023u;
    char* tp = sm_ + (ta - sb);
    uint32_t ctrl = ta + CTRL_OFF;
    int wid = tid >> 5, lane = tid & 31;
    uint32_t tmem = gemm_prologue(ctrl, tid, wid);
    gemm_mainloop(A + (size_t)row0 * lda, B + (size_t)col0 * ldb, lda, ldb, nk,
                  tp, ta, ctrl, tmem, tid, wid);

    int sub = wid & 3, half = wid >> 2;
    int rsub = (sub << 5) + lane;
    float* smf = (float*)tp + half * 4224;
    int barid = 1 + half;
    #pragma unroll
    for (int q = 0; q < 2; q++) {
        int cb = (half << 1) + q;
        uint32_t r_[32];
        LDTM_X32(r_, tmem + (cb << 5));
        asm volatile("tcgen05.wait::ld.sync.aligned;" ::: "memory");
        asm volatile("bar.sync %0, 128;" :: "r"(barid) : "memory");
        #pragma unroll
        for (int j = 0; j < 32; j++) smf[rsub * 33 + j] = __uint_as_float(r_[j]);
        asm volatile("bar.sync %0, 128;" :: "r"(barid) : "memory");
        #pragma unroll
        for (int i = 0; i < 32; i++) {
            int idx = rsub + (i << 7);
            int orow = idx >> 5, ocol = idx & 31;
            int cc = col0 + (cb << 5) + ocol;
            if (cc < nguard) {
                float v = smf[orow * 33 + ocol];
                if (BIAS == 1) v += bias[cc];
                size_t off = (size_t)(row0 + orow) * ldc + cc;
                if (EPI == 1) ((__nv_bfloat16*)C)[off] = __float2bfloat16(v);
                else {
                    v += __bfloat162float(X[(size_t)(row0 + orow) * ldx + cc]);
                    ((__nv_bfloat16*)C)[off] = __float2bfloat16(v);
                }
            }
        }
    }
    __syncthreads();
    if (wid == 0) {
        asm volatile("tcgen05.dealloc.cta_group::1.sync.aligned.b32 %0, %1;"
                     :: "r"(tmem), "r"(128u));
    }
#else
    (void)sm_;
    if (tid < 128) {
        int row = row0 + tid;
        int K = nk << 6;
        for (int cc = 0; cc < 128; cc++) {
            int c = col0 + cc;
            if (c >= nguard) continue;
            float acc = 0.f;
            for (int k = 0; k < K; k++)
                acc += __bfloat162float(A[(size_t)row * lda + k]) *
                       __bfloat162float(B[(size_t)c * ldb + k]);
            if (BIAS == 1) acc += bias[c];
            size_t off = (size_t)row * ldc + c;
            if (EPI == 1) ((__nv_bfloat16*)C)[off] = __float2bfloat16(acc);
            else {
                acc += __bfloat162float(X[(size_t)row * ldx + c]);
                ((__nv_bfloat16*)C)[off] = __float2bfloat16(acc);
            }
        }
    }
#endif
}

// ---------------- inverse: z-build + ifft_b(8) + Hermitian irfft -> out ----
// grid 1025: block 1024 handles the cls-row passthrough
__global__ void __launch_bounds__(512) fft_inv(const float* __restrict__ feats,
                                               const float* __restrict__ scale_p,
                                               float* __restrict__ out)
{
    int tid = threadIdx.x;
    int n = blockIdx.x;
    if (n == 1024) {               // cls row copy: 8192 floats
        for (int i = tid; i < 8192; i += 512) out[i] = feats[i];
        return;
    }
    extern __shared__ float sm[];
    float* sre = sm;               // 8192
    float* sim = sm + 8192;        // 8192
    float* twr = sm + 16384;       // 1024
    float* twi = twr + 1024;       // 1024

    for (int t = tid; t < 1024; t += 512) {
        float s_, c_;
        __sincosf((float)t * 6.1359233e-3f, &s_, &c_);    // +2*pi/1024
        twr[t] = c_; twi[t] = s_;
    }
    __syncthreads();

    const float W8R[8] = {1.f, 0.70710678f, 0.f, -0.70710678f, -1.f, -0.70710678f, 0.f, 0.70710678f};
    const float W8I[8] = {0.f, -0.70710678f, -1.f, -0.70710678f, 0.f, 0.70710678f, 1.f, 0.70710678f};

    for (int c = tid; c < 513; c += 512) {
        float zr_[8], zi_[8];
        #pragma unroll
        for (int b = 0; b < 8; b++) {
            size_t off = (size_t)((n << 3) + b) * NZ + c;
            float phv = __bfloat162float(g_dpb[off]);
            float amv = __bfloat162float(g_dab[off]);
            float s_, c_;
            __sincosf(phv, &s_, &c_);
            zr_[b] = c_ * amv;
            zi_[b] = s_ * amv;
        }
        int rcp = rc4(c);
        int rcm = rc4((1024 - c) & 1023);
        bool mir = (c != 0) && (c != 512);
        #pragma unroll
        for (int b = 0; b < 8; b++) {
            float orr = 0.f, oii = 0.f;
            #pragma unroll
            for (int kb = 0; kb < 8; kb++) {
                int t8 = (kb * b) & 7;
                float wr = W8R[t8], wi = -W8I[t8];
                orr += zr_[kb] * wr - zi_[kb] * wi;
                oii += zr_[kb] * wi + zi_[kb] * wr;
            }
            int p1 = SW((b << 10) + rcp);
            sre[p1] = orr; sim[p1] = oii;
            if (mir) {
                int p2 = SW((b << 10) + rcm);
                sre[p2] = orr; sim[p2] = -oii;
            }
        }
    }
    __syncthreads();
    fft_stages_r4(sre, sim, twr, twi, tid, +1);

    float sc = scale_p[0];
    for (int i = tid; i < 8192; i += 512) {
        int b = i >> 10, c = i & 1023;
        float d = sre[SW((b << 10) + c)] * (1.0f / 4096.0f);
        size_t off = ((size_t)(n + 1) * 8 + b) * 1024 + c;
        out[off] = feats[off] + d * sc;
    }
}

// ---------------- host ------------------------------------------------------
static void* symaddr(const void* s)
{
    void* p = nullptr;
    cudaGetSymbolAddress(&p, s);
    return p;
}

extern "C" void kernel_launch(void* const* d_in, const int* in_sizes, int n_in,
                              void* d_out, int out_size)
{
    (void)in_sizes; (void)n_in; (void)out_size;
    const float* feats  = (const float*)d_in[0];
    const float* lt1    = (const float*)d_in[1];
    const float* lt2    = (const float*)d_in[2];
    const float* w_t2f  = (const float*)d_in[3];
    const float* b_t2f  = (const float*)d_in[4];
    const float* w_df   = (const float*)d_in[5];
    const float* b_df   = (const float*)d_in[6];
    const float* w_t2f2 = (const float*)d_in[7];
    const float* b_t2f2 = (const float*)d_in[8];
    const float* w_df2  = (const float*)d_in[9];
    const float* b_df2  = (const float*)d_in[10];
    const float* scale  = (const float*)d_in[11];
    const int*   layer  = (const int*)d_in[12];
    float* out = (float*)d_out;

    __nv_bfloat16* phb = (__nv_bfloat16*)symaddr(g_phb);
    __nv_bfloat16* amb = (__nv_bfloat16*)symaddr(g_amb);
    __nv_bfloat16* T1b = (__nv_bfloat16*)symaddr(g_T1b);
    __nv_bfloat16* T2b = (__nv_bfloat16*)symaddr(g_T2b);
    __nv_bfloat16* S1  = (__nv_bfloat16*)symaddr(g_S1);
    __nv_bfloat16* S2  = (__nv_bfloat16*)symaddr(g_S2);
    __nv_bfloat16* vT1 = (__nv_bfloat16*)symaddr(g_vT1);
    __nv_bfloat16* vT2 = (__nv_bfloat16*)symaddr(g_vT2);
    __nv_bfloat16* P1  = (__nv_bfloat16*)symaddr(g_P1);
    __nv_bfloat16* P2  = (__nv_bfloat16*)symaddr(g_P2);
    __nv_bfloat16* W1  = (__nv_bfloat16*)symaddr(g_W1);
    __nv_bfloat16* W2  = (__nv_bfloat16*)symaddr(g_W2);
    __nv_bfloat16* W3  = (__nv_bfloat16*)symaddr(g_W3);
    __nv_bfloat16* W4  = (__nv_bfloat16*)symaddr(g_W4);
    __nv_bfloat16* dpb = (__nv_bfloat16*)symaddr(g_dpb);
    __nv_bfloat16* dab = (__nv_bfloat16*)symaddr(g_dab);

    const int FFT_SMEM  = (8192 * 2 + 2048) * 4;   // 73728
    const int GEMM_SMEM = 1024 + CTRL_OFF + 64;    // 67648
    cudaFuncSetAttribute(fft_fwd, cudaFuncAttributeMaxDynamicSharedMemorySize, FFT_SMEM);
    cudaFuncSetAttribute(fft_inv, cudaFuncAttributeMaxDynamicSharedMemorySize, FFT_SMEM);
    cudaFuncSetAttribute(gemm_attn_vt, cudaFuncAttributeMaxDynamicSharedMemorySize, GEMM_SMEM);
    cudaFuncSetAttribute(gemm_tc<2,0>, cudaFuncAttributeMaxDynamicSharedMemorySize, GEMM_SMEM);
    cudaFuncSetAttribute(gemm_tc<1,1>, cudaFuncAttributeMaxDynamicSharedMemorySize, GEMM_SMEM);

    // 1) tokens (bf16, padded) + weight conversion (one launch)
    prep_all<<<4672, 256>>>(lt1, lt2, layer, w_t2f, w_t2f2, w_df, w_df2);

    // 2) FFT2 + amp/phase (bf16)
    fft_fwd<<<1024, 512, FFT_SMEM>>>(feats);

    // 3) fused: attn = X @ T^T + softmax -> S,  and  vT = W @ T[1:]^T + b
    {
        GB g = { phb, amb, T1b, T2b, (float*)vT1, (float*)vT2, W1, W2, S1, S2 };
        gemm_attn_vt<<<dim3(1, 72, 2), 256, GEMM_SMEM>>>(g, b_t2f, b_t2f2);
    }

    // 4) P = S @ vT^T + X  -> bf16 [8192 x 1024]
    {
        GB g = { S1, S2, vT1, vT2, nullptr, nullptr, phb, amb, P1, P2 };
        gemm_tc<2,0><<<dim3(8, 64, 2), 256, GEMM_SMEM>>>(g, KP, KP, CDIM, CDIM, 2, CDIM);
    }

    // 5) d = P @ Wdf^T + b  -> bf16 [8192 x 513]
    {
        GB g = { P1, P2, W3, W4, b_df, b_df2, nullptr, nullptr, dpb, dab };
        gemm_tc<1,1><<<dim3(5, 64, 2), 256, GEMM_SMEM>>>(g, CDIM, CDIM, NZ, 0, 16, NZ);
    }

    // 6) z-build + irfft2 + residual add + cls copy (grid 1025)
    fft_inv<<<1025, 512, FFT_SMEM>>>(feats, scale, out);
}

// round 13
// speedup vs baseline: 5.5102x; 1.2058x over previous
#include <cuda_runtime.h>
#include <cuda_bf16.h>
#include <math.h>
#include <stdint.h>

#if defined(__CUDA_ARCH__) && (defined(__CUDA_ARCH_SPECIFIC__) || defined(__CUDA_ARCH_FAMILY_SPECIFIC__))
#define HAS_TCGEN05 1
#else
#define HAS_TCGEN05 0
#endif

#define MROWS 8192      // 1024 * 8 rows
#define CDIM  1024
#define KP    128       // padded token/attention dim
#define NZ    513       // kept spectrum columns
#define NUPAD 640       // padded U rows (513 -> 5 tiles of 128)

// smem bank swizzle for FFT arrays
#define SW(i) ((i) ^ (((i) >> 5) & 31))

// ---------------- scratch (device globals; no allocation allowed) ----------
__device__ __nv_bfloat16 g_phb[MROWS*CDIM];
__device__ __nv_bfloat16 g_amb[MROWS*CDIM];
__device__ __nv_bfloat16 g_T1b[144*CDIM];
__device__ __nv_bfloat16 g_T2b[144*CDIM];
__device__ __nv_bfloat16 g_S1[MROWS*KP];
__device__ __nv_bfloat16 g_S2[MROWS*KP];
__device__ __nv_bfloat16 g_vTt1[KP*CDIM];   // vT transposed: [j][c]
__device__ __nv_bfloat16 g_vTt2[KP*CDIM];
__device__ __nv_bfloat16 g_U1[NUPAD*KP];    // U = W @ vT : [o][j]
__device__ __nv_bfloat16 g_U2[NUPAD*KP];
__device__ __nv_bfloat16 g_W1[CDIM*CDIM]; // w_t2f
__device__ __nv_bfloat16 g_W2[CDIM*CDIM]; // w_t2f2
__device__ __nv_bfloat16 g_W3[CDIM*CDIM]; // w_df
__device__ __nv_bfloat16 g_W4[CDIM*CDIM]; // w_df2
__device__ __nv_bfloat16 g_dpb[MROWS*NZ];
__device__ __nv_bfloat16 g_dab[MROWS*NZ];

// ---------------- PTX helpers ----------------------------------------------
__device__ __forceinline__ uint32_t smem_u32(const void* p) {
    uint32_t a;
    asm("{ .reg .u64 t; cvta.to.shared.u64 t, %1; cvt.u32.u64 %0, t; }" : "=r"(a) : "l"(p));
    return a;
}
__device__ __forceinline__ bool elect1() {
    uint32_t p;
    asm volatile("{ .reg .pred p; elect.sync _|p, 0xFFFFFFFF; selp.b32 %0, 1, 0, p; }" : "=r"(p));
    return p != 0;
}
__device__ __forceinline__ uint64_t make_desc(uint32_t addr) {
    const uint64_t base = (uint64_t(2) << 61) | (uint64_t(1) << 46) |
                          (uint64_t(64) << 32) | (uint64_t(1) << 16);
    return base | ((addr >> 4) & 0x3FFF);
}
__device__ __forceinline__ void mbar_wait(uint32_t mbar, uint32_t parity) {
    asm volatile(
        "{\n\t.reg .pred P;\n\t"
        "WL%=:\n\t"
        "mbarrier.try_wait.parity.acquire.cta.shared::cta.b64 P, [%0], %1, 0x989680;\n\t"
        "@P bra.uni WD%=;\n\t"
        "bra.uni WL%=;\n\t"
        "WD%=:\n\t}"
        :: "r"(mbar), "r"(parity) : "memory");
}

#if HAS_TCGEN05
__device__ __forceinline__ void mma_ss_f16(uint32_t d, uint64_t ad, uint64_t bd,
                                           uint32_t idesc, bool acc) {
    uint32_t en = acc ? 1u : 0u;
    asm volatile(
        "{\n\t.reg .pred p;\n\tsetp.ne.u32 p, %4, 0;\n\t"
        "tcgen05.mma.cta_group::1.kind::f16 [%0], %1, %2, %3, {%5, %5, %5, %5}, p;\n\t}"
        :: "r"(d), "l"(ad), "l"(bd), "r"(idesc), "r"(en), "r"(0u) : "memory");
}
#define LDTM_X32(r, a) \
    asm volatile( \
        "tcgen05.ld.sync.aligned.32x32b.x32.b32 " \
        "{%0, %1, %2, %3, %4, %5, %6, %7, " \
        " %8, %9, %10, %11, %12, %13, %14, %15, " \
        " %16, %17, %18, %19, %20, %21, %22, %23, " \
        " %24, %25, %26, %27, %28, %29, %30, %31}, [%32];" \
        : "=r"((r)[0]),  "=r"((r)[1]),  "=r"((r)[2]),  "=r"((r)[3]), \
          "=r"((r)[4]),  "=r"((r)[5]),  "=r"((r)[6]),  "=r"((r)[7]), \
          "=r"((r)[8]),  "=r"((r)[9]),  "=r"((r)[10]), "=r"((r)[11]), \
          "=r"((r)[12]), "=r"((r)[13]), "=r"((r)[14]), "=r"((r)[15]), \
          "=r"((r)[16]), "=r"((r)[17]), "=r"((r)[18]), "=r"((r)[19]), \
          "=r"((r)[20]), "=r"((r)[21]), "=r"((r)[22]), "=r"((r)[23]), \
          "=r"((r)[24]), "=r"((r)[25]), "=r"((r)[26]), "=r"((r)[27]), \
          "=r"((r)[28]), "=r"((r)[29]), "=r"((r)[30]), "=r"((r)[31]) \
        : "r"(a))
#endif

// idesc: fp32 accum, bf16 A/B, M=128, N=128
#define IDESC_128 0x08200490u
#define CTRL_OFF 66560   // above 64KB tiles / 66KB softmax staging

// base-4 digit reverse of 10-bit index
__device__ __forceinline__ int rc4(int c) {
    return ((c & 3) << 8) | (((c >> 2) & 3) << 6) | (((c >> 4) & 3) << 4) |
           (((c >> 6) & 3) << 2) | ((c >> 8) & 3);
}

// fast atan2 (~2e-5 rad abs err) — delta-path only, error suppressed x1e-3
__device__ __forceinline__ float fast_atan2(float y, float x) {
    float ax = fabsf(x), ay = fabsf(y);
    float mx = fmaxf(ax, ay), mn = fminf(ax, ay);
    float a = __fdividef(mn, mx);
    float s = a * a;
    float r = a * (0.99997726f + s * (-0.33262347f + s * (0.19354346f +
              s * (-0.11643287f + s * (0.05265332f - s * 0.01172120f)))));
    if (ay > ax) r = 1.57079637f - r;
    if (x < 0.f) r = 3.14159274f - r;
    return copysignf(r, y);
}

// ---------------- prep: tokens -> bf16 padded + weights -> bf16 (one launch)
__global__ void prep_all(const float* __restrict__ lt1,
                         const float* __restrict__ lt2,
                         const int* __restrict__ layer_p,
                         const float* __restrict__ wa, const float* __restrict__ wb,
                         const float* __restrict__ wc, const float* __restrict__ wd)
{
    int blk = blockIdx.x;
    if (blk < 4096) {                       // weight conversion: 1M elements
        int i = blk * 256 + threadIdx.x;
        g_W1[i] = __float2bfloat16(wa[i]);
        g_W2[i] = __float2bfloat16(wb[i]);
        g_W3[i] = __float2bfloat16(wc[i]);
        g_W4[i] = __float2bfloat16(wd[i]);
    } else {                                // token prep: 144K elements
        int i = (blk - 4096) * 256 + threadIdx.x;
        if (i >= 144 * CDIM) return;
        int row = i >> 10;
        int layer = layer_p[0];
        float v1 = 0.f, v2 = 0.f;
        if (row < 100) {
            v1 = lt1[layer * 100 * CDIM + i];
            v2 = lt2[layer * 100 * CDIM + i];
        }
        g_T1b[i] = __float2bfloat16(v1);
        g_T2b[i] = __float2bfloat16(v2);
    }
}

// ---------------- radix-4 butterfly stages (in-place, swizzled smem) --------
__device__ __forceinline__ void fft_stages_r4(float* sre, float* sim,
                                              const float* twr, const float* twi,
                                              int tid, int dir)
{
    #pragma unroll
    for (int s = 1; s <= 5; s++) {
        int Q = 1 << (2 * (s - 1));
        int sh = 10 - 2 * s;
        for (int t = tid; t < 2048; t += 512) {
            int b = t >> 8, j = t & 255;
            int pos = j & (Q - 1);
            int i0 = (b << 10) + ((j >> (2 * (s - 1))) << (2 * s)) + pos;
            int e = pos << sh;
            float w1r = twr[e], w1i = twi[e];
            float w2r = w1r * w1r - w1i * w1i, w2i = 2.f * w1r * w1i;
            float w3r = w2r * w1r - w2i * w1i, w3i = w2r * w1i + w2i * w1r;
            int p0 = SW(i0), p1 = SW(i0 + Q), p2 = SW(i0 + 2 * Q), p3 = SW(i0 + 3 * Q);
            float a0r = sre[p0], a0i = sim[p0];
            float b1r = sre[p1], b1i = sim[p1];
            float b2r = sre[p2], b2i = sim[p2];
            float b3r = sre[p3], b3i = sim[p3];
            float x1r = b1r * w1r - b1i * w1i, x1i = b1r * w1i + b1i * w1r;
            float x2r = b2r * w2r - b2i * w2i, x2i = b2r * w2i + b2i * w2r;
            float x3r = b3r * w3r - b3i * w3i, x3i = b3r * w3i + b3i * w3r;
            float t0r = a0r + x2r, t0i = a0i + x2i;
            float t1r = a0r - x2r, t1i = a0i - x2i;
            float t2r = x1r + x3r, t2i = x1i + x3i;
            float t3r = x1r - x3r, t3i = x1i - x3i;
            sre[p0] = t0r + t2r; sim[p0] = t0i + t2i;
            sre[p2] = t0r - t2r; sim[p2] = t0i - t2i;
            if (dir < 0) {
                sre[p1] = t1r + t3i; sim[p1] = t1i - t3r;
                sre[p3] = t1r - t3i; sim[p3] = t1i + t3r;
            } else {
                sre[p1] = t1r - t3i; sim[p1] = t1i + t3r;
                sre[p3] = t1r + t3i; sim[p3] = t1i - t3r;
            }
        }
        __syncthreads();
    }
}

// ---------------- forward FFT2 + amp/phase (bf16x2 stores) ------------------
__global__ void __launch_bounds__(512) fft_fwd(const float* __restrict__ feats)
{
    extern __shared__ float sm[];
    float* sre = sm;               // 8192
    float* sim = sm + 8192;        // 8192
    float* twr = sm + 16384;       // 1024
    float* twi = twr + 1024;       // 1024
    int tid = threadIdx.x;
    int n = blockIdx.x;
    const float* x = feats + (size_t)(n + 1) * 8192;

    for (int t = tid; t < 1024; t += 512) {
        float s_, c_;
        __sincosf((float)t * -6.1359233e-3f, &s_, &c_);   // -2*pi/1024
        twr[t] = c_; twi[t] = s_;
    }
    for (int i = tid; i < 8192; i += 512) {
        int b = i >> 10, c = i & 1023;
        int p = SW((b << 10) + rc4(c));
        sre[p] = x[i];
        sim[p] = 0.f;
    }
    __syncthreads();
    fft_stages_r4(sre, sim, twr, twi, tid, -1);

    const float W8R[8] = {1.f, 0.70710678f, 0.f, -0.70710678f, -1.f, -0.70710678f, 0.f, 0.70710678f};
    const float W8I[8] = {0.f, -0.70710678f, -1.f, -0.70710678f, 0.f, 0.70710678f, 1.f, 0.70710678f};
    int c0 = tid << 1;             // two consecutive columns per thread
    float ar0[8], ai0[8], ar1[8], ai1[8];
    #pragma unroll
    for (int b = 0; b < 8; b++) {
        int p0 = SW((b << 10) + c0), p1 = SW((b << 10) + c0 + 1);
        ar0[b] = sre[p0]; ai0[b] = sim[p0];
        ar1[b] = sre[p1]; ai1[b] = sim[p1];
    }
    #pragma unroll
    for (int kb = 0; kb < 8; kb++) {
        float o0r = 0.f, o0i = 0.f, o1r = 0.f, o1i = 0.f;
        #pragma unroll
        for (int b = 0; b < 8; b++) {
            int t8 = (kb * b) & 7;
            float wr = W8R[t8], wi = W8I[t8];
            o0r += ar0[b] * wr - ai0[b] * wi;
            o0i += ar0[b] * wi + ai0[b] * wr;
            o1r += ar1[b] * wr - ai1[b] * wi;
            o1i += ar1[b] * wi + ai1[b] * wr;
        }
        float p20 = o0r * o0r + o0i * o0i; if (p20 < 1e-5f) p20 = 1e-5f;
        float p21 = o1r * o1r + o1i * o1i; if (p21 < 1e-5f) p21 = 1e-5f;
        float am0 = sqrtf(p20), am1 = sqrtf(p21);
        float rr0 = o0r; if (rr0 < 1e-5f && rr0 > -1e-5f) rr0 = 1e-5f;
        float rr1 = o1r; if (rr1 < 1e-5f && rr1 > -1e-5f) rr1 = 1e-5f;
        float ph0 = fast_atan2(o0i, rr0);
        float ph1 = fast_atan2(o1i, rr1);
        int off = (((n << 3) + kb) << 10) + c0;
        *(__nv_bfloat162*)(&g_amb[off]) = __nv_bfloat162(__float2bfloat16(am0), __float2bfloat16(am1));
        *(__nv_bfloat162*)(&g_phb[off]) = __nv_bfloat162(__float2bfloat16(ph0), __float2bfloat16(ph1));
    }
}

// ---------------- tcgen05 bf16 GEMM building blocks -------------------------
#if HAS_TCGEN05
__device__ __forceinline__ uint32_t gemm_prologue(uint32_t ctrl, int tid, int wid)
{
    if (wid == 0) {
        asm volatile("tcgen05.alloc.cta_group::1.sync.aligned.shared::cta.b32 [%0], %1;"
                     :: "r"(ctrl), "r"(128u) : "memory");
        asm volatile("tcgen05.relinquish_alloc_permit.cta_group::1.sync.aligned;");
    }
    if (tid == 0) {
        asm volatile("mbarrier.init.shared.b64 [%0], 1;" :: "r"(ctrl + 8) : "memory");
        asm volatile("mbarrier.init.shared.b64 [%0], 1;" :: "r"(ctrl + 16) : "memory");
    }
    __syncthreads();
    uint32_t tmem;
    asm volatile("ld.shared.b32 %0, [%1];" : "=r"(tmem) : "r"(ctrl));
    return tmem;
}

// Two-phase mainloop with register-prefetch pipeline.
// Chunks [0, nk1) read A1/B1 (lda1/ldb1); chunks [nk1, nk) read A2/B2.
// All pointers pre-adjusted to the tile's row0/col0.
__device__ __forceinline__ void gemm_mainloop2(
    const __nv_bfloat16* A1, int lda1, const __nv_bfloat16* A2, int lda2,
    const __nv_bfloat16* B1, int ldb1, const __nv_bfloat16* B2, int ldb2,
    int nk1, int nk, char* tp, uint32_t ta, uint32_t ctrl,
    uint32_t tmem, int tid, int wid)
{
    const int abase[2] = {0, 16384};
    const int bbase[2] = {32768, 49152};
    int ph[2] = {0, 0};

    const __nv_bfloat16 *ap1[4], *ap2[4], *bp1[4], *bp2[4];
    uint32_t so[4];
    #pragma unroll
    for (int it = 0; it < 4; it++) {
        int u = tid + (it << 8);
        int r = u >> 3, s = u & 7;
        ap1[it] = A1 + (size_t)r * lda1 + (s << 3);
        ap2[it] = A2 + (size_t)r * lda2 + (s << 3);
        bp1[it] = B1 + (size_t)r * ldb1 + (s << 3);
        bp2[it] = B2 + (size_t)r * ldb2 + (s << 3);
        uint32_t bo = (r << 7) + (s << 4);
        so[it] = bo ^ ((bo >> 3) & 0x70);
    }
    uint4 ra[4], rb[4];
    #pragma unroll
    for (int it = 0; it < 4; it++) { ra[it] = *(const uint4*)ap1[it]; rb[it] = *(const uint4*)bp1[it]; }

    for (int c = 0; c < nk; c++) {
        int b = c & 1;
        if (c >= 2) { mbar_wait(ctrl + 8 + b * 8, (uint32_t)ph[b]); ph[b] ^= 1; }
        #pragma unroll
        for (int it = 0; it < 4; it++) {
            *(uint4*)(tp + abase[b] + so[it]) = ra[it];
            *(uint4*)(tp + bbase[b] + so[it]) = rb[it];
        }
        int cn = c + 1;
        if (cn < nk) {
            if (cn < nk1) {
                int k1 = cn << 6;
                #pragma unroll
                for (int it = 0; it < 4; it++) {
                    ra[it] = *(const uint4*)(ap1[it] + k1);
                    rb[it] = *(const uint4*)(bp1[it] + k1);
                }
            } else {
                int k2 = (cn - nk1) << 6;
                #pragma unroll
                for (int it = 0; it < 4; it++) {
                    ra[it] = *(const uint4*)(ap2[it] + k2);
                    rb[it] = *(const uint4*)(bp2[it] + k2);
                }
            }
        }
        asm volatile("fence.proxy.async.shared::cta;" ::: "memory");
        __syncthreads();
        if (wid == 0 && elect1()) {
            uint64_t ad = make_desc(ta + abase[b]);
            uint64_t bd = make_desc(ta + bbase[b]);
            #pragma unroll
            for (int kk = 0; kk < 4; kk++)
                mma_ss_f16(tmem, ad + kk * 2, bd + kk * 2, IDESC_128, (c | kk) != 0);
            asm volatile(
                "tcgen05.commit.cta_group::1.mbarrier::arrive::one.shared::cluster.b64 [%0];"
                :: "r"(ctrl + 8 + b * 8) : "memory");
        }
    }
    mbar_wait(ctrl + 8, (uint32_t)ph[0]);
    mbar_wait(ctrl + 16, (uint32_t)ph[1]);
    asm volatile("tcgen05.fence::after_thread_sync;" ::: "memory");
    __syncthreads();
}
#endif

// ---------------- fused attn(+softmax) / vT(transposed) launch --------------
struct GAV {
    const __nv_bfloat16 *X0, *X1;      // phb, amb
    const __nv_bfloat16 *T0, *T1;      // tokens
    const __nv_bfloat16 *W0, *W1;      // w_t2f weights (bf16)
    const float *bias0, *bias1;        // b_t2f
    __nv_bfloat16 *S0, *S1;            // softmax out
    __nv_bfloat16 *V0, *V1;            // vT transposed out [j][c]
};

// grid (1, 72, 2): y<64 -> attn rows (softmax epilogue), y>=64 -> vT rows
__global__ void __launch_bounds__(256, 2) gemm_attn_vt(GAV g)
{
    extern __shared__ char sm_[];
    int tid = threadIdx.x;
    int z = blockIdx.z;
    bool is_vt = (blockIdx.y >= 64);
    int row0 = (is_vt ? ((int)blockIdx.y - 64) : (int)blockIdx.y) << 7;
    const __nv_bfloat16* A = is_vt ? (z ? g.W1 : g.W0) : (z ? g.X1 : g.X0);
    const __nv_bfloat16* Bm = (z ? g.T1 : g.T0) + (is_vt ? CDIM : 0);
    const float* bias = z ? g.bias1 : g.bias0;

#if HAS_TCGEN05
    uint32_t sb = smem_u32(sm_);
    uint32_t ta = (sb + 1023u) & ~1023u;
    char* tp = sm_ + (ta - sb);
    uint32_t ctrl = ta + CTRL_OFF;
    int wid = tid >> 5, lane = tid & 31;
    uint32_t tmem = gemm_prologue(ctrl, tid, wid);
    gemm_mainloop2(A + (size_t)row0 * CDIM, CDIM, A, CDIM, Bm, CDIM, Bm, CDIM,
                   16, 16, tp, ta, ctrl, tmem, tid, wid);

    int sub = wid & 3, half = wid >> 2;
    int rsub = (sub << 5) + lane;

    if (!is_vt) {
        // fused softmax epilogue: stage 128x128 tile (stride 129)
        float* smf = (float*)tp;
        #pragma unroll
        for (int q = 0; q < 2; q++) {
            int cb = (half << 1) + q;
            uint32_t r_[32];
            LDTM_X32(r_, tmem + (cb << 5));
            asm volatile("tcgen05.wait::ld.sync.aligned;" ::: "memory");
            #pragma unroll
            for (int j = 0; j < 32; j++)
                smf[rsub * 129 + (cb << 5) + j] = __uint_as_float(r_[j]);
        }
        __syncthreads();
        bool inorm = (z != 0);
        __nv_bfloat16* Srow = z ? g.S1 : g.S0;
        for (int r = wid; r < 128; r += 8) {
            const float* a = smf + r * 129;
            float v[4]; bool val[4];
            #pragma unroll
            for (int q = 0; q < 4; q++) {
                int idx = lane + 32 * q;
                val[q] = idx < 100;
                v[q] = val[q] ? a[idx] : 0.f;
            }
            if (inorm) {
                float s = v[0] + v[1] + v[2] + v[3];
                #pragma unroll
                for (int off = 16; off > 0; off >>= 1) s += __shfl_xor_sync(0xffffffffu, s, off);
                float mu = s * 0.01f;
                float s2 = 0.f;
                #pragma unroll
                for (int q = 0; q < 4; q++) if (val[q]) { float d = v[q] - mu; s2 += d * d; }
                #pragma unroll
                for (int off = 16; off > 0; off >>= 1) s2 += __shfl_xor_sync(0xffffffffu, s2, off);
                float inv = rsqrtf(s2 * 0.01f + 1e-5f);
                #pragma unroll
                for (int q = 0; q < 4; q++) v[q] = (v[q] - mu) * inv;
            }
            float m = -1e30f;
            #pragma unroll
            for (int q = 0; q < 4; q++) if (val[q]) m = fmaxf(m, v[q] * 0.03125f);
            #pragma unroll
            for (int off = 16; off > 0; off >>= 1) m = fmaxf(m, __shfl_xor_sync(0xffffffffu, m, off));
            float e[4]; float se = 0.f;
            #pragma unroll
            for (int q = 0; q < 4; q++) {
                e[q] = val[q] ? __expf(v[q] * 0.03125f - m) : 0.f;
                se += e[q];
            }
            #pragma unroll
            for (int off = 16; off > 0; off >>= 1) se += __shfl_xor_sync(0xffffffffu, se, off);
            float rinv = __fdividef(1.f, se);
            __nv_bfloat16* o = Srow + (size_t)(row0 + r) * KP;
            #pragma unroll
            for (int q = 0; q < 4; q++) {
                int idx = lane + 32 * q;
                if (idx >= 1 && idx < 100) o[idx - 1] = __float2bfloat16(e[q] * rinv);
                else if (idx >= 100) o[idx - 1] = __float2bfloat16(0.f);
                else o[127] = __float2bfloat16(0.f);
            }
        }
    } else {
        // vT epilogue, TRANSPOSED output: V[j][c] = acc[c][j] + bias[c].
        // Direct register->global; consecutive rsub -> consecutive c: coalesced.
        __nv_bfloat16* V = z ? g.V1 : g.V0;
        float biasr = bias[row0 + rsub];
        #pragma unroll
        for (int q = 0; q < 2; q++) {
            int cb = (half << 1) + q;
            uint32_t r_[32];
            LDTM_X32(r_, tmem + (cb << 5));
            asm volatile("tcgen05.wait::ld.sync.aligned;" ::: "memory");
            #pragma unroll
            for (int j = 0; j < 32; j++) {
                int jj = (cb << 5) + j;
                V[(size_t)jj * CDIM + row0 + rsub] =
                    __float2bfloat16(__uint_as_float(r_[j]) + biasr);
            }
        }
    }
    __syncthreads();
    if (wid == 0) {
        asm volatile("tcgen05.dealloc.cta_group::1.sync.aligned.b32 %0, %1;"
                     :: "r"(tmem), "r"(128u));
    }
#else
    (void)sm_;
    if (tid < 128) {
        int row = row0 + tid;
        float acc_row[128];
        for (int cc = 0; cc < 128; cc++) {
            float acc = 0.f;
            for (int k = 0; k < 1024; k++)
                acc += __bfloat162float(A[(size_t)row * CDIM + k]) *
                       __bfloat162float(Bm[(size_t)cc * CDIM + k]);
            acc_row[cc] = acc;
        }
        if (is_vt) {
            __nv_bfloat16* V = z ? g.V1 : g.V0;
            for (int cc = 0; cc < 128; cc++)
                V[(size_t)cc * CDIM + row] = __float2bfloat16(acc_row[cc] + bias[row]);
        } else {
            bool inorm = (z != 0);
            if (inorm) {
                float s = 0.f;
                for (int i = 0; i < 100; i++) s += acc_row[i];
                float mu = s * 0.01f, s2 = 0.f;
                for (int i = 0; i < 100; i++) { float d = acc_row[i] - mu; s2 += d * d; }
                float inv = rsqrtf(s2 * 0.01f + 1e-5f);
                for (int i = 0; i < 100; i++) acc_row[i] = (acc_row[i] - mu) * inv;
            }
            float m = -1e30f;
            for (int i = 0; i < 100; i++) m = fmaxf(m, acc_row[i] * 0.03125f);
            float se = 0.f;
            for (int i = 0; i < 100; i++) { acc_row[i] = expf(acc_row[i] * 0.03125f - m); se += acc_row[i]; }
            float rinv = 1.f / se;
            __nv_bfloat16* o = (z ? g.S1 : g.S0) + (size_t)row * KP;
            for (int i = 1; i < 100; i++) o[i - 1] = __float2bfloat16(acc_row[i] * rinv);
            for (int i = 99; i < 128; i++) o[i] = __float2bfloat16(0.f);
        }
    }
#endif
}

// ---------------- generic two-phase GEMM, bf16 out, optional col bias -------
struct GG {
    const __nv_bfloat16 *A10, *A11, *A20, *A21;
    const __nv_bfloat16 *B10, *B11, *B20, *B21;
    const float *bias0, *bias1;
    __nv_bfloat16 *C0, *C1;
};

template<int BIAS>
__global__ void __launch_bounds__(256, 2) gemm_tc(GG g, int lda1, int lda2,
                                                  int ldb1, int ldb2, int ldc,
                                                  int nk1, int nk, int nguard)
{
    extern __shared__ char sm_[];
    int tid = threadIdx.x;
    int z = blockIdx.z;
    const __nv_bfloat16* A1 = z ? g.A11 : g.A10;
    const __nv_bfloat16* A2 = z ? g.A21 : g.A20;
    const __nv_bfloat16* B1 = z ? g.B11 : g.B10;
    const __nv_bfloat16* B2 = z ? g.B21 : g.B20;
    const float* bias = z ? g.bias1 : g.bias0;
    __nv_bfloat16* C = z ? g.C1 : g.C0;
    int row0 = blockIdx.y << 7, col0 = blockIdx.x << 7;

#if HAS_TCGEN05
    uint32_t sb = smem_u32(sm_);
    uint32_t ta = (sb + 1023u) & ~1023u;
    char* tp = sm_ + (ta - sb);
    uint32_t ctrl = ta + CTRL_OFF;
    int wid = tid >> 5, lane = tid & 31;
    uint32_t tmem = gemm_prologue(ctrl, tid, wid);
    gemm_mainloop2(A1 + (size_t)row0 * lda1, lda1, A2 + (size_t)row0 * lda2, lda2,
                   B1 + (size_t)col0 * ldb1, ldb1, B2 + (size_t)col0 * ldb2, ldb2,
                   nk1, nk, tp, ta, ctrl, tmem, tid, wid);

    int sub = wid & 3, half = wid >> 2;
    int rsub = (sub << 5) + lane;
    float* smf = (float*)tp + half * 4224;
    int barid = 1 + half;
    #pragma unroll
    for (int q = 0; q < 2; q++) {
        int cb = (half << 1) + q;
        uint32_t r_[32];
        LDTM_X32(r_, tmem + (cb << 5));
        asm volatile("tcgen05.wait::ld.sync.aligned;" ::: "memory");
        asm volatile("bar.sync %0, 128;" :: "r"(barid) : "memory");
        #pragma unroll
        for (int j = 0; j < 32; j++) smf[rsub * 33 + j] = __uint_as_float(r_[j]);
        asm volatile("bar.sync %0, 128;" :: "r"(barid) : "memory");
        #pragma unroll
        for (int i = 0; i < 32; i++) {
            int idx = rsub + (i << 7);
            int orow = idx >> 5, ocol = idx & 31;
            int cc = col0 + (cb << 5) + ocol;
            if (cc < nguard) {
                float v = smf[orow * 33 + ocol];
                if (BIAS == 1) v += bias[cc];
                C[(size_t)(row0 + orow) * ldc + cc] = __float2bfloat16(v);
            }
        }
    }
    __syncthreads();
    if (wid == 0) {
        asm volatile("tcgen05.dealloc.cta_group::1.sync.aligned.b32 %0, %1;"
                     :: "r"(tmem), "r"(128u));
    }
#else
    (void)sm_;
    if (tid < 128) {
        int row = row0 + tid;
        for (int cc = 0; cc < 128; cc++) {
            int c = col0 + cc;
            if (c >= nguard) continue;
            float acc = 0.f;
            for (int ch = 0; ch < nk; ch++) {
                const __nv_bfloat16* Ar = (ch < nk1)
                    ? A1 + (size_t)row * lda1 + (ch << 6)
                    : A2 + (size_t)row * lda2 + ((ch - nk1) << 6);
                const __nv_bfloat16* Br = (ch < nk1)
                    ? B1 + (size_t)c * ldb1 + (ch << 6)
                    : B2 + (size_t)c * ldb2 + ((ch - nk1) << 6);
                for (int k = 0; k < 64; k++)
                    acc += __bfloat162float(Ar[k]) * __bfloat162float(Br[k]);
            }
            if (BIAS == 1) acc += bias[c];
            C[(size_t)row * ldc + c] = __float2bfloat16(acc);
        }
    }
#endif
}

// ---------------- inverse: z-build + ifft_b(8) + Hermitian irfft -> out ----
// grid 1025: block 1024 handles the cls-row passthrough
__global__ void __launch_bounds__(512) fft_inv(const float* __restrict__ feats,
                                               const float* __restrict__ scale_p,
                                               float* __restrict__ out)
{
    int tid = threadIdx.x;
    int n = blockIdx.x;
    if (n == 1024) {               // cls row copy: 8192 floats
        for (int i = tid; i < 8192; i += 512) out[i] = feats[i];
        return;
    }
    extern __shared__ float sm[];
    float* sre = sm;               // 8192
    float* sim = sm + 8192;        // 8192
    float* twr = sm + 16384;       // 1024
    float* twi = twr + 1024;       // 1024

    for (int t = tid; t < 1024; t += 512) {
        float s_, c_;
        __sincosf((float)t * 6.1359233e-3f, &s_, &c_);    // +2*pi/1024
        twr[t] = c_; twi[t] = s_;
    }
    __syncthreads();

    const float W8R[8] = {1.f, 0.70710678f, 0.f, -0.70710678f, -1.f, -0.70710678f, 0.f, 0.70710678f};
    const float W8I[8] = {0.f, -0.70710678f, -1.f, -0.70710678f, 0.f, 0.70710678f, 1.f, 0.70710678f};

    for (int c = tid; c < 513; c += 512) {
        float zr_[8], zi_[8];
        #pragma unroll
        for (int b = 0; b < 8; b++) {
            size_t off = (size_t)((n << 3) + b) * NZ + c;
            float phv = __bfloat162float(g_dpb[off]);
            float amv = __bfloat162float(g_dab[off]);
            float s_, c_;
            __sincosf(phv, &s_, &c_);
            zr_[b] = c_ * amv;
            zi_[b] = s_ * amv;
        }
        int rcp = rc4(c);
        int rcm = rc4((1024 - c) & 1023);
        bool mir = (c != 0) && (c != 512);
        #pragma unroll
        for (int b = 0; b < 8; b++) {
            float orr = 0.f, oii = 0.f;
            #pragma unroll
            for (int kb = 0; kb < 8; kb++) {
                int t8 = (kb * b) & 7;
                float wr = W8R[t8], wi = -W8I[t8];
                orr += zr_[kb] * wr - zi_[kb] * wi;
                oii += zr_[kb] * wi + zi_[kb] * wr;
            }
            int p1 = SW((b << 10) + rcp);
            sre[p1] = orr; sim[p1] = oii;
            if (mir) {
                int p2 = SW((b << 10) + rcm);
                sre[p2] = orr; sim[p2] = -oii;
            }
        }
    }
    __syncthreads();
    fft_stages_r4(sre, sim, twr, twi, tid, +1);

    float sc = scale_p[0];
    for (int i = tid; i < 8192; i += 512) {
        int b = i >> 10, c = i & 1023;
        float d = sre[SW((b << 10) + c)] * (1.0f / 4096.0f);
        size_t off = ((size_t)(n + 1) * 8 + b) * 1024 + c;
        out[off] = feats[off] + d * sc;
    }
}

// ---------------- host ------------------------------------------------------
static void* symaddr(const void* s)
{
    void* p = nullptr;
    cudaGetSymbolAddress(&p, s);
    return p;
}

extern "C" void kernel_launch(void* const* d_in, const int* in_sizes, int n_in,
                              void* d_out, int out_size)
{
    (void)in_sizes; (void)n_in; (void)out_size;
    const float* feats  = (const float*)d_in[0];
    const float* lt1    = (const float*)d_in[1];
    const float* lt2    = (const float*)d_in[2];
    const float* w_t2f  = (const float*)d_in[3];
    const float* b_t2f  = (const float*)d_in[4];
    const float* w_df   = (const float*)d_in[5];
    const float* b_df   = (const float*)d_in[6];
    const float* w_t2f2 = (const float*)d_in[7];
    const float* b_t2f2 = (const float*)d_in[8];
    const float* w_df2  = (const float*)d_in[9];
    const float* b_df2  = (const float*)d_in[10];
    const float* scale  = (const float*)d_in[11];
    const int*   layer  = (const int*)d_in[12];
    float* out = (float*)d_out;

    __nv_bfloat16* phb  = (__nv_bfloat16*)symaddr(g_phb);
    __nv_bfloat16* amb  = (__nv_bfloat16*)symaddr(g_amb);
    __nv_bfloat16* T1b  = (__nv_bfloat16*)symaddr(g_T1b);
    __nv_bfloat16* T2b  = (__nv_bfloat16*)symaddr(g_T2b);
    __nv_bfloat16* S1   = (__nv_bfloat16*)symaddr(g_S1);
    __nv_bfloat16* S2   = (__nv_bfloat16*)symaddr(g_S2);
    __nv_bfloat16* vTt1 = (__nv_bfloat16*)symaddr(g_vTt1);
    __nv_bfloat16* vTt2 = (__nv_bfloat16*)symaddr(g_vTt2);
    __nv_bfloat16* U1   = (__nv_bfloat16*)symaddr(g_U1);
    __nv_bfloat16* U2   = (__nv_bfloat16*)symaddr(g_U2);
    __nv_bfloat16* W1   = (__nv_bfloat16*)symaddr(g_W1);
    __nv_bfloat16* W2   = (__nv_bfloat16*)symaddr(g_W2);
    __nv_bfloat16* W3   = (__nv_bfloat16*)symaddr(g_W3);
    __nv_bfloat16* W4   = (__nv_bfloat16*)symaddr(g_W4);
    __nv_bfloat16* dpb  = (__nv_bfloat16*)symaddr(g_dpb);
    __nv_bfloat16* dab  = (__nv_bfloat16*)symaddr(g_dab);

    const int FFT_SMEM  = (8192 * 2 + 2048) * 4;   // 73728
    const int GEMM_SMEM = 1024 + CTRL_OFF + 64;    // 67648
    cudaFuncSetAttribute(fft_fwd, cudaFuncAttributeMaxDynamicSharedMemorySize, FFT_SMEM);
    cudaFuncSetAttribute(fft_inv, cudaFuncAttributeMaxDynamicSharedMemorySize, FFT_SMEM);
    cudaFuncSetAttribute(gemm_attn_vt, cudaFuncAttributeMaxDynamicSharedMemorySize, GEMM_SMEM);
    cudaFuncSetAttribute(gemm_tc<0>, cudaFuncAttributeMaxDynamicSharedMemorySize, GEMM_SMEM);
    cudaFuncSetAttribute(gemm_tc<1>, cudaFuncAttributeMaxDynamicSharedMemorySize, GEMM_SMEM);

    // 1) tokens (bf16, padded) + weight conversion (one launch)
    prep_all<<<4672, 256>>>(lt1, lt2, layer, w_t2f, w_t2f2, w_df, w_df2);

    // 2) FFT2 + amp/phase (bf16)
    fft_fwd<<<1024, 512, FFT_SMEM>>>(feats);

    // 3) fused: attn = X @ T^T + softmax -> S,  and  vTt = (W @ T[1:]^T + b)^T
    {
        GAV g = { phb, amb, T1b, T2b, W1, W2, b_t2f, b_t2f2, S1, S2, vTt1, vTt2 };
        gemm_attn_vt<<<dim3(1, 72, 2), 256, GEMM_SMEM>>>(g);
    }

    // 4) U = Wdf @ vT : [640 x 128] bf16  (A = W3/W4, B = vTt)
    {
        GG g = { W3, W4, W3, W4, vTt1, vTt2, vTt1, vTt2, nullptr, nullptr, U1, U2 };
        gemm_tc<0><<<dim3(1, 5, 2), 256, GEMM_SMEM>>>(g, CDIM, CDIM, CDIM, CDIM,
                                                      KP, 16, 16, KP);
    }

    // 5) d = [X | S] @ [Wdf | U]^T + b  -> bf16 [8192 x 513], K = 1152
    {
        GG g = { phb, amb, S1, S2, W3, W4, U1, U2, b_df, b_df2, dpb, dab };
        gemm_tc<1><<<dim3(5, 64, 2), 256, GEMM_SMEM>>>(g, CDIM, KP, CDIM, KP,
                                                       NZ, 16, 18, NZ);
    }

    // 6) z-build + irfft2 + residual add + cls copy (grid 1025)
    fft_inv<<<1025, 512, FFT_SMEM>>>(feats, scale, out);
}

// round 15
// speedup vs baseline: 7.0689x; 1.2829x over previous
#include <cuda_runtime.h>
#include <cuda_bf16.h>
#include <math.h>
#include <stdint.h>

#if defined(__CUDA_ARCH__) && (defined(__CUDA_ARCH_SPECIFIC__) || defined(__CUDA_ARCH_FAMILY_SPECIFIC__))
#define HAS_TCGEN05 1
#else
#define HAS_TCGEN05 0
#endif

#define MROWS 8192      // 1024 * 8 rows
#define CDIM  1024
#define KP    128       // padded token/attention dim
#define NZ    513       // kept spectrum columns
#define NUPAD 640       // padded U rows

// smem bank swizzle for FFT arrays
#define SW(i) ((i) ^ (((i) >> 5) & 31))

// ---------------- scratch (device globals; no allocation allowed) ----------
__device__ __nv_bfloat16 g_phb[MROWS*CDIM];
__device__ __nv_bfloat16 g_amb[MROWS*CDIM];
__device__ __nv_bfloat16 g_T1b[144*CDIM];
__device__ __nv_bfloat16 g_T2b[144*CDIM];
__device__ __nv_bfloat16 g_S1[MROWS*KP];
__device__ __nv_bfloat16 g_S2[MROWS*KP];
__device__ __nv_bfloat16 g_vTt1[KP*CDIM];   // vT transposed: [j][c]
__device__ __nv_bfloat16 g_vTt2[KP*CDIM];
__device__ __nv_bfloat16 g_U1[NUPAD*KP];    // U = W @ vT : [o][j]
__device__ __nv_bfloat16 g_U2[NUPAD*KP];
__device__ __nv_bfloat16 g_W1[CDIM*CDIM]; // w_t2f
__device__ __nv_bfloat16 g_W2[CDIM*CDIM]; // w_t2f2
__device__ __nv_bfloat16 g_W3[CDIM*CDIM]; // w_df
__device__ __nv_bfloat16 g_W4[CDIM*CDIM]; // w_df2
__device__ __nv_bfloat16 g_dpb[MROWS*NZ];
__device__ __nv_bfloat16 g_dab[MROWS*NZ];

// ---------------- PTX helpers ----------------------------------------------
__device__ __forceinline__ uint32_t smem_u32(const void* p) {
    uint32_t a;
    asm("{ .reg .u64 t; cvta.to.shared.u64 t, %1; cvt.u32.u64 %0, t; }" : "=r"(a) : "l"(p));
    return a;
}
__device__ __forceinline__ bool elect1() {
    uint32_t p;
    asm volatile("{ .reg .pred p; elect.sync _|p, 0xFFFFFFFF; selp.b32 %0, 1, 0, p; }" : "=r"(p));
    return p != 0;
}
__device__ __forceinline__ uint64_t make_desc(uint32_t addr) {
    const uint64_t base = (uint64_t(2) << 61) | (uint64_t(1) << 46) |
                          (uint64_t(64) << 32) | (uint64_t(1) << 16);
    return base | ((addr >> 4) & 0x3FFF);
}
__device__ __forceinline__ void mbar_wait(uint32_t mbar, uint32_t parity) {
    asm volatile(
        "{\n\t.reg .pred P;\n\t"
        "WL%=:\n\t"
        "mbarrier.try_wait.parity.acquire.cta.shared::cta.b64 P, [%0], %1, 0x989680;\n\t"
        "@P bra.uni WD%=;\n\t"
        "bra.uni WL%=;\n\t"
        "WD%=:\n\t}"
        :: "r"(mbar), "r"(parity) : "memory");
}

#if HAS_TCGEN05
__device__ __forceinline__ void mma_ss_f16(uint32_t d, uint64_t ad, uint64_t bd,
                                           uint32_t idesc, bool acc) {
    uint32_t en = acc ? 1u : 0u;
    asm volatile(
        "{\n\t.reg .pred p;\n\tsetp.ne.u32 p, %4, 0;\n\t"
        "tcgen05.mma.cta_group::1.kind::f16 [%0], %1, %2, %3, {%5, %5, %5, %5}, p;\n\t}"
        :: "r"(d), "l"(ad), "l"(bd), "r"(idesc), "r"(en), "r"(0u) : "memory");
}
#define LDTM_X32(r, a) \
    asm volatile( \
        "tcgen05.ld.sync.aligned.32x32b.x32.b32 " \
        "{%0, %1, %2, %3, %4, %5, %6, %7, " \
        " %8, %9, %10, %11, %12, %13, %14, %15, " \
        " %16, %17, %18, %19, %20, %21, %22, %23, " \
        " %24, %25, %26, %27, %28, %29, %30, %31}, [%32];" \
        : "=r"((r)[0]),  "=r"((r)[1]),  "=r"((r)[2]),  "=r"((r)[3]), \
          "=r"((r)[4]),  "=r"((r)[5]),  "=r"((r)[6]),  "=r"((r)[7]), \
          "=r"((r)[8]),  "=r"((r)[9]),  "=r"((r)[10]), "=r"((r)[11]), \
          "=r"((r)[12]), "=r"((r)[13]), "=r"((r)[14]), "=r"((r)[15]), \
          "=r"((r)[16]), "=r"((r)[17]), "=r"((r)[18]), "=r"((r)[19]), \
          "=r"((r)[20]), "=r"((r)[21]), "=r"((r)[22]), "=r"((r)[23]), \
          "=r"((r)[24]), "=r"((r)[25]), "=r"((r)[26]), "=r"((r)[27]), \
          "=r"((r)[28]), "=r"((r)[29]), "=r"((r)[30]), "=r"((r)[31]) \
        : "r"(a))
#endif

// idesc: fp32 accum, bf16 A/B, M=128, N=128
#define IDESC_128 0x08200490u
#define CTRL_OFF 66560   // above 64KB tiles / 66KB softmax staging

// base-4 digit reverse of 10-bit index
__device__ __forceinline__ int rc4(int c) {
    return ((c & 3) << 8) | (((c >> 2) & 3) << 6) | (((c >> 4) & 3) << 4) |
           (((c >> 6) & 3) << 2) | ((c >> 8) & 3);
}

// fast atan2 (~2e-5 rad abs err) — delta-path only, error suppressed x1e-3
__device__ __forceinline__ float fast_atan2(float y, float x) {
    float ax = fabsf(x), ay = fabsf(y);
    float mx = fmaxf(ax, ay), mn = fminf(ax, ay);
    float a = __fdividef(mn, mx);
    float s = a * a;
    float r = a * (0.99997726f + s * (-0.33262347f + s * (0.19354346f +
              s * (-0.11643287f + s * (0.05265332f - s * 0.01172120f)))));
    if (ay > ax) r = 1.57079637f - r;
    if (x < 0.f) r = 3.14159274f - r;
    return copysignf(r, y);
}

// ---------------- prep: tokens -> bf16 padded + weights -> bf16 (one launch)
__global__ void prep_all(const float* __restrict__ lt1,
                         const float* __restrict__ lt2,
                         const int* __restrict__ layer_p,
                         const float* __restrict__ wa, const float* __restrict__ wb,
                         const float* __restrict__ wc, const float* __restrict__ wd)
{
    int blk = blockIdx.x;
    if (blk < 4096) {
        int i = blk * 256 + threadIdx.x;
        g_W1[i] = __float2bfloat16(wa[i]);
        g_W2[i] = __float2bfloat16(wb[i]);
        g_W3[i] = __float2bfloat16(wc[i]);
        g_W4[i] = __float2bfloat16(wd[i]);
    } else {
        int i = (blk - 4096) * 256 + threadIdx.x;
        if (i >= 144 * CDIM) return;
        int row = i >> 10;
        int layer = layer_p[0];
        float v1 = 0.f, v2 = 0.f;
        if (row < 100) {
            v1 = lt1[layer * 100 * CDIM + i];
            v2 = lt2[layer * 100 * CDIM + i];
        }
        g_T1b[i] = __float2bfloat16(v1);
        g_T2b[i] = __float2bfloat16(v2);
    }
}

// ---------------- radix-4 butterfly stages (4 packed rows, swizzled smem) ---
__device__ __forceinline__ void fft_stages_r4(float* sre, float* sim,
                                              const float* twr, const float* twi,
                                              int tid, int dir)
{
    #pragma unroll
    for (int s = 1; s <= 5; s++) {
        int Q = 1 << (2 * (s - 1));
        int sh = 10 - 2 * s;
        #pragma unroll 2
        for (int t = tid; t < 1024; t += 512) {
            int b = t >> 8, j = t & 255;
            int pos = j & (Q - 1);
            int i0 = (b << 10) + ((j >> (2 * (s - 1))) << (2 * s)) + pos;
            int e = pos << sh;
            float w1r = twr[e], w1i = twi[e];
            float w2r = w1r * w1r - w1i * w1i, w2i = 2.f * w1r * w1i;
            float w3r = w2r * w1r - w2i * w1i, w3i = w2r * w1i + w2i * w1r;
            int p0 = SW(i0), p1 = SW(i0 + Q), p2 = SW(i0 + 2 * Q), p3 = SW(i0 + 3 * Q);
            float a0r = sre[p0], a0i = sim[p0];
            float b1r = sre[p1], b1i = sim[p1];
            float b2r = sre[p2], b2i = sim[p2];
            float b3r = sre[p3], b3i = sim[p3];
            float x1r = b1r * w1r - b1i * w1i, x1i = b1r * w1i + b1i * w1r;
            float x2r = b2r * w2r - b2i * w2i, x2i = b2r * w2i + b2i * w2r;
            float x3r = b3r * w3r - b3i * w3i, x3i = b3r * w3i + b3i * w3r;
            float t0r = a0r + x2r, t0i = a0i + x2i;
            float t1r = a0r - x2r, t1i = a0i - x2i;
            float t2r = x1r + x3r, t2i = x1i + x3i;
            float t3r = x1r - x3r, t3i = x1i - x3i;
            sre[p0] = t0r + t2r; sim[p0] = t0i + t2i;
            sre[p2] = t0r - t2r; sim[p2] = t0i - t2i;
            if (dir < 0) {
                sre[p1] = t1r + t3i; sim[p1] = t1i - t3r;
                sre[p3] = t1r - t3i; sim[p3] = t1i + t3r;
            } else {
                sre[p1] = t1r - t3i; sim[p1] = t1i + t3r;
                sre[p3] = t1r + t3i; sim[p3] = t1i - t3r;
            }
        }
        __syncthreads();
    }
}

// ---------------- forward FFT2 + amp/phase (real-pair packed) ---------------
// v_j = x[2j] + i*x[2j+1]; 4 complex 1024-pt FFTs; unpack via Hermitian split.
__global__ void __launch_bounds__(512) fft_fwd(const float* __restrict__ feats)
{
    extern __shared__ float sm[];
    float* sre = sm;               // 4096
    float* sim = sm + 4096;        // 4096
    float* twr = sm + 8192;        // 1024
    float* twi = twr + 1024;       // 1024
    int tid = threadIdx.x;
    int n = blockIdx.x;
    const float* x = feats + (size_t)(n + 1) * 8192;

    for (int t = tid; t < 1024; t += 512) {
        float s_, c_;
        __sincosf((float)t * -6.1359233e-3f, &s_, &c_);   // -2*pi/1024
        twr[t] = c_; twi[t] = s_;
    }
    // pack rows (2j, 2j+1) -> complex row j, base-4 digit-reversed
    for (int i = tid; i < 4096; i += 512) {
        int j = i >> 10, c = i & 1023;
        int p = SW((j << 10) + rc4(c));
        sre[p] = x[((j << 1) << 10) + c];
        sim[p] = x[(((j << 1) + 1) << 10) + c];
    }
    __syncthreads();
    fft_stages_r4(sre, sim, twr, twi, tid, -1);

    const float W8R[8] = {1.f, 0.70710678f, 0.f, -0.70710678f, -1.f, -0.70710678f, 0.f, 0.70710678f};
    const float W8I[8] = {0.f, -0.70710678f, -1.f, -0.70710678f, 0.f, 0.70710678f, 1.f, 0.70710678f};
    int c0 = tid << 1;             // two consecutive columns per thread
    int mc0 = (1024 - c0) & 1023;
    int mc1 = 1023 - c0;           // = (1024 - (c0+1)) & 1023 for c0 in [0,1022]
    // unpack: F2j = (Zp + conj(Zm))/2 ; F2j+1 = -i(Zp - conj(Zm))/2
    float F0r[8], F0i[8], F1r[8], F1i[8];
    #pragma unroll
    for (int j = 0; j < 4; j++) {
        int base = j << 10;
        float zpr0 = sre[SW(base + c0)],  zpi0 = sim[SW(base + c0)];
        float zmr0 = sre[SW(base + mc0)], zmi0 = sim[SW(base + mc0)];
        F0r[2*j]   = 0.5f * (zpr0 + zmr0);
        F0i[2*j]   = 0.5f * (zpi0 - zmi0);
        F0r[2*j+1] = 0.5f * (zpi0 + zmi0);
        F0i[2*j+1] = 0.5f * (zmr0 - zpr0);
        float zpr1 = sre[SW(base + c0 + 1)], zpi1 = sim[SW(base + c0 + 1)];
        float zmr1 = sre[SW(base + mc1)],    zmi1 = sim[SW(base + mc1)];
        F1r[2*j]   = 0.5f * (zpr1 + zmr1);
        F1i[2*j]   = 0.5f * (zpi1 - zmi1);
        F1r[2*j+1] = 0.5f * (zpi1 + zmi1);
        F1i[2*j+1] = 0.5f * (zmr1 - zpr1);
    }
    #pragma unroll
    for (int kb = 0; kb < 8; kb++) {
        float o0r = 0.f, o0i = 0.f, o1r = 0.f, o1i = 0.f;
        #pragma unroll
        for (int b = 0; b < 8; b++) {
            int t8 = (kb * b) & 7;
            float wr = W8R[t8], wi = W8I[t8];
            o0r += F0r[b] * wr - F0i[b] * wi;
            o0i += F0r[b] * wi + F0i[b] * wr;
            o1r += F1r[b] * wr - F1i[b] * wi;
            o1i += F1r[b] * wi + F1i[b] * wr;
        }
        float p20 = o0r * o0r + o0i * o0i; if (p20 < 1e-5f) p20 = 1e-5f;
        float p21 = o1r * o1r + o1i * o1i; if (p21 < 1e-5f) p21 = 1e-5f;
        float am0 = sqrtf(p20), am1 = sqrtf(p21);
        float rr0 = o0r; if (rr0 < 1e-5f && rr0 > -1e-5f) rr0 = 1e-5f;
        float rr1 = o1r; if (rr1 < 1e-5f && rr1 > -1e-5f) rr1 = 1e-5f;
        float ph0 = fast_atan2(o0i, rr0);
        float ph1 = fast_atan2(o1i, rr1);
        int off = (((n << 3) + kb) << 10) + c0;
        *(__nv_bfloat162*)(&g_amb[off]) = __nv_bfloat162(__float2bfloat16(am0), __float2bfloat16(am1));
        *(__nv_bfloat162*)(&g_phb[off]) = __nv_bfloat162(__float2bfloat16(ph0), __float2bfloat16(ph1));
    }
}

// ---------------- tcgen05 bf16 GEMM building blocks -------------------------
#if HAS_TCGEN05
__device__ __forceinline__ uint32_t gemm_prologue(uint32_t ctrl, int tid, int wid)
{
    if (wid == 0) {
        asm volatile("tcgen05.alloc.cta_group::1.sync.aligned.shared::cta.b32 [%0], %1;"
                     :: "r"(ctrl), "r"(128u) : "memory");
        asm volatile("tcgen05.relinquish_alloc_permit.cta_group::1.sync.aligned;");
    }
    if (tid == 0) {
        asm volatile("mbarrier.init.shared.b64 [%0], 1;" :: "r"(ctrl + 8) : "memory");
        asm volatile("mbarrier.init.shared.b64 [%0], 1;" :: "r"(ctrl + 16) : "memory");
    }
    __syncthreads();
    uint32_t tmem;
    asm volatile("ld.shared.b32 %0, [%1];" : "=r"(tmem) : "r"(ctrl));
    return tmem;
}

// Two-phase mainloop with register-prefetch pipeline.
__device__ __forceinline__ void gemm_mainloop2(
    const __nv_bfloat16* A1, int lda1, const __nv_bfloat16* A2, int lda2,
    const __nv_bfloat16* B1, int ldb1, const __nv_bfloat16* B2, int ldb2,
    int nk1, int nk, char* tp, uint32_t ta, uint32_t ctrl,
    uint32_t tmem, int tid, int wid)
{
    const int abase[2] = {0, 16384};
    const int bbase[2] = {32768, 49152};
    int ph[2] = {0, 0};

    const __nv_bfloat16 *ap1[4], *ap2[4], *bp1[4], *bp2[4];
    uint32_t so[4];
    #pragma unroll
    for (int it = 0; it < 4; it++) {
        int u = tid + (it << 8);
        int r = u >> 3, s = u & 7;
        ap1[it] = A1 + (size_t)r * lda1 + (s << 3);
        ap2[it] = A2 + (size_t)r * lda2 + (s << 3);
        bp1[it] = B1 + (size_t)r * ldb1 + (s << 3);
        bp2[it] = B2 + (size_t)r * ldb2 + (s << 3);
        uint32_t bo = (r << 7) + (s << 4);
        so[it] = bo ^ ((bo >> 3) & 0x70);
    }
    uint4 ra[4], rb[4];
    #pragma unroll
    for (int it = 0; it < 4; it++) { ra[it] = *(const uint4*)ap1[it]; rb[it] = *(const uint4*)bp1[it]; }

    for (int c = 0; c < nk; c++) {
        int b = c & 1;
        if (c >= 2) { mbar_wait(ctrl + 8 + b * 8, (uint32_t)ph[b]); ph[b] ^= 1; }
        #pragma unroll
        for (int it = 0; it < 4; it++) {
            *(uint4*)(tp + abase[b] + so[it]) = ra[it];
            *(uint4*)(tp + bbase[b] + so[it]) = rb[it];
        }
        int cn = c + 1;
        if (cn < nk) {
            if (cn < nk1) {
                int k1 = cn << 6;
                #pragma unroll
                for (int it = 0; it < 4; it++) {
                    ra[it] = *(const uint4*)(ap1[it] + k1);
                    rb[it] = *(const uint4*)(bp1[it] + k1);
                }
            } else {
                int k2 = (cn - nk1) << 6;
                #pragma unroll
                for (int it = 0; it < 4; it++) {
                    ra[it] = *(const uint4*)(ap2[it] + k2);
                    rb[it] = *(const uint4*)(bp2[it] + k2);
                }
            }
        }
        asm volatile("fence.proxy.async.shared::cta;" ::: "memory");
        __syncthreads();
        if (wid == 0 && elect1()) {
            uint64_t ad = make_desc(ta + abase[b]);
            uint64_t bd = make_desc(ta + bbase[b]);
            #pragma unroll
            for (int kk = 0; kk < 4; kk++)
                mma_ss_f16(tmem, ad + kk * 2, bd + kk * 2, IDESC_128, (c | kk) != 0);
            asm volatile(
                "tcgen05.commit.cta_group::1.mbarrier::arrive::one.shared::cluster.b64 [%0];"
                :: "r"(ctrl + 8 + b * 8) : "memory");
        }
    }
    mbar_wait(ctrl + 8, (uint32_t)ph[0]);
    mbar_wait(ctrl + 16, (uint32_t)ph[1]);
    asm volatile("tcgen05.fence::after_thread_sync;" ::: "memory");
    __syncthreads();
}
#endif

// ---------------- fused attn(+softmax) / vT(transposed) launch --------------
struct GAV {
    const __nv_bfloat16 *X0, *X1;      // phb, amb
    const __nv_bfloat16 *T0, *T1;      // tokens
    const __nv_bfloat16 *W0, *W1;      // w_t2f weights (bf16)
    const float *bias0, *bias1;        // b_t2f
    __nv_bfloat16 *S0, *S1;            // softmax out
    __nv_bfloat16 *V0, *V1;            // vT transposed out [j][c]
};

// grid (1, 72, 2): y<64 -> attn rows (softmax epilogue), y>=64 -> vT rows
__global__ void __launch_bounds__(256, 2) gemm_attn_vt(GAV g)
{
    extern __shared__ char sm_[];
    int tid = threadIdx.x;
    int z = blockIdx.z;
    bool is_vt = (blockIdx.y >= 64);
    int row0 = (is_vt ? ((int)blockIdx.y - 64) : (int)blockIdx.y) << 7;
    const __nv_bfloat16* A = is_vt ? (z ? g.W1 : g.W0) : (z ? g.X1 : g.X0);
    const __nv_bfloat16* Bm = (z ? g.T1 : g.T0) + (is_vt ? CDIM : 0);
    const float* bias = z ? g.bias1 : g.bias0;

#if HAS_TCGEN05
    uint32_t sb = smem_u32(sm_);
    uint32_t ta = (sb + 1023u) & ~1023u;
    char* tp = sm_ + (ta - sb);
    uint32_t ctrl = ta + CTRL_OFF;
    int wid = tid >> 5, lane = tid & 31;
    uint32_t tmem = gemm_prologue(ctrl, tid, wid);
    gemm_mainloop2(A + (size_t)row0 * CDIM, CDIM, A, CDIM, Bm, CDIM, Bm, CDIM,
                   16, 16, tp, ta, ctrl, tmem, tid, wid);

    int sub = wid & 3, half = wid >> 2;
    int rsub = (sub << 5) + lane;

    if (!is_vt) {
        float* smf = (float*)tp;
        #pragma unroll
        for (int q = 0; q < 2; q++) {
            int cb = (half << 1) + q;
            uint32_t r_[32];
            LDTM_X32(r_, tmem + (cb << 5));
            asm volatile("tcgen05.wait::ld.sync.aligned;" ::: "memory");
            #pragma unroll
            for (int j = 0; j < 32; j++)
                smf[rsub * 129 + (cb << 5) + j] = __uint_as_float(r_[j]);
        }
        __syncthreads();
        bool inorm = (z != 0);
        __nv_bfloat16* Srow = z ? g.S1 : g.S0;
        for (int r = wid; r < 128; r += 8) {
            const float* a = smf + r * 129;
            float v[4]; bool val[4];
            #pragma unroll
            for (int q = 0; q < 4; q++) {
                int idx = lane + 32 * q;
                val[q] = idx < 100;
                v[q] = val[q] ? a[idx] : 0.f;
            }
            if (inorm) {
                float s = v[0] + v[1] + v[2] + v[3];
                #pragma unroll
                for (int off = 16; off > 0; off >>= 1) s += __shfl_xor_sync(0xffffffffu, s, off);
                float mu = s * 0.01f;
                float s2 = 0.f;
                #pragma unroll
                for (int q = 0; q < 4; q++) if (val[q]) { float d = v[q] - mu; s2 += d * d; }
                #pragma unroll
                for (int off = 16; off > 0; off >>= 1) s2 += __shfl_xor_sync(0xffffffffu, s2, off);
                float inv = rsqrtf(s2 * 0.01f + 1e-5f);
                #pragma unroll
                for (int q = 0; q < 4; q++) v[q] = (v[q] - mu) * inv;
            }
            float m = -1e30f;
            #pragma unroll
            for (int q = 0; q < 4; q++) if (val[q]) m = fmaxf(m, v[q] * 0.03125f);
            #pragma unroll
            for (int off = 16; off > 0; off >>= 1) m = fmaxf(m, __shfl_xor_sync(0xffffffffu, m, off));
            float e[4]; float se = 0.f;
            #pragma unroll
            for (int q = 0; q < 4; q++) {
                e[q] = val[q] ? __expf(v[q] * 0.03125f - m) : 0.f;
                se += e[q];
            }
            #pragma unroll
            for (int off = 16; off > 0; off >>= 1) se += __shfl_xor_sync(0xffffffffu, se, off);
            float rinv = __fdividef(1.f, se);
            __nv_bfloat16* o = Srow + (size_t)(row0 + r) * KP;
            #pragma unroll
            for (int q = 0; q < 4; q++) {
                int idx = lane + 32 * q;
                if (idx >= 1 && idx < 100) o[idx - 1] = __float2bfloat16(e[q] * rinv);
                else if (idx >= 100) o[idx - 1] = __float2bfloat16(0.f);
                else o[127] = __float2bfloat16(0.f);
            }
        }
    } else {
        __nv_bfloat16* V = z ? g.V1 : g.V0;
        float biasr = bias[row0 + rsub];
        #pragma unroll
        for (int q = 0; q < 2; q++) {
            int cb = (half << 1) + q;
            uint32_t r_[32];
            LDTM_X32(r_, tmem + (cb << 5));
            asm volatile("tcgen05.wait::ld.sync.aligned;" ::: "memory");
            #pragma unroll
            for (int j = 0; j < 32; j++) {
                int jj = (cb << 5) + j;
                V[(size_t)jj * CDIM + row0 + rsub] =
                    __float2bfloat16(__uint_as_float(r_[j]) + biasr);
            }
        }
    }
    __syncthreads();
    if (wid == 0) {
        asm volatile("tcgen05.dealloc.cta_group::1.sync.aligned.b32 %0, %1;"
                     :: "r"(tmem), "r"(128u));
    }
#else
    (void)sm_;
    if (tid < 128) {
        int row = row0 + tid;
        float acc_row[128];
        for (int cc = 0; cc < 128; cc++) {
            float acc = 0.f;
            for (int k = 0; k < 1024; k++)
                acc += __bfloat162float(A[(size_t)row * CDIM + k]) *
                       __bfloat162float(Bm[(size_t)cc * CDIM + k]);
            acc_row[cc] = acc;
        }
        if (is_vt) {
            __nv_bfloat16* V = z ? g.V1 : g.V0;
            for (int cc = 0; cc < 128; cc++)
                V[(size_t)cc * CDIM + row] = __float2bfloat16(acc_row[cc] + bias[row]);
        } else {
            bool inorm = (z != 0);
            if (inorm) {
                float s = 0.f;
                for (int i = 0; i < 100; i++) s += acc_row[i];
                float mu = s * 0.01f, s2 = 0.f;
                for (int i = 0; i < 100; i++) { float d = acc_row[i] - mu; s2 += d * d; }
                float inv = rsqrtf(s2 * 0.01f + 1e-5f);
                for (int i = 0; i < 100; i++) acc_row[i] = (acc_row[i] - mu) * inv;
            }
            float m = -1e30f;
            for (int i = 0; i < 100; i++) m = fmaxf(m, acc_row[i] * 0.03125f);
            float se = 0.f;
            for (int i = 0; i < 100; i++) { acc_row[i] = expf(acc_row[i] * 0.03125f - m); se += acc_row[i]; }
            float rinv = 1.f / se;
            __nv_bfloat16* o = (z ? g.S1 : g.S0) + (size_t)row * KP;
            for (int i = 1; i < 100; i++) o[i - 1] = __float2bfloat16(acc_row[i] * rinv);
            for (int i = 99; i < 128; i++) o[i] = __float2bfloat16(0.f);
        }
    }
#endif
}

// ---------------- generic two-phase GEMM, bf16 out, optional col bias -------
struct GG {
    const __nv_bfloat16 *A10, *A11, *A20, *A21;
    const __nv_bfloat16 *B10, *B11, *B20, *B21;
    const float *bias0, *bias1;
    __nv_bfloat16 *C0, *C1;
};

template<int BIAS>
__global__ void __launch_bounds__(256, 2) gemm_tc(GG g, int lda1, int lda2,
                                                  int ldb1, int ldb2, int ldc,
                                                  int nk1, int nk, int nguard)
{
    extern __shared__ char sm_[];
    int tid = threadIdx.x;
    int z = blockIdx.z;
    const __nv_bfloat16* A1 = z ? g.A11 : g.A10;
    const __nv_bfloat16* A2 = z ? g.A21 : g.A20;
    const __nv_bfloat16* B1 = z ? g.B11 : g.B10;
    const __nv_bfloat16* B2 = z ? g.B21 : g.B20;
    const float* bias = z ? g.bias1 : g.bias0;
    __nv_bfloat16* C = z ? g.C1 : g.C0;
    int row0 = blockIdx.y << 7, col0 = blockIdx.x << 7;

#if HAS_TCGEN05
    uint32_t sb = smem_u32(sm_);
    uint32_t ta = (sb + 1023u) & ~1023u;
    char* tp = sm_ + (ta - sb);
    uint32_t ctrl = ta + CTRL_OFF;
    int wid = tid >> 5, lane = tid & 31;
    uint32_t tmem = gemm_prologue(ctrl, tid, wid);
    gemm_mainloop2(A1 + (size_t)row0 * lda1, lda1, A2 + (size_t)row0 * lda2, lda2,
                   B1 + (size_t)col0 * ldb1, ldb1, B2 + (size_t)col0 * ldb2, ldb2,
                   nk1, nk, tp, ta, ctrl, tmem, tid, wid);

    int sub = wid & 3, half = wid >> 2;
    int rsub = (sub << 5) + lane;
    float* smf = (float*)tp + half * 4224;
    int barid = 1 + half;
    #pragma unroll
    for (int q = 0; q < 2; q++) {
        int cb = (half << 1) + q;
        uint32_t r_[32];
        LDTM_X32(r_, tmem + (cb << 5));
        asm volatile("tcgen05.wait::ld.sync.aligned;" ::: "memory");
        asm volatile("bar.sync %0, 128;" :: "r"(barid) : "memory");
        #pragma unroll
        for (int j = 0; j < 32; j++) smf[rsub * 33 + j] = __uint_as_float(r_[j]);
        asm volatile("bar.sync %0, 128;" :: "r"(barid) : "memory");
        #pragma unroll
        for (int i = 0; i < 32; i++) {
            int idx = rsub + (i << 7);
            int orow = idx >> 5, ocol = idx & 31;
            int cc = col0 + (cb << 5) + ocol;
            if (cc < nguard) {
                float v = smf[orow * 33 + ocol];
                if (BIAS == 1) v += bias[cc];
                C[(size_t)(row0 + orow) * ldc + cc] = __float2bfloat16(v);
            }
        }
    }
    __syncthreads();
    if (wid == 0) {
        asm volatile("tcgen05.dealloc.cta_group::1.sync.aligned.b32 %0, %1;"
                     :: "r"(tmem), "r"(128u));
    }
#else
    (void)sm_;
    if (tid < 128) {
        int row = row0 + tid;
        for (int cc = 0; cc < 128; cc++) {
            int c = col0 + cc;
            if (c >= nguard) continue;
            float acc = 0.f;
            for (int ch = 0; ch < nk; ch++) {
                const __nv_bfloat16* Ar = (ch < nk1)
                    ? A1 + (size_t)row * lda1 + (ch << 6)
                    : A2 + (size_t)row * lda2 + ((ch - nk1) << 6);
                const __nv_bfloat16* Br = (ch < nk1)
                    ? B1 + (size_t)c * ldb1 + (ch << 6)
                    : B2 + (size_t)c * ldb2 + ((ch - nk1) << 6);
                for (int k = 0; k < 64; k++)
                    acc += __bfloat162float(Ar[k]) * __bfloat162float(Br[k]);
            }
            if (BIAS == 1) acc += bias[c];
            C[(size_t)row * ldc + c] = __float2bfloat16(acc);
        }
    }
#endif
}

// ---------------- inverse: z-build + ifft_b(8) + packed irfft -> out --------
// W_j = Z_{2j} + i*Z_{2j+1} (each Z_b Hermitian) -> IFFT -> (y_{2j}, y_{2j+1})
// grid 1025: block 1024 handles the cls-row passthrough
__global__ void __launch_bounds__(512) fft_inv(const float* __restrict__ feats,
                                               const float* __restrict__ scale_p,
                                               float* __restrict__ out)
{
    int tid = threadIdx.x;
    int n = blockIdx.x;
    if (n == 1024) {               // cls row copy: 8192 floats
        for (int i = tid; i < 8192; i += 512) out[i] = feats[i];
        return;
    }
    extern __shared__ float sm[];
    float* sre = sm;               // 4096
    float* sim = sm + 4096;        // 4096
    float* twr = sm + 8192;        // 1024
    float* twi = twr + 1024;       // 1024

    for (int t = tid; t < 1024; t += 512) {
        float s_, c_;
        __sincosf((float)t * 6.1359233e-3f, &s_, &c_);    // +2*pi/1024
        twr[t] = c_; twi[t] = s_;
    }
    __syncthreads();

    const float W8R[8] = {1.f, 0.70710678f, 0.f, -0.70710678f, -1.f, -0.70710678f, 0.f, 0.70710678f};
    const float W8I[8] = {0.f, -0.70710678f, -1.f, -0.70710678f, 0.f, 0.70710678f, 1.f, 0.70710678f};

    for (int c = tid; c < 513; c += 512) {
        float zr_[8], zi_[8];
        #pragma unroll
        for (int b = 0; b < 8; b++) {
            size_t off = (size_t)((n << 3) + b) * NZ + c;
            float phv = __bfloat162float(g_dpb[off]);
            float amv = __bfloat162float(g_dab[off]);
            float s_, c_;
            __sincosf(phv, &s_, &c_);
            zr_[b] = c_ * amv;
            zi_[b] = s_ * amv;
        }
        // inverse 8-pt DFT along b: Z_b[c]
        float orr[8], oii[8];
        #pragma unroll
        for (int b = 0; b < 8; b++) {
            float ar = 0.f, ai = 0.f;
            #pragma unroll
            for (int kb = 0; kb < 8; kb++) {
                int t8 = (kb * b) & 7;
                float wr = W8R[t8], wi = -W8I[t8];
                ar += zr_[kb] * wr - zi_[kb] * wi;
                ai += zr_[kb] * wi + zi_[kb] * wr;
            }
            orr[b] = ar; oii[b] = ai;
        }
        int rcp = rc4(c);
        int rcm = rc4((1024 - c) & 1023);
        bool mir = (c != 0) && (c != 512);
        #pragma unroll
        for (int j = 0; j < 4; j++) {
            float a0 = orr[2*j], b0 = oii[2*j];
            float a1 = orr[2*j+1], b1 = oii[2*j+1];
            int p1 = SW((j << 10) + rcp);
            sre[p1] = a0 - b1;                 // W_j[c]
            sim[p1] = b0 + a1;
            if (mir) {
                int p2 = SW((j << 10) + rcm);  // W_j[1024-c] from conj(Z_b[c])
                sre[p2] = a0 + b1;
                sim[p2] = a1 - b0;
            }
        }
    }
    __syncthreads();
    fft_stages_r4(sre, sim, twr, twi, tid, +1);

    float sc = scale_p[0];
    for (int i = tid; i < 4096; i += 512) {
        int j = i >> 10, c = i & 1023;
        int p = SW((j << 10) + c);
        float d0 = sre[p] * (1.0f / 4096.0f);     // row 2j
        float d1 = sim[p] * (1.0f / 4096.0f);     // row 2j+1
        size_t off0 = ((size_t)(n + 1) * 8 + (j << 1)) * 1024 + c;
        out[off0] = feats[off0] + d0 * sc;
        size_t off1 = off0 + 1024;
        out[off1] = feats[off1] + d1 * sc;
    }
}

// ---------------- host ------------------------------------------------------
static void* symaddr(const void* s)
{
    void* p = nullptr;
    cudaGetSymbolAddress(&p, s);
    return p;
}

extern "C" void kernel_launch(void* const* d_in, const int* in_sizes, int n_in,
                              void* d_out, int out_size)
{
    (void)in_sizes; (void)n_in; (void)out_size;
    const float* feats  = (const float*)d_in[0];
    const float* lt1    = (const float*)d_in[1];
    const float* lt2    = (const float*)d_in[2];
    const float* w_t2f  = (const float*)d_in[3];
    const float* b_t2f  = (const float*)d_in[4];
    const float* w_df   = (const float*)d_in[5];
    const float* b_df   = (const float*)d_in[6];
    const float* w_t2f2 = (const float*)d_in[7];
    const float* b_t2f2 = (const float*)d_in[8];
    const float* w_df2  = (const float*)d_in[9];
    const float* b_df2  = (const float*)d_in[10];
    const float* scale  = (const float*)d_in[11];
    const int*   layer  = (const int*)d_in[12];
    float* out = (float*)d_out;

    __nv_bfloat16* phb  = (__nv_bfloat16*)symaddr(g_phb);
    __nv_bfloat16* amb  = (__nv_bfloat16*)symaddr(g_amb);
    __nv_bfloat16* T1b  = (__nv_bfloat16*)symaddr(g_T1b);
    __nv_bfloat16* T2b  = (__nv_bfloat16*)symaddr(g_T2b);
    __nv_bfloat16* S1   = (__nv_bfloat16*)symaddr(g_S1);
    __nv_bfloat16* S2   = (__nv_bfloat16*)symaddr(g_S2);
    __nv_bfloat16* vTt1 = (__nv_bfloat16*)symaddr(g_vTt1);
    __nv_bfloat16* vTt2 = (__nv_bfloat16*)symaddr(g_vTt2);
    __nv_bfloat16* U1   = (__nv_bfloat16*)symaddr(g_U1);
    __nv_bfloat16* U2   = (__nv_bfloat16*)symaddr(g_U2);
    __nv_bfloat16* W1   = (__nv_bfloat16*)symaddr(g_W1);
    __nv_bfloat16* W2   = (__nv_bfloat16*)symaddr(g_W2);
    __nv_bfloat16* W3   = (__nv_bfloat16*)symaddr(g_W3);
    __nv_bfloat16* W4   = (__nv_bfloat16*)symaddr(g_W4);
    __nv_bfloat16* dpb  = (__nv_bfloat16*)symaddr(g_dpb);
    __nv_bfloat16* dab  = (__nv_bfloat16*)symaddr(g_dab);

    const int FFT_SMEM  = (4096 * 2 + 2048) * 4;   // 40960
    const int GEMM_SMEM = 1024 + CTRL_OFF + 64;    // 67648
    cudaFuncSetAttribute(fft_fwd, cudaFuncAttributeMaxDynamicSharedMemorySize, FFT_SMEM);
    cudaFuncSetAttribute(fft_inv, cudaFuncAttributeMaxDynamicSharedMemorySize, FFT_SMEM);
    cudaFuncSetAttribute(gemm_attn_vt, cudaFuncAttributeMaxDynamicSharedMemorySize, GEMM_SMEM);
    cudaFuncSetAttribute(gemm_tc<0>, cudaFuncAttributeMaxDynamicSharedMemorySize, GEMM_SMEM);
    cudaFuncSetAttribute(gemm_tc<1>, cudaFuncAttributeMaxDynamicSharedMemorySize, GEMM_SMEM);

    // 1) tokens (bf16, padded) + weight conversion (one launch)
    prep_all<<<4672, 256>>>(lt1, lt2, layer, w_t2f, w_t2f2, w_df, w_df2);

    // 2) FFT2 + amp/phase (bf16, real-pair packed)
    fft_fwd<<<1024, 512, FFT_SMEM>>>(feats);

    // 3) fused: attn = X @ T^T + softmax -> S,  and  vTt = (W @ T[1:]^T + b)^T
    {
        GAV g = { phb, amb, T1b, T2b, W1, W2, b_t2f, b_t2f2, S1, S2, vTt1, vTt2 };
        gemm_attn_vt<<<dim3(1, 72, 2), 256, GEMM_SMEM>>>(g);
    }

    // 4) U = Wdf @ vT : [640 x 128] bf16
    {
        GG g = { W3, W4, W3, W4, vTt1, vTt2, vTt1, vTt2, nullptr, nullptr, U1, U2 };
        gemm_tc<0><<<dim3(1, 5, 2), 256, GEMM_SMEM>>>(g, CDIM, CDIM, CDIM, CDIM,
                                                      KP, 16, 16, KP);
    }

    // 5) d = [X | S] @ [Wdf | U]^T + b  -> bf16 [8192 x 513], K = 1152
    {
        GG g = { phb, amb, S1, S2, W3, W4, U1, U2, b_df, b_df2, dpb, dab };
        gemm_tc<1><<<dim3(5, 64, 2), 256, GEMM_SMEM>>>(g, CDIM, KP, CDIM, KP,
                                                       NZ, 16, 18, NZ);
    }

    // 6) z-build + packed irfft2 + residual add + cls copy (grid 1025)
    fft_inv<<<1025, 512, FFT_SMEM>>>(feats, scale, out);
}